// round 3
// baseline (speedup 1.0000x reference)
#include <cuda_runtime.h>
#include <cuda_bf16.h>
#include <math.h>

// Problem constants
#define BS   128
#define NE   32
#define NA   8
#define TE   8
#define TA   4
#define WD   300
#define HD   1024
#define G3   900          // 3*WD
#define NG   (BS*NE)      // 4096
#define NATT (NG*NA)      // 32768
#define NNODE 9

typedef unsigned long long ull;

// ---------------- scratch ----------------------------------------------------
__device__ float g_xp_ent [NG   * TE * G3];
__device__ float g_xp_attr[NATT * TA * G3];
__device__ float g_gh     [NATT * G3];
__device__ float g_h_ent  [NG   * WD];
__device__ float g_h_attr [NATT * WD];
__device__ float g_nodes  [NG * NNODE * HD];
__device__ float g_va     [HD];
__device__ float g_vb     [HD];
// sort scratch
__device__ int g_cnt_ent [TE + 1];
__device__ int g_off_ent [TE + 1];
__device__ int g_perm_ent[NG];
__device__ int g_mcnt_ent[TE];
__device__ int g_cnt_attr [TA + 1];
__device__ int g_off_attr [TA + 1];
__device__ int g_perm_attr[NATT];
__device__ int g_mcnt_attr[TA];

// ---------------- packed f32x2 helpers ---------------------------------------
__device__ __forceinline__ ull pack2(float x, float y) {
    ull r; asm("mov.b64 %0, {%1, %2};" : "=l"(r) : "f"(x), "f"(y)); return r;
}
__device__ __forceinline__ void unpack2(ull p, float& lo, float& hi) {
    asm("mov.b64 {%0, %1}, %2;" : "=f"(lo), "=f"(hi) : "l"(p));
}
__device__ __forceinline__ void ffma2(ull& acc, ull a, ull b) {
    asm("fma.rn.f32x2 %0, %1, %2, %0;" : "+l"(acc) : "l"(a), "l"(b));
}

// ---------------- SGEMM: C = act(A(gather) @ W^T + bias) ---------------------
// 128x128 tile, BK=8, 256 threads, 8x8 microtile via packed f32x2 FFMA.
// A smem tile stored DUPLICATED: each a value as (a,a) 8-byte pair.
#define BM 128
#define BN 128
#define BK 8
#define ASTR 132   // A smem row stride in ull (>=128, 16B-aligned rows)
#define BSTR 132   // B smem row stride in floats

__global__ __launch_bounds__(256, 2)
void sgemm128(const float* __restrict__ A, const int* __restrict__ gather,
              const float* __restrict__ W, const float* __restrict__ bias,
              float* __restrict__ C, int M, int N, int K, int act, int outMap,
              const int* __restrict__ mlimit)
{
    __shared__ ull   As[2][BK][ASTR];   // duplicated pairs
    __shared__ float Bs[2][BK][BSTR];

    if (mlimit) {
        int Ma = *mlimit;
        if ((int)blockIdx.x * BM >= Ma) return;
        if (Ma < M) M = Ma;
    }

    const int tid   = threadIdx.x;
    const int m0    = blockIdx.x * BM;
    const int n0    = blockIdx.y * BN;
    const int ldRow = tid >> 1;          // 0..127
    const int ldK   = (tid & 1) * 4;     // 0 or 4
    const int rb    = (tid >> 4) * 8;    // micro-tile row base
    const int cb    = (tid & 15) * 8;    // micro-tile col base

    const float* Aptr = nullptr;
    {
        int m = m0 + ldRow;
        if (m < M) Aptr = gather ? A + (long)gather[m] * K : A + (long)m * K;
    }
    const float* Wptr = (n0 + ldRow < N) ? W + (long)(n0 + ldRow) * K : nullptr;

    ull acc[8][4];
#pragma unroll
    for (int i = 0; i < 8; ++i)
#pragma unroll
        for (int j = 0; j < 4; ++j) acc[i][j] = 0ULL;

    const int nk = (K + BK - 1) / BK;
    const float4 z4 = make_float4(0.f, 0.f, 0.f, 0.f);
    float4 aR, bR;

    // prefetch tile 0
    {
        int k = ldK;
        aR = (Aptr && k < K) ? *(const float4*)(Aptr + k) : z4;
        bR = (Wptr && k < K) ? *(const float4*)(Wptr + k) : z4;
    }
    As[0][ldK + 0][ldRow] = pack2(aR.x, aR.x);
    As[0][ldK + 1][ldRow] = pack2(aR.y, aR.y);
    As[0][ldK + 2][ldRow] = pack2(aR.z, aR.z);
    As[0][ldK + 3][ldRow] = pack2(aR.w, aR.w);
    Bs[0][ldK + 0][ldRow] = bR.x; Bs[0][ldK + 1][ldRow] = bR.y;
    Bs[0][ldK + 2][ldRow] = bR.z; Bs[0][ldK + 3][ldRow] = bR.w;
    __syncthreads();

    for (int t = 0; t < nk; ++t) {
        const int buf = t & 1;
        if (t + 1 < nk) {
            int k = (t + 1) * BK + ldK;
            aR = (Aptr && k < K) ? *(const float4*)(Aptr + k) : z4;
            bR = (Wptr && k < K) ? *(const float4*)(Wptr + k) : z4;
        }
#pragma unroll
        for (int kk = 0; kk < BK; ++kk) {
            ull pa[8], pb[4];
            // A: 4 x 16B loads of duplicated pairs (broadcast-heavy)
            *(ulonglong2*)&pa[0] = *(const ulonglong2*)&As[buf][kk][rb + 0];
            *(ulonglong2*)&pa[2] = *(const ulonglong2*)&As[buf][kk][rb + 2];
            *(ulonglong2*)&pa[4] = *(const ulonglong2*)&As[buf][kk][rb + 4];
            *(ulonglong2*)&pa[6] = *(const ulonglong2*)&As[buf][kk][rb + 6];
            // B: 2 x 16B loads = 4 natural packed pairs
            *(ulonglong2*)&pb[0] = *(const ulonglong2*)&Bs[buf][kk][cb];
            *(ulonglong2*)&pb[2] = *(const ulonglong2*)&Bs[buf][kk][cb + 4];
#pragma unroll
            for (int i = 0; i < 8; ++i)
#pragma unroll
                for (int j = 0; j < 4; ++j)
                    ffma2(acc[i][j], pa[i], pb[j]);
        }
        if (t + 1 < nk) {
            const int nb = buf ^ 1;
            As[nb][ldK + 0][ldRow] = pack2(aR.x, aR.x);
            As[nb][ldK + 1][ldRow] = pack2(aR.y, aR.y);
            As[nb][ldK + 2][ldRow] = pack2(aR.z, aR.z);
            As[nb][ldK + 3][ldRow] = pack2(aR.w, aR.w);
            Bs[nb][ldK + 0][ldRow] = bR.x; Bs[nb][ldK + 1][ldRow] = bR.y;
            Bs[nb][ldK + 2][ldRow] = bR.z; Bs[nb][ldK + 3][ldRow] = bR.w;
        }
        __syncthreads();
    }

    // epilogue
#pragma unroll
    for (int i = 0; i < 8; ++i) {
        int m = m0 + rb + i;
        if (m >= M) continue;
        long base;
        if (outMap == 0)      base = (long)m * N;
        else if (outMap == 1) base = (long)m * NNODE * HD;
        else                  base = ((long)(m >> 3) * NNODE + 1 + (m & 7)) * (long)HD;
#pragma unroll
        for (int jp = 0; jp < 4; jp += 2) {
            int n = n0 + cb + jp * 2;
            if (n >= N) continue;
            float4 v;
            unpack2(acc[i][jp],     v.x, v.y);
            unpack2(acc[i][jp + 1], v.z, v.w);
            float* vp = &v.x;
#pragma unroll
            for (int j = 0; j < 4; ++j) {
                float x = vp[j];
                if (bias) x += bias[n + j];
                if (act == 1)      x = fmaxf(x, 0.f);
                else if (act == 2) x = x > 0.f ? x : expm1f(x);
                vp[j] = x;
            }
            *(float4*)(C + base + n) = v;
        }
    }
}

// ---------------- counting sort by length (descending) -----------------------
__global__ void hist_kernel(const int* __restrict__ len, int n, int T,
                            int* __restrict__ cnt)
{
    int i = blockIdx.x * blockDim.x + threadIdx.x;
    if (i >= n) return;
    int L = len[i]; L = L < 1 ? 1 : (L > T ? T : L);
    atomicAdd(&cnt[L], 1);
}
__global__ void offsets_kernel(const int* __restrict__ cnt,
                               int* __restrict__ off, int* __restrict__ mcnt, int T)
{
    if (threadIdx.x != 0 || blockIdx.x != 0) return;
    int run = 0;
    for (int L = T; L >= 1; --L) { off[L] = run; run += cnt[L]; }
    for (int t = 0; t < T; ++t) {
        int s = 0;
        for (int L = t + 1; L <= T; ++L) s += cnt[L];
        mcnt[t] = s;
    }
}
__global__ void scatter_kernel(const int* __restrict__ len, int n, int T,
                               int* __restrict__ off, int* __restrict__ perm)
{
    int i = blockIdx.x * blockDim.x + threadIdx.x;
    if (i >= n) return;
    int L = len[i]; L = L < 1 ? 1 : (L > T ? T : L);
    int pos = atomicAdd(&off[L], 1);
    perm[pos] = i;
}

// ---------------- GRU gate update (compact rows, float4) ---------------------
__global__ void gru_gate4(const float* __restrict__ xp,
                          const float* __restrict__ gh,
                          float* __restrict__ h,
                          const int* __restrict__ perm,
                          const int* __restrict__ mcnt,
                          int t, int T)
{
    const int Q = WD / 4;   // 75
    int idx = blockIdx.x * blockDim.x + threadIdx.x;
    int i = idx / Q;
    if (i >= *mcnt) return;
    int d = idx - i * Q;
    int orig = perm[i];
    const float4* x = (const float4*)(xp + ((long)orig * T + t) * G3);
    const float4* g = (const float4*)(gh + (long)i * G3);
    float4* hp = (float4*)(h + (long)orig * WD);

    float4 xr = x[d], xz = x[Q + d], xn = x[2 * Q + d];
    float4 gr = g[d], gz = g[Q + d], gn = g[2 * Q + d];
    float4 hv = hp[d];

    float4 res;
    const float* pxr = &xr.x; const float* pxz = &xz.x; const float* pxn = &xn.x;
    const float* pgr = &gr.x; const float* pgz = &gz.x; const float* pgn = &gn.x;
    const float* phv = &hv.x; float* pres = &res.x;
#pragma unroll
    for (int c = 0; c < 4; ++c) {
        float r = 1.f / (1.f + expf(-(pxr[c] + pgr[c])));
        float z = 1.f / (1.f + expf(-(pxz[c] + pgz[c])));
        float n = tanhf(pxn[c] + r * pgn[c]);
        pres[c] = (1.f - z) * n + z * phv[c];
    }
    hp[d] = res;
}

// ---------------- va/vb = Wg^T a_src / Wg^T a_dst ----------------------------
__global__ void wgt_vec_kernel(const float* __restrict__ Wg,
                               const float* __restrict__ a_src,
                               const float* __restrict__ a_dst,
                               float* __restrict__ va, float* __restrict__ vb)
{
    int k = blockIdx.x * blockDim.x + threadIdx.x;
    if (k >= HD) return;
    float sa = 0.f, sb = 0.f;
    for (int d = 0; d < HD; ++d) {
        float w = Wg[(long)d * HD + k];
        sa += w * a_src[d];
        sb += w * a_dst[d];
    }
    va[k] = sa;
    vb[k] = sb;
}

// ---------------- GAT dots + softmax + node mix -------------------------------
__global__ void gat_mix_kernel(const float* __restrict__ nodes,
                               const float* __restrict__ va,
                               const float* __restrict__ vb,
                               const unsigned char* __restrict__ amask,
                               float* __restrict__ mix)
{
    int g = blockIdx.x;
    const float* base = nodes + (long)g * NNODE * HD;
    __shared__ float sdots[10];
    __shared__ float salpha[NNODE];

    int tid  = threadIdx.x;
    int warp = tid >> 5, lane = tid & 31;

    float partial = 0.f;
    if (warp < 9) {
        const float* row = base + warp * HD;
        for (int d = lane; d < HD; d += 32) partial += row[d] * vb[d];
    } else {
        for (int d = lane; d < HD; d += 32) partial += base[d] * va[d];
    }
#pragma unroll
    for (int off = 16; off; off >>= 1)
        partial += __shfl_down_sync(0xffffffffu, partial, off);
    if (lane == 0) sdots[warp] = partial;
    __syncthreads();

    if (tid == 0) {
        float es0 = sdots[9];
        float e[NNODE];
#pragma unroll
        for (int j = 0; j < NNODE; ++j) {
            bool valid;
            if (j == 0) valid = true;
            else {
                const unsigned char* m = amask + ((long)g * NA + (j - 1)) * TA;
                valid = !(m[0] && m[1] && m[2] && m[3]);
            }
            if (valid) {
                float v = es0 + sdots[j];
                e[j] = v > 0.f ? v : 0.2f * v;
            } else e[j] = -1e9f;
        }
        float mx = e[0];
#pragma unroll
        for (int j = 1; j < NNODE; ++j) mx = fmaxf(mx, e[j]);
        float s = 0.f, ex[NNODE];
#pragma unroll
        for (int j = 0; j < NNODE; ++j) { ex[j] = expf(e[j] - mx); s += ex[j]; }
        float inv = 1.f / s;
#pragma unroll
        for (int j = 0; j < NNODE; ++j) salpha[j] = ex[j] * inv;
    }
    __syncthreads();

    for (int d = tid; d < HD; d += blockDim.x) {
        float s = 0.f;
#pragma unroll
        for (int j = 0; j < NNODE; ++j) s += salpha[j] * base[j * HD + d];
        mix[(long)g * HD + d] = s;
    }
}

// ---------------- launch ------------------------------------------------------
extern "C" void kernel_launch(void* const* d_in, const int* in_sizes, int n_in,
                              void* d_out, int out_size)
{
    const int*   ent_tok  = (const int*)  d_in[0];
    const int*   ent_len  = (const int*)  d_in[1];
    const int*   at_tok   = (const int*)  d_in[3];
    const int*   at_len   = (const int*)  d_in[4];
    const unsigned char* at_mask = (const unsigned char*)d_in[5];
    const float* emb      = (const float*)d_in[6];
    const float* Wih_ent  = (const float*)d_in[7];
    const float* Whh_ent  = (const float*)d_in[8];
    const float* bih_ent  = (const float*)d_in[9];
    const float* bhh_ent  = (const float*)d_in[10];
    const float* Wih_attr = (const float*)d_in[11];
    const float* Whh_attr = (const float*)d_in[12];
    const float* bih_attr = (const float*)d_in[13];
    const float* bhh_attr = (const float*)d_in[14];
    const float* Wfc      = (const float*)d_in[15];
    const float* bfc      = (const float*)d_in[16];
    const float* Wg       = (const float*)d_in[17];
    const float* a_src    = (const float*)d_in[18];
    const float* a_dst    = (const float*)d_in[19];
    float* out = (float*)d_out;

    float *xp_ent, *xp_attr, *gh, *h_ent, *h_attr, *nodes, *va, *vb;
    int *cntE, *offE, *permE, *mcntE, *cntA, *offA, *permA, *mcntA;
    cudaGetSymbolAddress((void**)&xp_ent,  g_xp_ent);
    cudaGetSymbolAddress((void**)&xp_attr, g_xp_attr);
    cudaGetSymbolAddress((void**)&gh,      g_gh);
    cudaGetSymbolAddress((void**)&h_ent,   g_h_ent);
    cudaGetSymbolAddress((void**)&h_attr,  g_h_attr);
    cudaGetSymbolAddress((void**)&nodes,   g_nodes);
    cudaGetSymbolAddress((void**)&va,      g_va);
    cudaGetSymbolAddress((void**)&vb,      g_vb);
    cudaGetSymbolAddress((void**)&cntE,  g_cnt_ent);
    cudaGetSymbolAddress((void**)&offE,  g_off_ent);
    cudaGetSymbolAddress((void**)&permE, g_perm_ent);
    cudaGetSymbolAddress((void**)&mcntE, g_mcnt_ent);
    cudaGetSymbolAddress((void**)&cntA,  g_cnt_attr);
    cudaGetSymbolAddress((void**)&offA,  g_off_attr);
    cudaGetSymbolAddress((void**)&permA, g_perm_attr);
    cudaGetSymbolAddress((void**)&mcntA, g_mcnt_attr);
    float* mixbuf = gh;

    cudaMemsetAsync(h_ent,  0, (size_t)NG   * WD * sizeof(float));
    cudaMemsetAsync(h_attr, 0, (size_t)NATT * WD * sizeof(float));
    cudaMemsetAsync(cntE, 0, (TE + 1) * sizeof(int));
    cudaMemsetAsync(cntA, 0, (TA + 1) * sizeof(int));

    // length sort (both phrase sets)
    hist_kernel<<<(NG + 255) / 256, 256>>>(ent_len, NG, TE, cntE);
    offsets_kernel<<<1, 32>>>(cntE, offE, mcntE, TE);
    scatter_kernel<<<(NG + 255) / 256, 256>>>(ent_len, NG, TE, offE, permE);
    hist_kernel<<<(NATT + 255) / 256, 256>>>(at_len, NATT, TA, cntA);
    offsets_kernel<<<1, 32>>>(cntA, offA, mcntA, TA);
    scatter_kernel<<<(NATT + 255) / 256, 256>>>(at_len, NATT, TA, offA, permA);

    const int cB900  = (G3 + BN - 1) / BN;   // 8
    const int cB1024 = HD / BN;              // 8

    // xp = emb[tokens] @ Wih^T + bih
    sgemm128<<<dim3((NG * TE) / BM, cB900), 256>>>(
        emb, ent_tok, Wih_ent, bih_ent, xp_ent, NG * TE, G3, WD, 0, 0, nullptr);
    sgemm128<<<dim3((NATT * TA) / BM, cB900), 256>>>(
        emb, at_tok, Wih_attr, bih_attr, xp_attr, NATT * TA, G3, WD, 0, 0, nullptr);

    wgt_vec_kernel<<<(HD + 255) / 256, 256>>>(Wg, a_src, a_dst, va, vb);

    // entity GRU (compact active rows via perm; blocks early-exit past *mcnt)
    for (int t = 0; t < TE; ++t) {
        sgemm128<<<dim3(NG / BM, cB900), 256>>>(
            h_ent, permE, Whh_ent, bhh_ent, gh, NG, G3, WD, 0, 0, mcntE + t);
        gru_gate4<<<(NG * 75 + 255) / 256, 256>>>(
            xp_ent, gh, h_ent, permE, mcntE + t, t, TE);
    }

    // attribute GRU
    for (int t = 0; t < TA; ++t) {
        sgemm128<<<dim3(NATT / BM, cB900), 256>>>(
            h_attr, permA, Whh_attr, bhh_attr, gh, NATT, G3, WD, 0, 0, mcntA + t);
        gru_gate4<<<(NATT * 75 + 255) / 256, 256>>>(
            xp_attr, gh, h_attr, permA, mcntA + t, t, TA);
    }

    // FC + ReLU -> node layout [G, 9, HD]
    sgemm128<<<dim3(NG / BM,   cB1024), 256>>>(
        h_ent,  nullptr, Wfc, bfc, nodes, NG,   HD, WD, 1, 1, nullptr);
    sgemm128<<<dim3(NATT / BM, cB1024), 256>>>(
        h_attr, nullptr, Wfc, bfc, nodes, NATT, HD, WD, 1, 2, nullptr);

    // GAT: dots + alpha + mix
    gat_mix_kernel<<<NG, 320>>>(nodes, va, vb, at_mask, mixbuf);

    // out = elu(mix @ Wg^T)
    sgemm128<<<dim3(NG / BM, cB1024), 256>>>(
        mixbuf, nullptr, Wg, nullptr, out, NG, HD, HD, 2, 0, nullptr);
}

// round 4
// speedup vs baseline: 1.3818x; 1.3818x over previous
#include <cuda_runtime.h>
#include <cuda_bf16.h>
#include <math.h>

// Problem constants
#define BS   128
#define NE   32
#define NA   8
#define TE   8
#define TA   4
#define WD   300
#define HD   1024
#define G3   900          // 3*WD
#define NG   (BS*NE)      // 4096
#define NATT (NG*NA)      // 32768
#define NNODE 9

// ---------------- scratch ----------------------------------------------------
__device__ float g_xp_ent [NG   * TE * G3];
__device__ float g_xp_attr[NATT * TA * G3];
__device__ float g_gh     [NATT * G3];
__device__ float g_h_ent  [NG   * WD];
__device__ float g_h_attr [NATT * WD];
__device__ float g_nodes  [NG * NNODE * HD];
__device__ float g_va     [HD];
__device__ float g_vb     [HD];
// length-sort scratch
__device__ int g_cnt_ent [TE + 1];
__device__ int g_off_ent [TE + 1];
__device__ int g_perm_ent[NG];
__device__ int g_mcnt_ent[TE];
__device__ int g_cnt_attr [TA + 1];
__device__ int g_off_attr [TA + 1];
__device__ int g_perm_attr[NATT];
__device__ int g_mcnt_attr[TA];
// xp pair-compaction scratch
__device__ int g_paircnt_ent;
__device__ int g_gtok_ent[NG * TE];
__device__ int g_orow_ent[NG * TE];
__device__ int g_paircnt_attr;
__device__ int g_gtok_attr[NATT * TA];
__device__ int g_orow_attr[NATT * TA];

// ---------------- SGEMM: C = act(A(gather) @ W^T + bias) ---------------------
// 128x128 tile, BK=8, 256 threads, 8x8 microtile, double-buffered smem.
#define BM 128
#define BN 128
#define BK 8
#define SMS 132

__global__ __launch_bounds__(256, 2)
void sgemm128(const float* __restrict__ A, const int* __restrict__ gather,
              const float* __restrict__ W, const float* __restrict__ bias,
              float* __restrict__ C, int M, int N, int K, int act, int outMap,
              const int* __restrict__ mlimit, const int* __restrict__ orow)
{
    __shared__ float As[2][BK][SMS];
    __shared__ float Bs[2][BK][SMS];

    if (mlimit) {
        int Ma = *mlimit;
        if ((int)blockIdx.x * BM >= Ma) return;
        if (Ma < M) M = Ma;
    }

    const int tid   = threadIdx.x;
    const int m0    = blockIdx.x * BM;
    const int n0    = blockIdx.y * BN;
    const int ldRow = tid >> 1;
    const int ldK   = (tid & 1) * 4;
    const int rb    = (tid >> 4) * 8;
    const int cb    = (tid & 15) * 8;

    const float* Aptr = nullptr;
    {
        int m = m0 + ldRow;
        if (m < M) Aptr = gather ? A + (long)gather[m] * K : A + (long)m * K;
    }
    const float* Wptr = (n0 + ldRow < N) ? W + (long)(n0 + ldRow) * K : nullptr;

    float acc[8][8];
#pragma unroll
    for (int i = 0; i < 8; ++i)
#pragma unroll
        for (int j = 0; j < 8; ++j) acc[i][j] = 0.f;

    const int nk = (K + BK - 1) / BK;
    const float4 z4 = make_float4(0.f, 0.f, 0.f, 0.f);
    float4 aR, bR;

    {
        int k = ldK;
        aR = (Aptr && k < K) ? *(const float4*)(Aptr + k) : z4;
        bR = (Wptr && k < K) ? *(const float4*)(Wptr + k) : z4;
    }
    As[0][ldK + 0][ldRow] = aR.x; As[0][ldK + 1][ldRow] = aR.y;
    As[0][ldK + 2][ldRow] = aR.z; As[0][ldK + 3][ldRow] = aR.w;
    Bs[0][ldK + 0][ldRow] = bR.x; Bs[0][ldK + 1][ldRow] = bR.y;
    Bs[0][ldK + 2][ldRow] = bR.z; Bs[0][ldK + 3][ldRow] = bR.w;
    __syncthreads();

    for (int t = 0; t < nk; ++t) {
        const int buf = t & 1;
        if (t + 1 < nk) {
            int k = (t + 1) * BK + ldK;
            aR = (Aptr && k < K) ? *(const float4*)(Aptr + k) : z4;
            bR = (Wptr && k < K) ? *(const float4*)(Wptr + k) : z4;
        }
#pragma unroll
        for (int kk = 0; kk < BK; ++kk) {
            float a[8], b[8];
            *(float4*)&a[0] = *(const float4*)&As[buf][kk][rb];
            *(float4*)&a[4] = *(const float4*)&As[buf][kk][rb + 4];
            *(float4*)&b[0] = *(const float4*)&Bs[buf][kk][cb];
            *(float4*)&b[4] = *(const float4*)&Bs[buf][kk][cb + 4];
#pragma unroll
            for (int i = 0; i < 8; ++i)
#pragma unroll
                for (int j = 0; j < 8; ++j)
                    acc[i][j] += a[i] * b[j];
        }
        if (t + 1 < nk) {
            const int nb = buf ^ 1;
            As[nb][ldK + 0][ldRow] = aR.x; As[nb][ldK + 1][ldRow] = aR.y;
            As[nb][ldK + 2][ldRow] = aR.z; As[nb][ldK + 3][ldRow] = aR.w;
            Bs[nb][ldK + 0][ldRow] = bR.x; Bs[nb][ldK + 1][ldRow] = bR.y;
            Bs[nb][ldK + 2][ldRow] = bR.z; Bs[nb][ldK + 3][ldRow] = bR.w;
        }
        __syncthreads();
    }

#pragma unroll
    for (int i = 0; i < 8; ++i) {
        int m = m0 + rb + i;
        if (m >= M) continue;
        long base;
        if (orow)             base = (long)orow[m] * N;
        else if (outMap == 0) base = (long)m * N;
        else if (outMap == 1) base = (long)m * NNODE * HD;
        else                  base = ((long)(m >> 3) * NNODE + 1 + (m & 7)) * (long)HD;
#pragma unroll
        for (int j0 = 0; j0 < 8; j0 += 4) {
            int n = n0 + cb + j0;
            if (n >= N) continue;
            float4 v;
            float* vp = &v.x;
#pragma unroll
            for (int j = 0; j < 4; ++j) {
                float x = acc[i][j0 + j];
                if (bias) x += bias[n + j];
                if (act == 1)      x = fmaxf(x, 0.f);
                else if (act == 2) x = x > 0.f ? x : expm1f(x);
                vp[j] = x;
            }
            *(float4*)(C + base + n) = v;
        }
    }
}

// ---------------- counting sort by length (descending) -----------------------
__global__ void hist_kernel(const int* __restrict__ len, int n, int T,
                            int* __restrict__ cnt)
{
    int i = blockIdx.x * blockDim.x + threadIdx.x;
    if (i >= n) return;
    int L = len[i]; L = L < 1 ? 1 : (L > T ? T : L);
    atomicAdd(&cnt[L], 1);
}
__global__ void offsets_kernel(const int* __restrict__ cnt,
                               int* __restrict__ off, int* __restrict__ mcnt, int T)
{
    if (threadIdx.x != 0 || blockIdx.x != 0) return;
    int run = 0;
    for (int L = T; L >= 1; --L) { off[L] = run; run += cnt[L]; }
    for (int t = 0; t < T; ++t) {
        int s = 0;
        for (int L = t + 1; L <= T; ++L) s += cnt[L];
        mcnt[t] = s;
    }
}
__global__ void scatter_kernel(const int* __restrict__ len, int n, int T,
                               int* __restrict__ off, int* __restrict__ perm)
{
    int i = blockIdx.x * blockDim.x + threadIdx.x;
    if (i >= n) return;
    int L = len[i]; L = L < 1 ? 1 : (L > T ? T : L);
    int pos = atomicAdd(&off[L], 1);
    perm[pos] = i;
}

// ---------------- xp pair compaction ------------------------------------------
// Valid (row,t) pairs (t < len): gather token value + remember dense output row.
__global__ void build_pairs(const int* __restrict__ tok,
                            const int* __restrict__ len, int n, int T,
                            int* __restrict__ cnt,
                            int* __restrict__ gtok, int* __restrict__ orow)
{
    int p = blockIdx.x * blockDim.x + threadIdx.x;
    if (p >= n * T) return;
    int i = p / T, t = p - i * T;
    int L = len[i]; L = L < 1 ? 1 : (L > T ? T : L);
    if (t >= L) return;
    int pos = atomicAdd(cnt, 1);
    gtok[pos] = tok[p];
    orow[pos] = p;
}

// ---------------- GRU gate update (compact rows, float4) ---------------------
__global__ void gru_gate4(const float* __restrict__ xp,
                          const float* __restrict__ gh,
                          float* __restrict__ h,
                          const int* __restrict__ perm,
                          const int* __restrict__ mcnt,
                          int t, int T)
{
    const int Q = WD / 4;   // 75
    int idx = blockIdx.x * blockDim.x + threadIdx.x;
    int i = idx / Q;
    if (i >= *mcnt) return;
    int d = idx - i * Q;
    int orig = perm[i];
    const float4* x = (const float4*)(xp + ((long)orig * T + t) * G3);
    const float4* g = (const float4*)(gh + (long)i * G3);
    float4* hp = (float4*)(h + (long)orig * WD);

    float4 xr = x[d], xz = x[Q + d], xn = x[2 * Q + d];
    float4 gr = g[d], gz = g[Q + d], gn = g[2 * Q + d];
    float4 hv = hp[d];

    float4 res;
    const float* pxr = &xr.x; const float* pxz = &xz.x; const float* pxn = &xn.x;
    const float* pgr = &gr.x; const float* pgz = &gz.x; const float* pgn = &gn.x;
    const float* phv = &hv.x; float* pres = &res.x;
#pragma unroll
    for (int c = 0; c < 4; ++c) {
        float r = 1.f / (1.f + expf(-(pxr[c] + pgr[c])));
        float z = 1.f / (1.f + expf(-(pxz[c] + pgz[c])));
        float n = tanhf(pxn[c] + r * pgn[c]);
        pres[c] = (1.f - z) * n + z * phv[c];
    }
    hp[d] = res;
}

// ---------------- va/vb = Wg^T a_src / Wg^T a_dst ----------------------------
__global__ void wgt_vec_kernel(const float* __restrict__ Wg,
                               const float* __restrict__ a_src,
                               const float* __restrict__ a_dst,
                               float* __restrict__ va, float* __restrict__ vb)
{
    int k = blockIdx.x * blockDim.x + threadIdx.x;
    if (k >= HD) return;
    float sa = 0.f, sb = 0.f;
    for (int d = 0; d < HD; ++d) {
        float w = Wg[(long)d * HD + k];
        sa += w * a_src[d];
        sb += w * a_dst[d];
    }
    va[k] = sa;
    vb[k] = sb;
}

// ---------------- GAT dots + softmax + node mix -------------------------------
__global__ void gat_mix_kernel(const float* __restrict__ nodes,
                               const float* __restrict__ va,
                               const float* __restrict__ vb,
                               const unsigned char* __restrict__ amask,
                               float* __restrict__ mix)
{
    int g = blockIdx.x;
    const float* base = nodes + (long)g * NNODE * HD;
    __shared__ float sdots[10];
    __shared__ float salpha[NNODE];

    int tid  = threadIdx.x;
    int warp = tid >> 5, lane = tid & 31;

    float partial = 0.f;
    if (warp < 9) {
        const float* row = base + warp * HD;
        for (int d = lane; d < HD; d += 32) partial += row[d] * vb[d];
    } else {
        for (int d = lane; d < HD; d += 32) partial += base[d] * va[d];
    }
#pragma unroll
    for (int off = 16; off; off >>= 1)
        partial += __shfl_down_sync(0xffffffffu, partial, off);
    if (lane == 0) sdots[warp] = partial;
    __syncthreads();

    if (tid == 0) {
        float es0 = sdots[9];
        float e[NNODE];
#pragma unroll
        for (int j = 0; j < NNODE; ++j) {
            bool valid;
            if (j == 0) valid = true;
            else {
                const unsigned char* m = amask + ((long)g * NA + (j - 1)) * TA;
                valid = !(m[0] && m[1] && m[2] && m[3]);
            }
            if (valid) {
                float v = es0 + sdots[j];
                e[j] = v > 0.f ? v : 0.2f * v;
            } else e[j] = -1e9f;
        }
        float mx = e[0];
#pragma unroll
        for (int j = 1; j < NNODE; ++j) mx = fmaxf(mx, e[j]);
        float s = 0.f, ex[NNODE];
#pragma unroll
        for (int j = 0; j < NNODE; ++j) { ex[j] = expf(e[j] - mx); s += ex[j]; }
        float inv = 1.f / s;
#pragma unroll
        for (int j = 0; j < NNODE; ++j) salpha[j] = ex[j] * inv;
    }
    __syncthreads();

    for (int d = tid; d < HD; d += blockDim.x) {
        float s = 0.f;
#pragma unroll
        for (int j = 0; j < NNODE; ++j) s += salpha[j] * base[j * HD + d];
        mix[(long)g * HD + d] = s;
    }
}

// ---------------- launch ------------------------------------------------------
extern "C" void kernel_launch(void* const* d_in, const int* in_sizes, int n_in,
                              void* d_out, int out_size)
{
    const int*   ent_tok  = (const int*)  d_in[0];
    const int*   ent_len  = (const int*)  d_in[1];
    const int*   at_tok   = (const int*)  d_in[3];
    const int*   at_len   = (const int*)  d_in[4];
    const unsigned char* at_mask = (const unsigned char*)d_in[5];
    const float* emb      = (const float*)d_in[6];
    const float* Wih_ent  = (const float*)d_in[7];
    const float* Whh_ent  = (const float*)d_in[8];
    const float* bih_ent  = (const float*)d_in[9];
    const float* bhh_ent  = (const float*)d_in[10];
    const float* Wih_attr = (const float*)d_in[11];
    const float* Whh_attr = (const float*)d_in[12];
    const float* bih_attr = (const float*)d_in[13];
    const float* bhh_attr = (const float*)d_in[14];
    const float* Wfc      = (const float*)d_in[15];
    const float* bfc      = (const float*)d_in[16];
    const float* Wg       = (const float*)d_in[17];
    const float* a_src    = (const float*)d_in[18];
    const float* a_dst    = (const float*)d_in[19];
    float* out = (float*)d_out;

    float *xp_ent, *xp_attr, *gh, *h_ent, *h_attr, *nodes, *va, *vb;
    int *cntE, *offE, *permE, *mcntE, *cntA, *offA, *permA, *mcntA;
    int *pcE, *gtokE, *orowE, *pcA, *gtokA, *orowA;
    cudaGetSymbolAddress((void**)&xp_ent,  g_xp_ent);
    cudaGetSymbolAddress((void**)&xp_attr, g_xp_attr);
    cudaGetSymbolAddress((void**)&gh,      g_gh);
    cudaGetSymbolAddress((void**)&h_ent,   g_h_ent);
    cudaGetSymbolAddress((void**)&h_attr,  g_h_attr);
    cudaGetSymbolAddress((void**)&nodes,   g_nodes);
    cudaGetSymbolAddress((void**)&va,      g_va);
    cudaGetSymbolAddress((void**)&vb,      g_vb);
    cudaGetSymbolAddress((void**)&cntE,  g_cnt_ent);
    cudaGetSymbolAddress((void**)&offE,  g_off_ent);
    cudaGetSymbolAddress((void**)&permE, g_perm_ent);
    cudaGetSymbolAddress((void**)&mcntE, g_mcnt_ent);
    cudaGetSymbolAddress((void**)&cntA,  g_cnt_attr);
    cudaGetSymbolAddress((void**)&offA,  g_off_attr);
    cudaGetSymbolAddress((void**)&permA, g_perm_attr);
    cudaGetSymbolAddress((void**)&mcntA, g_mcnt_attr);
    cudaGetSymbolAddress((void**)&pcE,   g_paircnt_ent);
    cudaGetSymbolAddress((void**)&gtokE, g_gtok_ent);
    cudaGetSymbolAddress((void**)&orowE, g_orow_ent);
    cudaGetSymbolAddress((void**)&pcA,   g_paircnt_attr);
    cudaGetSymbolAddress((void**)&gtokA, g_gtok_attr);
    cudaGetSymbolAddress((void**)&orowA, g_orow_attr);
    float* mixbuf = gh;

    cudaMemsetAsync(h_ent,  0, (size_t)NG   * WD * sizeof(float));
    cudaMemsetAsync(h_attr, 0, (size_t)NATT * WD * sizeof(float));
    cudaMemsetAsync(cntE, 0, (TE + 1) * sizeof(int));
    cudaMemsetAsync(cntA, 0, (TA + 1) * sizeof(int));
    cudaMemsetAsync(pcE, 0, sizeof(int));
    cudaMemsetAsync(pcA, 0, sizeof(int));

    // length sort + xp pair lists
    hist_kernel<<<(NG + 255) / 256, 256>>>(ent_len, NG, TE, cntE);
    offsets_kernel<<<1, 32>>>(cntE, offE, mcntE, TE);
    scatter_kernel<<<(NG + 255) / 256, 256>>>(ent_len, NG, TE, offE, permE);
    hist_kernel<<<(NATT + 255) / 256, 256>>>(at_len, NATT, TA, cntA);
    offsets_kernel<<<1, 32>>>(cntA, offA, mcntA, TA);
    scatter_kernel<<<(NATT + 255) / 256, 256>>>(at_len, NATT, TA, offA, permA);
    build_pairs<<<(NG * TE + 255) / 256, 256>>>(ent_tok, ent_len, NG, TE, pcE, gtokE, orowE);
    build_pairs<<<(NATT * TA + 255) / 256, 256>>>(at_tok, at_len, NATT, TA, pcA, gtokA, orowA);

    const int cB900  = (G3 + BN - 1) / BN;   // 8
    const int cB1024 = HD / BN;              // 8

    // xp = emb[tok] @ Wih^T + bih  — only valid (row,t) pairs
    sgemm128<<<dim3((NG * TE + BM - 1) / BM, cB900), 256>>>(
        emb, gtokE, Wih_ent, bih_ent, xp_ent, NG * TE, G3, WD, 0, 0, pcE, orowE);
    sgemm128<<<dim3((NATT * TA + BM - 1) / BM, cB900), 256>>>(
        emb, gtokA, Wih_attr, bih_attr, xp_attr, NATT * TA, G3, WD, 0, 0, pcA, orowA);

    wgt_vec_kernel<<<(HD + 255) / 256, 256>>>(Wg, a_src, a_dst, va, vb);

    // entity GRU (compact active rows)
    for (int t = 0; t < TE; ++t) {
        sgemm128<<<dim3(NG / BM, cB900), 256>>>(
            h_ent, permE, Whh_ent, bhh_ent, gh, NG, G3, WD, 0, 0, mcntE + t, nullptr);
        gru_gate4<<<(NG * 75 + 255) / 256, 256>>>(
            xp_ent, gh, h_ent, permE, mcntE + t, t, TE);
    }

    // attribute GRU
    for (int t = 0; t < TA; ++t) {
        sgemm128<<<dim3(NATT / BM, cB900), 256>>>(
            h_attr, permA, Whh_attr, bhh_attr, gh, NATT, G3, WD, 0, 0, mcntA + t, nullptr);
        gru_gate4<<<(NATT * 75 + 255) / 256, 256>>>(
            xp_attr, gh, h_attr, permA, mcntA + t, t, TA);
    }

    // FC + ReLU -> node layout [G, 9, HD]
    sgemm128<<<dim3(NG / BM,   cB1024), 256>>>(
        h_ent,  nullptr, Wfc, bfc, nodes, NG,   HD, WD, 1, 1, nullptr, nullptr);
    sgemm128<<<dim3(NATT / BM, cB1024), 256>>>(
        h_attr, nullptr, Wfc, bfc, nodes, NATT, HD, WD, 1, 2, nullptr, nullptr);

    // GAT: dots + alpha + mix
    gat_mix_kernel<<<NG, 320>>>(nodes, va, vb, at_mask, mixbuf);

    // out = elu(mix @ Wg^T)
    sgemm128<<<dim3(NG / BM, cB1024), 256>>>(
        mixbuf, nullptr, Wg, nullptr, out, NG, HD, HD, 2, 0, nullptr, nullptr);
}

// round 6
// speedup vs baseline: 2.0851x; 1.5090x over previous
#include <cuda_runtime.h>
#include <cuda_bf16.h>
#include <math.h>

// Problem constants
#define BS   128
#define NE   32
#define NA   8
#define TE   8
#define TA   4
#define WD   300
#define HD   1024
#define G3   900          // 3*WD
#define NG   (BS*NE)      // 4096
#define NATT (NG*NA)      // 32768
#define NNODE 9

typedef unsigned long long u64;
typedef unsigned int u32;

// ---------------- scratch ----------------------------------------------------
__device__ float g_xp_ent [NG   * TE * G3];
__device__ float g_xp_attr[NATT * TA * G3];
__device__ float g_gh     [NATT * G3];
__device__ float g_h_ent  [NG   * WD];
__device__ float g_h_attr [NATT * WD];
__device__ float g_nodes  [NG * NNODE * HD];
__device__ float g_va     [HD];
__device__ float g_vb     [HD];
// length-sort scratch
__device__ int g_cnt_ent [TE + 1];
__device__ int g_off_ent [TE + 1];
__device__ int g_perm_ent[NG];
__device__ int g_mcnt_ent[TE];
__device__ int g_cnt_attr [TA + 1];
__device__ int g_off_attr [TA + 1];
__device__ int g_perm_attr[NATT];
__device__ int g_mcnt_attr[TA];
// xp pair-compaction scratch
__device__ int g_paircnt_ent;
__device__ int g_gtok_ent[NG * TE];
__device__ int g_orow_ent[NG * TE];
__device__ int g_paircnt_attr;
__device__ int g_gtok_attr[NATT * TA];
__device__ int g_orow_attr[NATT * TA];

// ---------------- helpers ------------------------------------------------------
__device__ __forceinline__ u32 smem_u32(const void* p) {
    u32 a;
    asm("{ .reg .u64 t; cvta.to.shared.u64 t, %1; cvt.u32.u64 %0, t; }"
        : "=r"(a) : "l"(p));
    return a;
}

#define LDSM_X4(r, addr) \
    asm volatile("ldmatrix.sync.aligned.m8n8.x4.shared.b16 {%0,%1,%2,%3}, [%4];" \
        : "=r"((r)[0]), "=r"((r)[1]), "=r"((r)[2]), "=r"((r)[3]) : "r"(addr))

#define LDSM_X2(r0, r1, addr) \
    asm volatile("ldmatrix.sync.aligned.m8n8.x2.shared.b16 {%0,%1}, [%2];" \
        : "=r"(r0), "=r"(r1) : "r"(addr))

#define MMA16816(c, a, b0, b1) \
    asm volatile("mma.sync.aligned.m16n8k16.row.col.f32.bf16.bf16.f32 " \
        "{%0,%1,%2,%3}, {%4,%5,%6,%7}, {%8,%9}, {%0,%1,%2,%3};" \
        : "+f"((c)[0]), "+f"((c)[1]), "+f"((c)[2]), "+f"((c)[3]) \
        : "r"((a)[0]), "r"((a)[1]), "r"((a)[2]), "r"((a)[3]), "r"(b0), "r"(b1))

#define SWZ(o) ((o) ^ (((o) >> 3) & 0x70u))

// ---------------- tensor GEMM: C = act(A(gather) @ W^T + bias) ----------------
// 128x128 tile, K-chunks of 64 fp32 -> bf16 hi/lo split (3-pass compensation),
// mma.sync m16n8k16 bf16, 8 warps (4x2), warp tile 32x64.
#define TM 128
#define TN 128
#define CK 64
#define ATILE 16384u                 // 128 rows x 128 B (64 bf16/row)
#define OFF_AHI 0u
#define OFF_ALO 16384u
#define OFF_BHI 32768u
#define OFF_BLO 49152u
#define TG_SMEM 65536u

__device__ __forceinline__ void store_pair(char* hiB, char* loB, int r, int kq, float4 v) {
    u32 off = (u32)(r * 128 + kq * 2);
    u32 sw = SWZ(off);
    unsigned short h[4], l[4];
    const float* pv = &v.x;
#pragma unroll
    for (int i = 0; i < 4; ++i) {
        float x = pv[i];
        __nv_bfloat16 hb = __float2bfloat16(x);
        float res = x - __bfloat162float(hb);
        __nv_bfloat16 lb = __float2bfloat16(res);
        h[i] = __bfloat16_as_ushort(hb);
        l[i] = __bfloat16_as_ushort(lb);
    }
    *(u64*)(hiB + sw) = (u64)h[0] | ((u64)h[1] << 16) | ((u64)h[2] << 32) | ((u64)h[3] << 48);
    *(u64*)(loB + sw) = (u64)l[0] | ((u64)l[1] << 16) | ((u64)l[2] << 32) | ((u64)l[3] << 48);
}

__global__ void __launch_bounds__(256, 2)
tgemm(const float* __restrict__ A, const int* __restrict__ gather,
      const float* __restrict__ W, const float* __restrict__ bias,
      float* __restrict__ C, int M, int N, int K, int act, int outMap,
      const int* __restrict__ mlimit, const int* __restrict__ orow)
{
    extern __shared__ char smem[];
    int Mdyn = M;
    if (mlimit) { Mdyn = *mlimit; if (Mdyn > M) Mdyn = M; }
    const int m0 = blockIdx.x * TM;
    const int n0 = blockIdx.y * TN;
    if (m0 >= Mdyn) return;

    const u32 sbase = smem_u32(smem);
    const int tid  = threadIdx.x;
    const int wid  = tid >> 5;
    const int lane = tid & 31;
    const int wm   = wid >> 1;        // 0..3 -> rows wm*32
    const int wn   = wid & 1;         // 0..1 -> cols wn*64

    // ldmatrix per-lane address components (xor-swizzle quad index)
    const u32 rbA0 = (u32)((wm * 32 + (lane & 15)) * 128);
    const u32 rbA1 = rbA0 + 16u * 128u;
    const u32 rbB  = (u32)((wn * 64 + (lane & 7)) * 128);
    const u32 xorq = (u32)(lane & 7);
    const u32 qAh  = (u32)(lane >> 4);         // 0/1
    const u32 qBh  = (u32)((lane >> 3) & 1);   // 0/1

    float acc[2][8][4];
#pragma unroll
    for (int i = 0; i < 2; ++i)
#pragma unroll
        for (int j = 0; j < 8; ++j)
#pragma unroll
            for (int q = 0; q < 4; ++q) acc[i][j][q] = 0.f;

    const float* Arow[1];
    (void)Arow;
    const int nc = (K + CK - 1) / CK;
    const float4 z4 = make_float4(0.f, 0.f, 0.f, 0.f);

    for (int c = 0; c < nc; ++c) {
        if (c) __syncthreads();               // smem reuse barrier
        const int k0 = c * CK;
        char* sAhi = smem + OFF_AHI;
        char* sAlo = smem + OFF_ALO;
        char* sBhi = smem + OFF_BHI;
        char* sBlo = smem + OFF_BLO;

        // load + convert A tile [128 x 64]
#pragma unroll
        for (int it = 0; it < 8; ++it) {
            int s = it * 256 + tid;
            int r = s >> 4;
            int kq = (s & 15) << 2;
            int gk = k0 + kq;
            int m = m0 + r;
            float4 v = z4;
            if (m < Mdyn && gk < K) {
                const float* rp = gather ? A + (long)gather[m] * K : A + (long)m * K;
                v = *(const float4*)(rp + gk);
            }
            store_pair(sAhi, sAlo, r, kq, v);
        }
        // load + convert B tile [128 x 64]
#pragma unroll
        for (int it = 0; it < 8; ++it) {
            int s = it * 256 + tid;
            int r = s >> 4;
            int kq = (s & 15) << 2;
            int gk = k0 + kq;
            int n = n0 + r;
            float4 v = z4;
            if (n < N && gk < K) v = *(const float4*)(W + (long)n * K + gk);
            store_pair(sBhi, sBlo, r, kq, v);
        }
        __syncthreads();

        // 3 compensation passes: AhiBhi, AloBhi, AhiBlo (all sum into acc)
        const u32 aoffs[3] = { OFF_AHI, OFF_ALO, OFF_AHI };
        const u32 boffs[3] = { OFF_BHI, OFF_BHI, OFF_BLO };
#pragma unroll
        for (int ps = 0; ps < 3; ++ps) {
            const u32 ab = sbase + aoffs[ps];
            const u32 bb = sbase + boffs[ps];
#pragma unroll
            for (int ks = 0; ks < 4; ++ks) {
                u32 qa = (((u32)(2 * ks) + qAh) ^ xorq) * 16u;
                u32 a0[4], a1[4];
                LDSM_X4(a0, ab + rbA0 + qa);
                LDSM_X4(a1, ab + rbA1 + qa);
                u32 qb = (((u32)(2 * ks) + qBh) ^ xorq) * 16u;
#pragma unroll
                for (int nb = 0; nb < 8; ++nb) {
                    u32 b0, b1;
                    LDSM_X2(b0, b1, bb + rbB + (u32)nb * 1024u + qb);
                    MMA16816(acc[0][nb], a0, b0, b1);
                    MMA16816(acc[1][nb], a1, b0, b1);
                }
            }
        }
    }

    // epilogue: acc[mi][nb][half*2+q] -> row m0+wm*32+mi*16+(lane>>2)+half*8,
    //           col n0+wn*64+nb*8+(lane&3)*2+q
#pragma unroll
    for (int mi = 0; mi < 2; ++mi) {
#pragma unroll
        for (int half = 0; half < 2; ++half) {
            int m = m0 + wm * 32 + mi * 16 + (lane >> 2) + half * 8;
            if (m >= Mdyn) continue;
            long base;
            if (orow)             base = (long)orow[m] * N;
            else if (outMap == 0) base = (long)m * N;
            else if (outMap == 1) base = (long)m * NNODE * HD;
            else                  base = ((long)(m >> 3) * NNODE + 1 + (m & 7)) * (long)HD;
#pragma unroll
            for (int nb = 0; nb < 8; ++nb) {
                int n = n0 + wn * 64 + nb * 8 + (lane & 3) * 2;
                if (n >= N) continue;
                float x0 = acc[mi][nb][half * 2 + 0];
                float x1 = acc[mi][nb][half * 2 + 1];
                if (bias) { x0 += bias[n]; x1 += bias[n + 1]; }
                if (act == 1)      { x0 = fmaxf(x0, 0.f); x1 = fmaxf(x1, 0.f); }
                else if (act == 2) { x0 = x0 > 0.f ? x0 : expm1f(x0);
                                     x1 = x1 > 0.f ? x1 : expm1f(x1); }
                float2 v = make_float2(x0, x1);
                *(float2*)(C + base + n) = v;
            }
        }
    }
}

// ---------------- counting sort by length (descending) -----------------------
__global__ void hist_kernel(const int* __restrict__ len, int n, int T,
                            int* __restrict__ cnt)
{
    int i = blockIdx.x * blockDim.x + threadIdx.x;
    if (i >= n) return;
    int L = len[i]; L = L < 1 ? 1 : (L > T ? T : L);
    atomicAdd(&cnt[L], 1);
}
__global__ void offsets_kernel(const int* __restrict__ cnt,
                               int* __restrict__ off, int* __restrict__ mcnt, int T)
{
    if (threadIdx.x != 0 || blockIdx.x != 0) return;
    int run = 0;
    for (int L = T; L >= 1; --L) { off[L] = run; run += cnt[L]; }
    for (int t = 0; t < T; ++t) {
        int s = 0;
        for (int L = t + 1; L <= T; ++L) s += cnt[L];
        mcnt[t] = s;
    }
}
__global__ void scatter_kernel(const int* __restrict__ len, int n, int T,
                               int* __restrict__ off, int* __restrict__ perm)
{
    int i = blockIdx.x * blockDim.x + threadIdx.x;
    if (i >= n) return;
    int L = len[i]; L = L < 1 ? 1 : (L > T ? T : L);
    int pos = atomicAdd(&off[L], 1);
    perm[pos] = i;
}

// ---------------- xp pair compaction ------------------------------------------
__global__ void build_pairs(const int* __restrict__ tok,
                            const int* __restrict__ len, int n, int T,
                            int* __restrict__ cnt,
                            int* __restrict__ gtok, int* __restrict__ orow)
{
    int p = blockIdx.x * blockDim.x + threadIdx.x;
    if (p >= n * T) return;
    int i = p / T, t = p - i * T;
    int L = len[i]; L = L < 1 ? 1 : (L > T ? T : L);
    if (t >= L) return;
    int pos = atomicAdd(cnt, 1);
    gtok[pos] = tok[p];
    orow[pos] = p;
}

// ---------------- GRU gate update (compact rows, float4) ---------------------
__global__ void gru_gate4(const float* __restrict__ xp,
                          const float* __restrict__ gh,
                          float* __restrict__ h,
                          const int* __restrict__ perm,
                          const int* __restrict__ mcnt,
                          int t, int T)
{
    const int Q = WD / 4;   // 75
    int idx = blockIdx.x * blockDim.x + threadIdx.x;
    int i = idx / Q;
    if (i >= *mcnt) return;
    int d = idx - i * Q;
    int orig = perm[i];
    const float4* x = (const float4*)(xp + ((long)orig * T + t) * G3);
    const float4* g = (const float4*)(gh + (long)i * G3);
    float4* hp = (float4*)(h + (long)orig * WD);

    float4 xr = x[d], xz = x[Q + d], xn = x[2 * Q + d];
    float4 gr = g[d], gz = g[Q + d], gn = g[2 * Q + d];
    float4 hv = hp[d];

    float4 res;
    const float* pxr = &xr.x; const float* pxz = &xz.x; const float* pxn = &xn.x;
    const float* pgr = &gr.x; const float* pgz = &gz.x; const float* pgn = &gn.x;
    const float* phv = &hv.x; float* pres = &res.x;
#pragma unroll
    for (int c = 0; c < 4; ++c) {
        float r = 1.f / (1.f + expf(-(pxr[c] + pgr[c])));
        float z = 1.f / (1.f + expf(-(pxz[c] + pgz[c])));
        float n = tanhf(pxn[c] + r * pgn[c]);
        pres[c] = (1.f - z) * n + z * phv[c];
    }
    hp[d] = res;
}

// ---------------- va/vb = Wg^T a_src / Wg^T a_dst ----------------------------
__global__ void wgt_vec_kernel(const float* __restrict__ Wg,
                               const float* __restrict__ a_src,
                               const float* __restrict__ a_dst,
                               float* __restrict__ va, float* __restrict__ vb)
{
    int k = blockIdx.x * blockDim.x + threadIdx.x;
    if (k >= HD) return;
    float sa = 0.f, sb = 0.f;
    for (int d = 0; d < HD; ++d) {
        float w = Wg[(long)d * HD + k];
        sa += w * a_src[d];
        sb += w * a_dst[d];
    }
    va[k] = sa;
    vb[k] = sb;
}

// ---------------- GAT dots + softmax + node mix -------------------------------
__global__ void gat_mix_kernel(const float* __restrict__ nodes,
                               const float* __restrict__ va,
                               const float* __restrict__ vb,
                               const unsigned char* __restrict__ amask,
                               float* __restrict__ mix)
{
    int g = blockIdx.x;
    const float* base = nodes + (long)g * NNODE * HD;
    __shared__ float sdots[10];
    __shared__ float salpha[NNODE];

    int tid  = threadIdx.x;
    int warp = tid >> 5, lane = tid & 31;

    float partial = 0.f;
    if (warp < 9) {
        const float* row = base + warp * HD;
        for (int d = lane; d < HD; d += 32) partial += row[d] * vb[d];
    } else {
        for (int d = lane; d < HD; d += 32) partial += base[d] * va[d];
    }
#pragma unroll
    for (int off = 16; off; off >>= 1)
        partial += __shfl_down_sync(0xffffffffu, partial, off);
    if (lane == 0) sdots[warp] = partial;
    __syncthreads();

    if (tid == 0) {
        float es0 = sdots[9];
        float e[NNODE];
#pragma unroll
        for (int j = 0; j < NNODE; ++j) {
            bool valid;
            if (j == 0) valid = true;
            else {
                const unsigned char* mk = amask + ((long)g * NA + (j - 1)) * TA;
                valid = !(mk[0] && mk[1] && mk[2] && mk[3]);
            }
            if (valid) {
                float v = es0 + sdots[j];
                e[j] = v > 0.f ? v : 0.2f * v;
            } else e[j] = -1e9f;
        }
        float mx = e[0];
#pragma unroll
        for (int j = 1; j < NNODE; ++j) mx = fmaxf(mx, e[j]);
        float s = 0.f, ex[NNODE];
#pragma unroll
        for (int j = 0; j < NNODE; ++j) { ex[j] = expf(e[j] - mx); s += ex[j]; }
        float inv = 1.f / s;
#pragma unroll
        for (int j = 0; j < NNODE; ++j) salpha[j] = ex[j] * inv;
    }
    __syncthreads();

    for (int d = tid; d < HD; d += blockDim.x) {
        float s = 0.f;
#pragma unroll
        for (int j = 0; j < NNODE; ++j) s += salpha[j] * base[j * HD + d];
        mix[(long)g * HD + d] = s;
    }
}

// ---------------- launch ------------------------------------------------------
extern "C" void kernel_launch(void* const* d_in, const int* in_sizes, int n_in,
                              void* d_out, int out_size)
{
    const int*   ent_tok  = (const int*)  d_in[0];
    const int*   ent_len  = (const int*)  d_in[1];
    const int*   at_tok   = (const int*)  d_in[3];
    const int*   at_len   = (const int*)  d_in[4];
    const unsigned char* at_mask = (const unsigned char*)d_in[5];
    const float* emb      = (const float*)d_in[6];
    const float* Wih_ent  = (const float*)d_in[7];
    const float* Whh_ent  = (const float*)d_in[8];
    const float* bih_ent  = (const float*)d_in[9];
    const float* bhh_ent  = (const float*)d_in[10];
    const float* Wih_attr = (const float*)d_in[11];
    const float* Whh_attr = (const float*)d_in[12];
    const float* bih_attr = (const float*)d_in[13];
    const float* bhh_attr = (const float*)d_in[14];
    const float* Wfc      = (const float*)d_in[15];
    const float* bfc      = (const float*)d_in[16];
    const float* Wg       = (const float*)d_in[17];
    const float* a_src    = (const float*)d_in[18];
    const float* a_dst    = (const float*)d_in[19];
    float* out = (float*)d_out;

    float *xp_ent, *xp_attr, *gh, *h_ent, *h_attr, *nodes, *va, *vb;
    int *cntE, *offE, *permE, *mcntE, *cntA, *offA, *permA, *mcntA;
    int *pcE, *gtokE, *orowE, *pcA, *gtokA, *orowA;
    cudaGetSymbolAddress((void**)&xp_ent,  g_xp_ent);
    cudaGetSymbolAddress((void**)&xp_attr, g_xp_attr);
    cudaGetSymbolAddress((void**)&gh,      g_gh);
    cudaGetSymbolAddress((void**)&h_ent,   g_h_ent);
    cudaGetSymbolAddress((void**)&h_attr,  g_h_attr);
    cudaGetSymbolAddress((void**)&nodes,   g_nodes);
    cudaGetSymbolAddress((void**)&va,      g_va);
    cudaGetSymbolAddress((void**)&vb,      g_vb);
    cudaGetSymbolAddress((void**)&cntE,  g_cnt_ent);
    cudaGetSymbolAddress((void**)&offE,  g_off_ent);
    cudaGetSymbolAddress((void**)&permE, g_perm_ent);
    cudaGetSymbolAddress((void**)&mcntE, g_mcnt_ent);
    cudaGetSymbolAddress((void**)&cntA,  g_cnt_attr);
    cudaGetSymbolAddress((void**)&offA,  g_off_attr);
    cudaGetSymbolAddress((void**)&permA, g_perm_attr);
    cudaGetSymbolAddress((void**)&mcntA, g_mcnt_attr);
    cudaGetSymbolAddress((void**)&pcE,   g_paircnt_ent);
    cudaGetSymbolAddress((void**)&gtokE, g_gtok_ent);
    cudaGetSymbolAddress((void**)&orowE, g_orow_ent);
    cudaGetSymbolAddress((void**)&pcA,   g_paircnt_attr);
    cudaGetSymbolAddress((void**)&gtokA, g_gtok_attr);
    cudaGetSymbolAddress((void**)&orowA, g_orow_attr);
    float* mixbuf = gh;

    cudaFuncSetAttribute(tgemm, cudaFuncAttributeMaxDynamicSharedMemorySize, TG_SMEM);

    cudaMemsetAsync(h_ent,  0, (size_t)NG   * WD * sizeof(float));
    cudaMemsetAsync(h_attr, 0, (size_t)NATT * WD * sizeof(float));
    cudaMemsetAsync(cntE, 0, (TE + 1) * sizeof(int));
    cudaMemsetAsync(cntA, 0, (TA + 1) * sizeof(int));
    cudaMemsetAsync(pcE, 0, sizeof(int));
    cudaMemsetAsync(pcA, 0, sizeof(int));

    hist_kernel<<<(NG + 255) / 256, 256>>>(ent_len, NG, TE, cntE);
    offsets_kernel<<<1, 32>>>(cntE, offE, mcntE, TE);
    scatter_kernel<<<(NG + 255) / 256, 256>>>(ent_len, NG, TE, offE, permE);
    hist_kernel<<<(NATT + 255) / 256, 256>>>(at_len, NATT, TA, cntA);
    offsets_kernel<<<1, 32>>>(cntA, offA, mcntA, TA);
    scatter_kernel<<<(NATT + 255) / 256, 256>>>(at_len, NATT, TA, offA, permA);
    build_pairs<<<(NG * TE + 255) / 256, 256>>>(ent_tok, ent_len, NG, TE, pcE, gtokE, orowE);
    build_pairs<<<(NATT * TA + 255) / 256, 256>>>(at_tok, at_len, NATT, TA, pcA, gtokA, orowA);

    const int nt900  = (G3 + TN - 1) / TN;   // 8
    const int nt1024 = HD / TN;              // 8

    // xp = emb[tok] @ Wih^T + bih — valid (row,t) pairs only
    tgemm<<<dim3(NG * TE / TM, nt900), 256, TG_SMEM>>>(
        emb, gtokE, Wih_ent, bih_ent, xp_ent, NG * TE, G3, WD, 0, 0, pcE, orowE);
    tgemm<<<dim3(NATT * TA / TM, nt900), 256, TG_SMEM>>>(
        emb, gtokA, Wih_attr, bih_attr, xp_attr, NATT * TA, G3, WD, 0, 0, pcA, orowA);

    wgt_vec_kernel<<<(HD + 255) / 256, 256>>>(Wg, a_src, a_dst, va, vb);

    // entity GRU
    for (int t = 0; t < TE; ++t) {
        tgemm<<<dim3(NG / TM, nt900), 256, TG_SMEM>>>(
            h_ent, permE, Whh_ent, bhh_ent, gh, NG, G3, WD, 0, 0, mcntE + t, nullptr);
        gru_gate4<<<(NG * 75 + 255) / 256, 256>>>(
            xp_ent, gh, h_ent, permE, mcntE + t, t, TE);
    }

    // attribute GRU
    for (int t = 0; t < TA; ++t) {
        tgemm<<<dim3(NATT / TM, nt900), 256, TG_SMEM>>>(
            h_attr, permA, Whh_attr, bhh_attr, gh, NATT, G3, WD, 0, 0, mcntA + t, nullptr);
        gru_gate4<<<(NATT * 75 + 255) / 256, 256>>>(
            xp_attr, gh, h_attr, permA, mcntA + t, t, TA);
    }

    // FC + ReLU -> node layout [G, 9, HD]
    tgemm<<<dim3(NG / TM,   nt1024), 256, TG_SMEM>>>(
        h_ent,  nullptr, Wfc, bfc, nodes, NG,   HD, WD, 1, 1, nullptr, nullptr);
    tgemm<<<dim3(NATT / TM, nt1024), 256, TG_SMEM>>>(
        h_attr, nullptr, Wfc, bfc, nodes, NATT, HD, WD, 1, 2, nullptr, nullptr);

    // GAT: dots + alpha + mix
    gat_mix_kernel<<<NG, 320>>>(nodes, va, vb, at_mask, mixbuf);

    // out = elu(mix @ Wg^T)
    tgemm<<<dim3(NG / TM, nt1024), 256, TG_SMEM>>>(
        mixbuf, nullptr, Wg, nullptr, out, NG, HD, HD, 2, 0, nullptr, nullptr);
}

// round 7
// speedup vs baseline: 2.4004x; 1.1512x over previous
#include <cuda_runtime.h>
#include <cuda_bf16.h>
#include <math.h>

// Problem constants
#define BS   128
#define NE   32
#define NA   8
#define TE   8
#define TA   4
#define WD   300
#define HD   1024
#define G3   900          // 3*WD
#define NG   (BS*NE)      // 4096
#define NATT (NG*NA)      // 32768
#define NNODE 9
#define V    30522

typedef unsigned long long u64;
typedef unsigned int u32;

// ---------------- scratch ----------------------------------------------------
__device__ float g_xp_ent [NG   * TE * G3];
__device__ float g_xp_attr[NATT * TA * G3];
__device__ float g_gh     [NATT * G3];
__device__ float g_h_ent  [NG   * WD];
__device__ float g_h_attr [NATT * WD];
__device__ float g_nodes  [NG * NNODE * HD];
__device__ float g_va     [HD];
__device__ float g_vb     [HD];
// bf16 hi/lo operand buffers
__device__ __nv_bfloat16 g_emb_hi[V * WD];
__device__ __nv_bfloat16 g_emb_lo[V * WD];
__device__ __nv_bfloat16 g_wihe_hi[G3 * WD];
__device__ __nv_bfloat16 g_wihe_lo[G3 * WD];
__device__ __nv_bfloat16 g_whhe_hi[G3 * WD];
__device__ __nv_bfloat16 g_whhe_lo[G3 * WD];
__device__ __nv_bfloat16 g_wiha_hi[G3 * WD];
__device__ __nv_bfloat16 g_wiha_lo[G3 * WD];
__device__ __nv_bfloat16 g_whha_hi[G3 * WD];
__device__ __nv_bfloat16 g_whha_lo[G3 * WD];
__device__ __nv_bfloat16 g_wfc_hi[HD * WD];
__device__ __nv_bfloat16 g_wfc_lo[HD * WD];
__device__ __nv_bfloat16 g_wg_hi[HD * HD];
__device__ __nv_bfloat16 g_wg_lo[HD * HD];
__device__ __nv_bfloat16 g_he_hi[NG * WD];
__device__ __nv_bfloat16 g_he_lo[NG * WD];
__device__ __nv_bfloat16 g_ha_hi[NATT * WD];
__device__ __nv_bfloat16 g_ha_lo[NATT * WD];
__device__ __nv_bfloat16 g_mix_hi[NG * HD];
__device__ __nv_bfloat16 g_mix_lo[NG * HD];
// length-sort scratch
__device__ int g_cnt_ent [TE + 1];
__device__ int g_off_ent [TE + 1];
__device__ int g_perm_ent[NG];
__device__ int g_mcnt_ent[TE];
__device__ int g_cnt_attr [TA + 1];
__device__ int g_off_attr [TA + 1];
__device__ int g_perm_attr[NATT];
__device__ int g_mcnt_attr[TA];
// xp pair-compaction scratch
__device__ int g_paircnt_ent;
__device__ int g_gtok_ent[NG * TE];
__device__ int g_orow_ent[NG * TE];
__device__ int g_paircnt_attr;
__device__ int g_gtok_attr[NATT * TA];
__device__ int g_orow_attr[NATT * TA];

// ---------------- helpers ------------------------------------------------------
__device__ __forceinline__ u32 smem_u32(const void* p) {
    u32 a;
    asm("{ .reg .u64 t; cvta.to.shared.u64 t, %1; cvt.u32.u64 %0, t; }"
        : "=r"(a) : "l"(p));
    return a;
}

#define LDSM_X4(r, addr) \
    asm volatile("ldmatrix.sync.aligned.m8n8.x4.shared.b16 {%0,%1,%2,%3}, [%4];" \
        : "=r"((r)[0]), "=r"((r)[1]), "=r"((r)[2]), "=r"((r)[3]) : "r"(addr))

#define LDSM_X2(r0, r1, addr) \
    asm volatile("ldmatrix.sync.aligned.m8n8.x2.shared.b16 {%0,%1}, [%2];" \
        : "=r"(r0), "=r"(r1) : "r"(addr))

#define MMA16816(c, a, b0, b1) \
    asm volatile("mma.sync.aligned.m16n8k16.row.col.f32.bf16.bf16.f32 " \
        "{%0,%1,%2,%3}, {%4,%5,%6,%7}, {%8,%9}, {%0,%1,%2,%3};" \
        : "+f"((c)[0]), "+f"((c)[1]), "+f"((c)[2]), "+f"((c)[3]) \
        : "r"((a)[0]), "r"((a)[1]), "r"((a)[2]), "r"((a)[3]), "r"(b0), "r"(b1))

#define SWZ(o) ((o) ^ (((o) >> 3) & 0x70u))

__device__ __forceinline__ void split1(float x, __nv_bfloat16& h, __nv_bfloat16& l) {
    h = __float2bfloat16(x);
    l = __float2bfloat16(x - __bfloat162float(h));
}
__device__ __forceinline__ void split4(float4 v, u64& hq, u64& lq) {
    unsigned short h[4], l[4];
    const float* pv = &v.x;
#pragma unroll
    for (int i = 0; i < 4; ++i) {
        __nv_bfloat16 hb, lb;
        split1(pv[i], hb, lb);
        h[i] = __bfloat16_as_ushort(hb);
        l[i] = __bfloat16_as_ushort(lb);
    }
    hq = (u64)h[0] | ((u64)h[1] << 16) | ((u64)h[2] << 32) | ((u64)h[3] << 48);
    lq = (u64)l[0] | ((u64)l[1] << 16) | ((u64)l[2] << 32) | ((u64)l[3] << 48);
}

// ---------------- fp32 -> bf16 hi/lo split (elementwise) ---------------------
__global__ void split_kernel(const float* __restrict__ x,
                             __nv_bfloat16* __restrict__ hi,
                             __nv_bfloat16* __restrict__ lo, int n4)
{
    int i = blockIdx.x * blockDim.x + threadIdx.x;
    if (i >= n4) return;
    float4 v = *(const float4*)(x + 4 * (long)i);
    u64 hq, lq;
    split4(v, hq, lq);
    *(u64*)(hi + 4 * (long)i) = hq;
    *(u64*)(lo + 4 * (long)i) = lq;
}

// ---------------- tensor GEMM (bf16 operands): C = act(A @ B^T + bias) -------
// 128x128 tile, K-chunks of 64, 3-pass hi/lo compensation, mma.sync m16n8k16.
#define TM 128
#define TN 128
#define CK 64
#define OFF_AHI 0u
#define OFF_ALO 16384u
#define OFF_BHI 32768u
#define OFF_BLO 49152u
#define TG_SMEM 65536u

__global__ void __launch_bounds__(256, 2)
tgemm(const __nv_bfloat16* __restrict__ Ahi, const __nv_bfloat16* __restrict__ Alo,
      const int* __restrict__ gather,
      const __nv_bfloat16* __restrict__ Bhi, const __nv_bfloat16* __restrict__ Blo,
      const float* __restrict__ bias,
      float* __restrict__ C, int M, int N, int K, int act, int outMap,
      const int* __restrict__ mlimit, const int* __restrict__ orow)
{
    extern __shared__ char smem[];
    int Mdyn = M;
    if (mlimit) { Mdyn = *mlimit; if (Mdyn > M) Mdyn = M; }
    const int m0 = blockIdx.x * TM;
    const int n0 = blockIdx.y * TN;
    if (m0 >= Mdyn) return;

    const u32 sbase = smem_u32(smem);
    const int tid  = threadIdx.x;
    const int wid  = tid >> 5;
    const int lane = tid & 31;
    const int wm   = wid >> 1;
    const int wn   = wid & 1;

    const u32 rbA0 = (u32)((wm * 32 + (lane & 15)) * 128);
    const u32 rbA1 = rbA0 + 16u * 128u;
    const u32 rbB  = (u32)((wn * 64 + (lane & 7)) * 128);
    const u32 xorq = (u32)(lane & 7);
    const u32 qAh  = (u32)(lane >> 4);
    const u32 qBh  = (u32)((lane >> 3) & 1);

    float acc[2][8][4];
#pragma unroll
    for (int i = 0; i < 2; ++i)
#pragma unroll
        for (int j = 0; j < 8; ++j)
#pragma unroll
            for (int q = 0; q < 4; ++q) acc[i][j][q] = 0.f;

    const int nc = (K + CK - 1) / CK;

    for (int c = 0; c < nc; ++c) {
        if (c) __syncthreads();
        const int k0 = c * CK;

        // fill A hi/lo tiles [128 x 64] — 8 iters x 256 threads, u64 loads
#pragma unroll
        for (int it = 0; it < 8; ++it) {
            int s = it * 256 + tid;
            int r = s >> 4;
            int kq = (s & 15) << 2;
            int gk = k0 + kq;
            int m = m0 + r;
            u64 hq = 0, lq = 0;
            if (m < Mdyn && gk < K) {
                long ro = gather ? (long)gather[m] * K : (long)m * K;
                hq = *(const u64*)(Ahi + ro + gk);
                lq = *(const u64*)(Alo + ro + gk);
            }
            u32 sw = SWZ((u32)(r * 128 + kq * 2));
            *(u64*)(smem + OFF_AHI + sw) = hq;
            *(u64*)(smem + OFF_ALO + sw) = lq;
        }
        // fill B hi/lo tiles [128 x 64]
#pragma unroll
        for (int it = 0; it < 8; ++it) {
            int s = it * 256 + tid;
            int r = s >> 4;
            int kq = (s & 15) << 2;
            int gk = k0 + kq;
            int n = n0 + r;
            u64 hq = 0, lq = 0;
            if (n < N && gk < K) {
                long ro = (long)n * K;
                hq = *(const u64*)(Bhi + ro + gk);
                lq = *(const u64*)(Blo + ro + gk);
            }
            u32 sw = SWZ((u32)(r * 128 + kq * 2));
            *(u64*)(smem + OFF_BHI + sw) = hq;
            *(u64*)(smem + OFF_BLO + sw) = lq;
        }
        __syncthreads();

        const u32 aoffs[3] = { OFF_AHI, OFF_ALO, OFF_AHI };
        const u32 boffs[3] = { OFF_BHI, OFF_BHI, OFF_BLO };
#pragma unroll
        for (int ps = 0; ps < 3; ++ps) {
            const u32 ab = sbase + aoffs[ps];
            const u32 bb = sbase + boffs[ps];
#pragma unroll
            for (int ks = 0; ks < 4; ++ks) {
                u32 qa = (((u32)(2 * ks) + qAh) ^ xorq) * 16u;
                u32 a0[4], a1[4];
                LDSM_X4(a0, ab + rbA0 + qa);
                LDSM_X4(a1, ab + rbA1 + qa);
                u32 qb = (((u32)(2 * ks) + qBh) ^ xorq) * 16u;
#pragma unroll
                for (int nb = 0; nb < 8; ++nb) {
                    u32 b0, b1;
                    LDSM_X2(b0, b1, bb + rbB + (u32)nb * 1024u + qb);
                    MMA16816(acc[0][nb], a0, b0, b1);
                    MMA16816(acc[1][nb], a1, b0, b1);
                }
            }
        }
    }

    // epilogue
#pragma unroll
    for (int mi = 0; mi < 2; ++mi) {
#pragma unroll
        for (int half = 0; half < 2; ++half) {
            int m = m0 + wm * 32 + mi * 16 + (lane >> 2) + half * 8;
            if (m >= Mdyn) continue;
            long base;
            if (orow)             base = (long)orow[m] * N;
            else if (outMap == 0) base = (long)m * N;
            else if (outMap == 1) base = (long)m * NNODE * HD;
            else                  base = ((long)(m >> 3) * NNODE + 1 + (m & 7)) * (long)HD;
#pragma unroll
            for (int nb = 0; nb < 8; ++nb) {
                int n = n0 + wn * 64 + nb * 8 + (lane & 3) * 2;
                if (n >= N) continue;
                float x0 = acc[mi][nb][half * 2 + 0];
                float x1 = acc[mi][nb][half * 2 + 1];
                if (bias) { x0 += bias[n]; x1 += bias[n + 1]; }
                if (act == 1)      { x0 = fmaxf(x0, 0.f); x1 = fmaxf(x1, 0.f); }
                else if (act == 2) { x0 = x0 > 0.f ? x0 : expm1f(x0);
                                     x1 = x1 > 0.f ? x1 : expm1f(x1); }
                *(float2*)(C + base + n) = make_float2(x0, x1);
            }
        }
    }
}

// ---------------- counting sort by length (descending) -----------------------
__global__ void hist_kernel(const int* __restrict__ len, int n, int T,
                            int* __restrict__ cnt)
{
    int i = blockIdx.x * blockDim.x + threadIdx.x;
    if (i >= n) return;
    int L = len[i]; L = L < 1 ? 1 : (L > T ? T : L);
    atomicAdd(&cnt[L], 1);
}
__global__ void offsets_kernel(const int* __restrict__ cnt,
                               int* __restrict__ off, int* __restrict__ mcnt, int T)
{
    if (threadIdx.x != 0 || blockIdx.x != 0) return;
    int run = 0;
    for (int L = T; L >= 1; --L) { off[L] = run; run += cnt[L]; }
    for (int t = 0; t < T; ++t) {
        int s = 0;
        for (int L = t + 1; L <= T; ++L) s += cnt[L];
        mcnt[t] = s;
    }
}
__global__ void scatter_kernel(const int* __restrict__ len, int n, int T,
                               int* __restrict__ off, int* __restrict__ perm)
{
    int i = blockIdx.x * blockDim.x + threadIdx.x;
    if (i >= n) return;
    int L = len[i]; L = L < 1 ? 1 : (L > T ? T : L);
    int pos = atomicAdd(&off[L], 1);
    perm[pos] = i;
}

// ---------------- xp pair compaction ------------------------------------------
__global__ void build_pairs(const int* __restrict__ tok,
                            const int* __restrict__ len, int n, int T,
                            int* __restrict__ cnt,
                            int* __restrict__ gtok, int* __restrict__ orow)
{
    int p = blockIdx.x * blockDim.x + threadIdx.x;
    if (p >= n * T) return;
    int i = p / T, t = p - i * T;
    int L = len[i]; L = L < 1 ? 1 : (L > T ? T : L);
    if (t >= L) return;
    int pos = atomicAdd(cnt, 1);
    gtok[pos] = tok[p];
    orow[pos] = p;
}

// ---------------- GRU gate update (compact rows; writes fp32 + bf16 hi/lo) ---
__global__ void gru_gate4(const float* __restrict__ xp,
                          const float* __restrict__ gh,
                          float* __restrict__ h,
                          __nv_bfloat16* __restrict__ hhi,
                          __nv_bfloat16* __restrict__ hlo,
                          const int* __restrict__ perm,
                          const int* __restrict__ mcnt,
                          int t, int T)
{
    const int Q = WD / 4;   // 75
    int idx = blockIdx.x * blockDim.x + threadIdx.x;
    int i = idx / Q;
    if (i >= *mcnt) return;
    int d = idx - i * Q;
    int orig = perm[i];
    const float4* x = (const float4*)(xp + ((long)orig * T + t) * G3);
    const float4* g = (const float4*)(gh + (long)i * G3);
    float4* hp = (float4*)(h + (long)orig * WD);

    float4 xr = x[d], xz = x[Q + d], xn = x[2 * Q + d];
    float4 gr = g[d], gz = g[Q + d], gn = g[2 * Q + d];
    float4 hv = hp[d];

    float4 res;
    const float* pxr = &xr.x; const float* pxz = &xz.x; const float* pxn = &xn.x;
    const float* pgr = &gr.x; const float* pgz = &gz.x; const float* pgn = &gn.x;
    const float* phv = &hv.x; float* pres = &res.x;
#pragma unroll
    for (int c = 0; c < 4; ++c) {
        float r = 1.f / (1.f + expf(-(pxr[c] + pgr[c])));
        float z = 1.f / (1.f + expf(-(pxz[c] + pgz[c])));
        float n = tanhf(pxn[c] + r * pgn[c]);
        pres[c] = (1.f - z) * n + z * phv[c];
    }
    hp[d] = res;
    u64 hq, lq;
    split4(res, hq, lq);
    *(u64*)(hhi + (long)orig * WD + 4 * d) = hq;
    *(u64*)(hlo + (long)orig * WD + 4 * d) = lq;
}

// ---------------- va/vb = Wg^T a_src / Wg^T a_dst ----------------------------
__global__ void wgt_vec_kernel(const float* __restrict__ Wg,
                               const float* __restrict__ a_src,
                               const float* __restrict__ a_dst,
                               float* __restrict__ va, float* __restrict__ vb)
{
    int k = blockIdx.x * blockDim.x + threadIdx.x;
    if (k >= HD) return;
    float sa = 0.f, sb = 0.f;
    for (int d = 0; d < HD; ++d) {
        float w = Wg[(long)d * HD + k];
        sa += w * a_src[d];
        sb += w * a_dst[d];
    }
    va[k] = sa;
    vb[k] = sb;
}

// ---------------- GAT dots + softmax + node mix (writes bf16 hi/lo) ----------
__global__ void gat_mix_kernel(const float* __restrict__ nodes,
                               const float* __restrict__ va,
                               const float* __restrict__ vb,
                               const unsigned char* __restrict__ amask,
                               __nv_bfloat16* __restrict__ mhi,
                               __nv_bfloat16* __restrict__ mlo)
{
    int g = blockIdx.x;
    const float* base = nodes + (long)g * NNODE * HD;
    __shared__ float sdots[10];
    __shared__ float salpha[NNODE];

    int tid  = threadIdx.x;
    int warp = tid >> 5, lane = tid & 31;

    float partial = 0.f;
    if (warp < 9) {
        const float* row = base + warp * HD;
        for (int d = lane; d < HD; d += 32) partial += row[d] * vb[d];
    } else {
        for (int d = lane; d < HD; d += 32) partial += base[d] * va[d];
    }
#pragma unroll
    for (int off = 16; off; off >>= 1)
        partial += __shfl_down_sync(0xffffffffu, partial, off);
    if (lane == 0) sdots[warp] = partial;
    __syncthreads();

    if (tid == 0) {
        float es0 = sdots[9];
        float e[NNODE];
#pragma unroll
        for (int j = 0; j < NNODE; ++j) {
            bool valid;
            if (j == 0) valid = true;
            else {
                const unsigned char* mk = amask + ((long)g * NA + (j - 1)) * TA;
                valid = !(mk[0] && mk[1] && mk[2] && mk[3]);
            }
            if (valid) {
                float v = es0 + sdots[j];
                e[j] = v > 0.f ? v : 0.2f * v;
            } else e[j] = -1e9f;
        }
        float mx = e[0];
#pragma unroll
        for (int j = 1; j < NNODE; ++j) mx = fmaxf(mx, e[j]);
        float s = 0.f, ex[NNODE];
#pragma unroll
        for (int j = 0; j < NNODE; ++j) { ex[j] = expf(e[j] - mx); s += ex[j]; }
        float inv = 1.f / s;
#pragma unroll
        for (int j = 0; j < NNODE; ++j) salpha[j] = ex[j] * inv;
    }
    __syncthreads();

    for (int d4 = tid; d4 < HD / 4; d4 += blockDim.x) {
        float4 s4;
        float* ps = &s4.x;
#pragma unroll
        for (int q = 0; q < 4; ++q) {
            int d = d4 * 4 + q;
            float s = 0.f;
#pragma unroll
            for (int j = 0; j < NNODE; ++j) s += salpha[j] * base[j * HD + d];
            ps[q] = s;
        }
        u64 hq, lq;
        split4(s4, hq, lq);
        *(u64*)(mhi + (long)g * HD + 4 * d4) = hq;
        *(u64*)(mlo + (long)g * HD + 4 * d4) = lq;
    }
}

// ---------------- launch ------------------------------------------------------
extern "C" void kernel_launch(void* const* d_in, const int* in_sizes, int n_in,
                              void* d_out, int out_size)
{
    const int*   ent_tok  = (const int*)  d_in[0];
    const int*   ent_len  = (const int*)  d_in[1];
    const int*   at_tok   = (const int*)  d_in[3];
    const int*   at_len   = (const int*)  d_in[4];
    const unsigned char* at_mask = (const unsigned char*)d_in[5];
    const float* emb      = (const float*)d_in[6];
    const float* Wih_ent  = (const float*)d_in[7];
    const float* Whh_ent  = (const float*)d_in[8];
    const float* bih_ent  = (const float*)d_in[9];
    const float* bhh_ent  = (const float*)d_in[10];
    const float* Wih_attr = (const float*)d_in[11];
    const float* Whh_attr = (const float*)d_in[12];
    const float* bih_attr = (const float*)d_in[13];
    const float* bhh_attr = (const float*)d_in[14];
    const float* Wfc      = (const float*)d_in[15];
    const float* bfc      = (const float*)d_in[16];
    const float* Wg       = (const float*)d_in[17];
    const float* a_src    = (const float*)d_in[18];
    const float* a_dst    = (const float*)d_in[19];
    float* out = (float*)d_out;

    float *xp_ent, *xp_attr, *gh, *h_ent, *h_attr, *nodes, *va, *vb;
    int *cntE, *offE, *permE, *mcntE, *cntA, *offA, *permA, *mcntA;
    int *pcE, *gtokE, *orowE, *pcA, *gtokA, *orowA;
    __nv_bfloat16 *embH, *embL, *wiheH, *wiheL, *whheH, *whheL;
    __nv_bfloat16 *wihaH, *wihaL, *whhaH, *whhaL, *wfcH, *wfcL, *wgH, *wgL;
    __nv_bfloat16 *heH, *heL, *haH, *haL, *mixH, *mixL;

    cudaGetSymbolAddress((void**)&xp_ent,  g_xp_ent);
    cudaGetSymbolAddress((void**)&xp_attr, g_xp_attr);
    cudaGetSymbolAddress((void**)&gh,      g_gh);
    cudaGetSymbolAddress((void**)&h_ent,   g_h_ent);
    cudaGetSymbolAddress((void**)&h_attr,  g_h_attr);
    cudaGetSymbolAddress((void**)&nodes,   g_nodes);
    cudaGetSymbolAddress((void**)&va,      g_va);
    cudaGetSymbolAddress((void**)&vb,      g_vb);
    cudaGetSymbolAddress((void**)&cntE,  g_cnt_ent);
    cudaGetSymbolAddress((void**)&offE,  g_off_ent);
    cudaGetSymbolAddress((void**)&permE, g_perm_ent);
    cudaGetSymbolAddress((void**)&mcntE, g_mcnt_ent);
    cudaGetSymbolAddress((void**)&cntA,  g_cnt_attr);
    cudaGetSymbolAddress((void**)&offA,  g_off_attr);
    cudaGetSymbolAddress((void**)&permA, g_perm_attr);
    cudaGetSymbolAddress((void**)&mcntA, g_mcnt_attr);
    cudaGetSymbolAddress((void**)&pcE,   g_paircnt_ent);
    cudaGetSymbolAddress((void**)&gtokE, g_gtok_ent);
    cudaGetSymbolAddress((void**)&orowE, g_orow_ent);
    cudaGetSymbolAddress((void**)&pcA,   g_paircnt_attr);
    cudaGetSymbolAddress((void**)&gtokA, g_gtok_attr);
    cudaGetSymbolAddress((void**)&orowA, g_orow_attr);
    cudaGetSymbolAddress((void**)&embH,  g_emb_hi);
    cudaGetSymbolAddress((void**)&embL,  g_emb_lo);
    cudaGetSymbolAddress((void**)&wiheH, g_wihe_hi);
    cudaGetSymbolAddress((void**)&wiheL, g_wihe_lo);
    cudaGetSymbolAddress((void**)&whheH, g_whhe_hi);
    cudaGetSymbolAddress((void**)&whheL, g_whhe_lo);
    cudaGetSymbolAddress((void**)&wihaH, g_wiha_hi);
    cudaGetSymbolAddress((void**)&wihaL, g_wiha_lo);
    cudaGetSymbolAddress((void**)&whhaH, g_whha_hi);
    cudaGetSymbolAddress((void**)&whhaL, g_whha_lo);
    cudaGetSymbolAddress((void**)&wfcH,  g_wfc_hi);
    cudaGetSymbolAddress((void**)&wfcL,  g_wfc_lo);
    cudaGetSymbolAddress((void**)&wgH,   g_wg_hi);
    cudaGetSymbolAddress((void**)&wgL,   g_wg_lo);
    cudaGetSymbolAddress((void**)&heH,   g_he_hi);
    cudaGetSymbolAddress((void**)&heL,   g_he_lo);
    cudaGetSymbolAddress((void**)&haH,   g_ha_hi);
    cudaGetSymbolAddress((void**)&haL,   g_ha_lo);
    cudaGetSymbolAddress((void**)&mixH,  g_mix_hi);
    cudaGetSymbolAddress((void**)&mixL,  g_mix_lo);
    float* mixbuf = gh;
    (void)mixbuf;

    cudaFuncSetAttribute(tgemm, cudaFuncAttributeMaxDynamicSharedMemorySize, TG_SMEM);

    cudaMemsetAsync(h_ent,  0, (size_t)NG   * WD * sizeof(float));
    cudaMemsetAsync(h_attr, 0, (size_t)NATT * WD * sizeof(float));
    cudaMemsetAsync(heH, 0, (size_t)NG * WD * 2);
    cudaMemsetAsync(heL, 0, (size_t)NG * WD * 2);
    cudaMemsetAsync(haH, 0, (size_t)NATT * WD * 2);
    cudaMemsetAsync(haL, 0, (size_t)NATT * WD * 2);
    cudaMemsetAsync(cntE, 0, (TE + 1) * sizeof(int));
    cudaMemsetAsync(cntA, 0, (TA + 1) * sizeof(int));
    cudaMemsetAsync(pcE, 0, sizeof(int));
    cudaMemsetAsync(pcA, 0, sizeof(int));

    // operand splits (once per launch)
    split_kernel<<<(V * WD / 4 + 255) / 256, 256>>>(emb, embH, embL, V * WD / 4);
    split_kernel<<<(G3 * WD / 4 + 255) / 256, 256>>>(Wih_ent, wiheH, wiheL, G3 * WD / 4);
    split_kernel<<<(G3 * WD / 4 + 255) / 256, 256>>>(Whh_ent, whheH, whheL, G3 * WD / 4);
    split_kernel<<<(G3 * WD / 4 + 255) / 256, 256>>>(Wih_attr, wihaH, wihaL, G3 * WD / 4);
    split_kernel<<<(G3 * WD / 4 + 255) / 256, 256>>>(Whh_attr, whhaH, whhaL, G3 * WD / 4);
    split_kernel<<<(HD * WD / 4 + 255) / 256, 256>>>(Wfc, wfcH, wfcL, HD * WD / 4);
    split_kernel<<<(HD * HD / 4 + 255) / 256, 256>>>(Wg, wgH, wgL, HD * HD / 4);

    hist_kernel<<<(NG + 255) / 256, 256>>>(ent_len, NG, TE, cntE);
    offsets_kernel<<<1, 32>>>(cntE, offE, mcntE, TE);
    scatter_kernel<<<(NG + 255) / 256, 256>>>(ent_len, NG, TE, offE, permE);
    hist_kernel<<<(NATT + 255) / 256, 256>>>(at_len, NATT, TA, cntA);
    offsets_kernel<<<1, 32>>>(cntA, offA, mcntA, TA);
    scatter_kernel<<<(NATT + 255) / 256, 256>>>(at_len, NATT, TA, offA, permA);
    build_pairs<<<(NG * TE + 255) / 256, 256>>>(ent_tok, ent_len, NG, TE, pcE, gtokE, orowE);
    build_pairs<<<(NATT * TA + 255) / 256, 256>>>(at_tok, at_len, NATT, TA, pcA, gtokA, orowA);

    const int nt900  = (G3 + TN - 1) / TN;   // 8
    const int nt1024 = HD / TN;              // 8

    // xp = emb[tok] @ Wih^T + bih — valid (row,t) pairs only
    tgemm<<<dim3(NG * TE / TM, nt900), 256, TG_SMEM>>>(
        embH, embL, gtokE, wiheH, wiheL, bih_ent, xp_ent,
        NG * TE, G3, WD, 0, 0, pcE, orowE);
    tgemm<<<dim3(NATT * TA / TM, nt900), 256, TG_SMEM>>>(
        embH, embL, gtokA, wihaH, wihaL, bih_attr, xp_attr,
        NATT * TA, G3, WD, 0, 0, pcA, orowA);

    wgt_vec_kernel<<<(HD + 255) / 256, 256>>>(Wg, a_src, a_dst, va, vb);

    // entity GRU
    for (int t = 0; t < TE; ++t) {
        tgemm<<<dim3(NG / TM, nt900), 256, TG_SMEM>>>(
            heH, heL, permE, whheH, whheL, bhh_ent, gh,
            NG, G3, WD, 0, 0, mcntE + t, nullptr);
        gru_gate4<<<(NG * 75 + 255) / 256, 256>>>(
            xp_ent, gh, h_ent, heH, heL, permE, mcntE + t, t, TE);
    }

    // attribute GRU
    for (int t = 0; t < TA; ++t) {
        tgemm<<<dim3(NATT / TM, nt900), 256, TG_SMEM>>>(
            haH, haL, permA, whhaH, whhaL, bhh_attr, gh,
            NATT, G3, WD, 0, 0, mcntA + t, nullptr);
        gru_gate4<<<(NATT * 75 + 255) / 256, 256>>>(
            xp_attr, gh, h_attr, haH, haL, permA, mcntA + t, t, TA);
    }

    // FC + ReLU -> node layout [G, 9, HD]
    tgemm<<<dim3(NG / TM,   nt1024), 256, TG_SMEM>>>(
        heH, heL, nullptr, wfcH, wfcL, bfc, nodes,
        NG, HD, WD, 1, 1, nullptr, nullptr);
    tgemm<<<dim3(NATT / TM, nt1024), 256, TG_SMEM>>>(
        haH, haL, nullptr, wfcH, wfcL, bfc, nodes,
        NATT, HD, WD, 1, 2, nullptr, nullptr);

    // GAT: dots + alpha + mix (bf16 hi/lo out)
    gat_mix_kernel<<<NG, 320>>>(nodes, va, vb, at_mask, mixH, mixL);

    // out = elu(mix @ Wg^T)
    tgemm<<<dim3(NG / TM, nt1024), 256, TG_SMEM>>>(
        mixH, mixL, nullptr, wgH, wgL, nullptr, out,
        NG, HD, HD, 2, 0, nullptr, nullptr);
}

// round 8
// speedup vs baseline: 2.9936x; 1.2471x over previous
#include <cuda_runtime.h>
#include <cuda_bf16.h>
#include <math.h>

// Problem constants
#define BS   128
#define NE   32
#define NA   8
#define TE   8
#define TA   4
#define WD   300
#define HD   1024
#define G3   900          // 3*WD
#define NG   (BS*NE)      // 4096
#define NATT (NG*NA)      // 32768
#define NNODE 9
#define V    30522
#define KP3  304          // WD padded to multiple of 8

typedef unsigned long long u64;
typedef unsigned int u32;

// ---------------- scratch ----------------------------------------------------
__device__ float g_xp_ent [NG   * TE * G3];
__device__ float g_xp_attr[NATT * TA * G3];
__device__ float g_gh     [NATT * G3];
__device__ float g_h_ent  [NG   * WD];
__device__ float g_h_attr [NATT * WD];
__device__ float g_nodes  [NG * NNODE * HD];
__device__ float g_va     [HD];
__device__ float g_vb     [HD];
// bf16 hi/lo operand buffers (K-padded strides)
__device__ __nv_bfloat16 g_emb_hi[V * KP3];
__device__ __nv_bfloat16 g_emb_lo[V * KP3];
__device__ __nv_bfloat16 g_wihe_hi[G3 * KP3];
__device__ __nv_bfloat16 g_wihe_lo[G3 * KP3];
__device__ __nv_bfloat16 g_whhe_hi[G3 * KP3];
__device__ __nv_bfloat16 g_whhe_lo[G3 * KP3];
__device__ __nv_bfloat16 g_wiha_hi[G3 * KP3];
__device__ __nv_bfloat16 g_wiha_lo[G3 * KP3];
__device__ __nv_bfloat16 g_whha_hi[G3 * KP3];
__device__ __nv_bfloat16 g_whha_lo[G3 * KP3];
__device__ __nv_bfloat16 g_wfc_hi[HD * KP3];
__device__ __nv_bfloat16 g_wfc_lo[HD * KP3];
__device__ __nv_bfloat16 g_wg_hi[HD * HD];
__device__ __nv_bfloat16 g_wg_lo[HD * HD];
__device__ __nv_bfloat16 g_he_hi[NG * KP3];
__device__ __nv_bfloat16 g_he_lo[NG * KP3];
__device__ __nv_bfloat16 g_ha_hi[NATT * KP3];
__device__ __nv_bfloat16 g_ha_lo[NATT * KP3];
__device__ __nv_bfloat16 g_mix_hi[NG * HD];
__device__ __nv_bfloat16 g_mix_lo[NG * HD];
// length-sort scratch
__device__ int g_cnt_ent [TE + 1];
__device__ int g_off_ent [TE + 1];
__device__ int g_perm_ent[NG];
__device__ int g_mcnt_ent[TE];
__device__ int g_cnt_attr [TA + 1];
__device__ int g_off_attr [TA + 1];
__device__ int g_perm_attr[NATT];
__device__ int g_mcnt_attr[TA];
// xp pair-compaction scratch
__device__ int g_paircnt_ent;
__device__ int g_gtok_ent[NG * TE];
__device__ int g_orow_ent[NG * TE];
__device__ int g_paircnt_attr;
__device__ int g_gtok_attr[NATT * TA];
__device__ int g_orow_attr[NATT * TA];

// ---------------- helpers ------------------------------------------------------
__device__ __forceinline__ u32 smem_u32(const void* p) {
    u32 a;
    asm("{ .reg .u64 t; cvta.to.shared.u64 t, %1; cvt.u32.u64 %0, t; }"
        : "=r"(a) : "l"(p));
    return a;
}

#define LDSM_X4(r, addr) \
    asm volatile("ldmatrix.sync.aligned.m8n8.x4.shared.b16 {%0,%1,%2,%3}, [%4];" \
        : "=r"((r)[0]), "=r"((r)[1]), "=r"((r)[2]), "=r"((r)[3]) : "r"(addr))

#define LDSM_X2(r0, r1, addr) \
    asm volatile("ldmatrix.sync.aligned.m8n8.x2.shared.b16 {%0,%1}, [%2];" \
        : "=r"(r0), "=r"(r1) : "r"(addr))

#define MMA16816(c, a, b0, b1) \
    asm volatile("mma.sync.aligned.m16n8k16.row.col.f32.bf16.bf16.f32 " \
        "{%0,%1,%2,%3}, {%4,%5,%6,%7}, {%8,%9}, {%0,%1,%2,%3};" \
        : "+f"((c)[0]), "+f"((c)[1]), "+f"((c)[2]), "+f"((c)[3]) \
        : "r"((a)[0]), "r"((a)[1]), "r"((a)[2]), "r"((a)[3]), "r"(b0), "r"(b1))

#define CP16(dst, src, sz) \
    asm volatile("cp.async.cg.shared.global [%0], [%1], 16, %2;" \
        :: "r"(dst), "l"(src), "r"(sz) : "memory")
#define CPCOMMIT() asm volatile("cp.async.commit_group;" ::: "memory")
#define CPWAIT1()  asm volatile("cp.async.wait_group 1;"  ::: "memory")
#define CPWAIT0()  asm volatile("cp.async.wait_group 0;"  ::: "memory")

#define SWZ(o) ((o) ^ (((o) >> 3) & 0x70u))

__device__ __forceinline__ void split4(float4 v, u64& hq, u64& lq) {
    unsigned short h[4], l[4];
    const float* pv = &v.x;
#pragma unroll
    for (int i = 0; i < 4; ++i) {
        __nv_bfloat16 hb = __float2bfloat16(pv[i]);
        __nv_bfloat16 lb = __float2bfloat16(pv[i] - __bfloat162float(hb));
        h[i] = __bfloat16_as_ushort(hb);
        l[i] = __bfloat16_as_ushort(lb);
    }
    hq = (u64)h[0] | ((u64)h[1] << 16) | ((u64)h[2] << 32) | ((u64)h[3] << 48);
    lq = (u64)l[0] | ((u64)l[1] << 16) | ((u64)l[2] << 32) | ((u64)l[3] << 48);
}

// ---------------- fp32 -> bf16 hi/lo split (row-based, padded dst) ------------
__global__ void split_rows(const float* __restrict__ x,
                           __nv_bfloat16* __restrict__ hi,
                           __nv_bfloat16* __restrict__ lo,
                           int rows, int K, int KP)
{
    int q = KP / 4;
    int idx = blockIdx.x * blockDim.x + threadIdx.x;
    int r = idx / q;
    if (r >= rows) return;
    int i4 = (idx - r * q) * 4;
    float4 v = make_float4(0.f, 0.f, 0.f, 0.f);
    if (i4 + 4 <= K) v = *(const float4*)(x + (long)r * K + i4);
    u64 hq, lq;
    split4(v, hq, lq);
    *(u64*)(hi + (long)r * KP + i4) = hq;
    *(u64*)(lo + (long)r * KP + i4) = lq;
}

// ---------------- tensor GEMM (bf16 hi/lo operands, cp.async pipeline) -------
// 128x128 tile, CK=64, 2-stage smem pipeline, 3-pass hi/lo compensation.
#define TM 128
#define TN 128
#define CK 64
#define OFF_AHI 0u
#define OFF_ALO 16384u
#define OFF_BHI 32768u
#define OFF_BLO 49152u
#define STAGE   65536u
#define TG_SMEM 131072u

__global__ void __launch_bounds__(256)
tgemm(const __nv_bfloat16* __restrict__ Ahi, const __nv_bfloat16* __restrict__ Alo,
      const int* __restrict__ gather,
      const __nv_bfloat16* __restrict__ Bhi, const __nv_bfloat16* __restrict__ Blo,
      const float* __restrict__ bias,
      float* __restrict__ C, int M, int N, int K, int KP, int act, int outMap,
      const int* __restrict__ mlimit, const int* __restrict__ orow)
{
    extern __shared__ char smem[];
    int Mdyn = M;
    if (mlimit) { Mdyn = *mlimit; if (Mdyn > M) Mdyn = M; }
    const int m0 = blockIdx.x * TM;
    const int n0 = blockIdx.y * TN;
    if (m0 >= Mdyn) return;

    const u32 sbase = smem_u32(smem);
    const int tid  = threadIdx.x;
    const int wid  = tid >> 5;
    const int lane = tid & 31;
    const int wm   = wid >> 1;
    const int wn   = wid & 1;

    // fill-geometry: each thread owns 4 rows (r = tid>>3 + 32*it), one 16B k-granule
    const int k8   = (tid & 7) * 8;
    const int rloc = tid >> 3;
    long roA[4], roB[4];
    bool vA[4], vB[4];
    u32  swR[4];
#pragma unroll
    for (int it = 0; it < 4; ++it) {
        int r = rloc + 32 * it;
        int m = m0 + r;
        vA[it] = (m < Mdyn);
        int src = vA[it] ? (gather ? gather[m] : m) : 0;
        roA[it] = (long)src * KP;
        int n = n0 + r;
        vB[it] = (n < N);
        roB[it] = (long)(vB[it] ? n : 0) * KP;
        swR[it] = SWZ((u32)(r * 128 + k8 * 2));
    }

#define FILL_CHUNK(cc, st) do { \
    int gk_ = (cc) * CK + k8; \
    u32 sb_ = sbase + (u32)(st) * STAGE; \
    bool kok_ = (gk_ < KP); \
    _Pragma("unroll") \
    for (int it = 0; it < 4; ++it) { \
        bool aok = vA[it] && kok_; u32 asz = aok ? 16u : 0u; \
        const __nv_bfloat16* pa1 = aok ? (Ahi + roA[it] + gk_) : Ahi; \
        const __nv_bfloat16* pa2 = aok ? (Alo + roA[it] + gk_) : Alo; \
        CP16(sb_ + OFF_AHI + swR[it], pa1, asz); \
        CP16(sb_ + OFF_ALO + swR[it], pa2, asz); \
        bool bok = vB[it] && kok_; u32 bsz = bok ? 16u : 0u; \
        const __nv_bfloat16* pb1 = bok ? (Bhi + roB[it] + gk_) : Bhi; \
        const __nv_bfloat16* pb2 = bok ? (Blo + roB[it] + gk_) : Blo; \
        CP16(sb_ + OFF_BHI + swR[it], pb1, bsz); \
        CP16(sb_ + OFF_BLO + swR[it], pb2, bsz); \
    } \
    CPCOMMIT(); \
} while (0)

    // mma-geometry
    const u32 rbA0 = (u32)((wm * 32 + (lane & 15)) * 128);
    const u32 rbA1 = rbA0 + 16u * 128u;
    const u32 rbB  = (u32)((wn * 64 + (lane & 7)) * 128);
    const u32 xorq = (u32)(lane & 7);
    const u32 qAh  = (u32)(lane >> 4);
    const u32 qBh  = (u32)((lane >> 3) & 1);

    float acc[2][8][4];
#pragma unroll
    for (int i = 0; i < 2; ++i)
#pragma unroll
        for (int j = 0; j < 8; ++j)
#pragma unroll
            for (int q = 0; q < 4; ++q) acc[i][j][q] = 0.f;

    const int nc = (K + CK - 1) / CK;

    FILL_CHUNK(0, 0);
    for (int c = 0; c < nc; ++c) {
        if (c + 1 < nc) { FILL_CHUNK(c + 1, (c + 1) & 1); CPWAIT1(); }
        else            { CPWAIT0(); }
        __syncthreads();

        const u32 stb = sbase + (u32)(c & 1) * STAGE;
        const u32 aoffs[3] = { OFF_AHI, OFF_ALO, OFF_AHI };
        const u32 boffs[3] = { OFF_BHI, OFF_BHI, OFF_BLO };
#pragma unroll
        for (int ps = 0; ps < 3; ++ps) {
            const u32 ab = stb + aoffs[ps];
            const u32 bb = stb + boffs[ps];
#pragma unroll
            for (int ks = 0; ks < 4; ++ks) {
                u32 qa = (((u32)(2 * ks) + qAh) ^ xorq) * 16u;
                u32 a0[4], a1[4];
                LDSM_X4(a0, ab + rbA0 + qa);
                LDSM_X4(a1, ab + rbA1 + qa);
                u32 qb = (((u32)(2 * ks) + qBh) ^ xorq) * 16u;
#pragma unroll
                for (int nb = 0; nb < 8; ++nb) {
                    u32 b0, b1;
                    LDSM_X2(b0, b1, bb + rbB + (u32)nb * 1024u + qb);
                    MMA16816(acc[0][nb], a0, b0, b1);
                    MMA16816(acc[1][nb], a1, b0, b1);
                }
            }
        }
        __syncthreads();
    }
#undef FILL_CHUNK

    // epilogue
#pragma unroll
    for (int mi = 0; mi < 2; ++mi) {
#pragma unroll
        for (int half = 0; half < 2; ++half) {
            int m = m0 + wm * 32 + mi * 16 + (lane >> 2) + half * 8;
            if (m >= Mdyn) continue;
            long base;
            if (orow)             base = (long)orow[m] * N;
            else if (outMap == 0) base = (long)m * N;
            else if (outMap == 1) base = (long)m * NNODE * HD;
            else                  base = ((long)(m >> 3) * NNODE + 1 + (m & 7)) * (long)HD;
#pragma unroll
            for (int nb = 0; nb < 8; ++nb) {
                int n = n0 + wn * 64 + nb * 8 + (lane & 3) * 2;
                if (n >= N) continue;
                float x0 = acc[mi][nb][half * 2 + 0];
                float x1 = acc[mi][nb][half * 2 + 1];
                if (bias) { x0 += bias[n]; x1 += bias[n + 1]; }
                if (act == 1)      { x0 = fmaxf(x0, 0.f); x1 = fmaxf(x1, 0.f); }
                else if (act == 2) { x0 = x0 > 0.f ? x0 : expm1f(x0);
                                     x1 = x1 > 0.f ? x1 : expm1f(x1); }
                *(float2*)(C + base + n) = make_float2(x0, x1);
            }
        }
    }
}

// ---------------- counting sort by length (descending) -----------------------
__global__ void hist_kernel(const int* __restrict__ len, int n, int T,
                            int* __restrict__ cnt)
{
    int i = blockIdx.x * blockDim.x + threadIdx.x;
    if (i >= n) return;
    int L = len[i]; L = L < 1 ? 1 : (L > T ? T : L);
    atomicAdd(&cnt[L], 1);
}
__global__ void offsets_kernel(const int* __restrict__ cnt,
                               int* __restrict__ off, int* __restrict__ mcnt, int T)
{
    if (threadIdx.x != 0 || blockIdx.x != 0) return;
    int run = 0;
    for (int L = T; L >= 1; --L) { off[L] = run; run += cnt[L]; }
    for (int t = 0; t < T; ++t) {
        int s = 0;
        for (int L = t + 1; L <= T; ++L) s += cnt[L];
        mcnt[t] = s;
    }
}
__global__ void scatter_kernel(const int* __restrict__ len, int n, int T,
                               int* __restrict__ off, int* __restrict__ perm)
{
    int i = blockIdx.x * blockDim.x + threadIdx.x;
    if (i >= n) return;
    int L = len[i]; L = L < 1 ? 1 : (L > T ? T : L);
    int pos = atomicAdd(&off[L], 1);
    perm[pos] = i;
}

// ---------------- xp pair compaction ------------------------------------------
__global__ void build_pairs(const int* __restrict__ tok,
                            const int* __restrict__ len, int n, int T,
                            int* __restrict__ cnt,
                            int* __restrict__ gtok, int* __restrict__ orow)
{
    int p = blockIdx.x * blockDim.x + threadIdx.x;
    if (p >= n * T) return;
    int i = p / T, t = p - i * T;
    int L = len[i]; L = L < 1 ? 1 : (L > T ? T : L);
    if (t >= L) return;
    int pos = atomicAdd(cnt, 1);
    gtok[pos] = tok[p];
    orow[pos] = p;
}

// ---------------- GRU gate update (compact rows; fp32 + padded bf16 hi/lo) ---
__global__ void gru_gate4(const float* __restrict__ xp,
                          const float* __restrict__ gh,
                          float* __restrict__ h,
                          __nv_bfloat16* __restrict__ hhi,
                          __nv_bfloat16* __restrict__ hlo,
                          const int* __restrict__ perm,
                          const int* __restrict__ mcnt,
                          int t, int T)
{
    const int Q = WD / 4;   // 75
    int idx = blockIdx.x * blockDim.x + threadIdx.x;
    int i = idx / Q;
    if (i >= *mcnt) return;
    int d = idx - i * Q;
    int orig = perm[i];
    const float4* x = (const float4*)(xp + ((long)orig * T + t) * G3);
    const float4* g = (const float4*)(gh + (long)i * G3);
    float4* hp = (float4*)(h + (long)orig * WD);

    float4 xr = x[d], xz = x[Q + d], xn = x[2 * Q + d];
    float4 gr = g[d], gz = g[Q + d], gn = g[2 * Q + d];
    float4 hv = hp[d];

    float4 res;
    const float* pxr = &xr.x; const float* pxz = &xz.x; const float* pxn = &xn.x;
    const float* pgr = &gr.x; const float* pgz = &gz.x; const float* pgn = &gn.x;
    const float* phv = &hv.x; float* pres = &res.x;
#pragma unroll
    for (int c = 0; c < 4; ++c) {
        float r = 1.f / (1.f + expf(-(pxr[c] + pgr[c])));
        float z = 1.f / (1.f + expf(-(pxz[c] + pgz[c])));
        float n = tanhf(pxn[c] + r * pgn[c]);
        pres[c] = (1.f - z) * n + z * phv[c];
    }
    hp[d] = res;
    u64 hq, lq;
    split4(res, hq, lq);
    *(u64*)(hhi + (long)orig * KP3 + 4 * d) = hq;
    *(u64*)(hlo + (long)orig * KP3 + 4 * d) = lq;
}

// ---------------- va/vb = Wg^T a_src / Wg^T a_dst ----------------------------
__global__ void wgt_vec_kernel(const float* __restrict__ Wg,
                               const float* __restrict__ a_src,
                               const float* __restrict__ a_dst,
                               float* __restrict__ va, float* __restrict__ vb)
{
    int k = blockIdx.x * blockDim.x + threadIdx.x;
    if (k >= HD) return;
    float sa = 0.f, sb = 0.f;
    for (int d = 0; d < HD; ++d) {
        float w = Wg[(long)d * HD + k];
        sa += w * a_src[d];
        sb += w * a_dst[d];
    }
    va[k] = sa;
    vb[k] = sb;
}

// ---------------- GAT dots + softmax + node mix (writes bf16 hi/lo) ----------
__global__ void gat_mix_kernel(const float* __restrict__ nodes,
                               const float* __restrict__ va,
                               const float* __restrict__ vb,
                               const unsigned char* __restrict__ amask,
                               __nv_bfloat16* __restrict__ mhi,
                               __nv_bfloat16* __restrict__ mlo)
{
    int g = blockIdx.x;
    const float* base = nodes + (long)g * NNODE * HD;
    __shared__ float sdots[10];
    __shared__ float salpha[NNODE];

    int tid  = threadIdx.x;
    int warp = tid >> 5, lane = tid & 31;

    float partial = 0.f;
    if (warp < 9) {
        const float* row = base + warp * HD;
        for (int d = lane; d < HD; d += 32) partial += row[d] * vb[d];
    } else {
        for (int d = lane; d < HD; d += 32) partial += base[d] * va[d];
    }
#pragma unroll
    for (int off = 16; off; off >>= 1)
        partial += __shfl_down_sync(0xffffffffu, partial, off);
    if (lane == 0) sdots[warp] = partial;
    __syncthreads();

    if (tid == 0) {
        float es0 = sdots[9];
        float e[NNODE];
#pragma unroll
        for (int j = 0; j < NNODE; ++j) {
            bool valid;
            if (j == 0) valid = true;
            else {
                const unsigned char* mk = amask + ((long)g * NA + (j - 1)) * TA;
                valid = !(mk[0] && mk[1] && mk[2] && mk[3]);
            }
            if (valid) {
                float v = es0 + sdots[j];
                e[j] = v > 0.f ? v : 0.2f * v;
            } else e[j] = -1e9f;
        }
        float mx = e[0];
#pragma unroll
        for (int j = 1; j < NNODE; ++j) mx = fmaxf(mx, e[j]);
        float s = 0.f, ex[NNODE];
#pragma unroll
        for (int j = 0; j < NNODE; ++j) { ex[j] = expf(e[j] - mx); s += ex[j]; }
        float inv = 1.f / s;
#pragma unroll
        for (int j = 0; j < NNODE; ++j) salpha[j] = ex[j] * inv;
    }
    __syncthreads();

    for (int d4 = tid; d4 < HD / 4; d4 += blockDim.x) {
        float4 s4;
        float* ps = &s4.x;
#pragma unroll
        for (int q = 0; q < 4; ++q) {
            int d = d4 * 4 + q;
            float s = 0.f;
#pragma unroll
            for (int j = 0; j < NNODE; ++j) s += salpha[j] * base[j * HD + d];
            ps[q] = s;
        }
        u64 hq, lq;
        split4(s4, hq, lq);
        *(u64*)(mhi + (long)g * HD + 4 * d4) = hq;
        *(u64*)(mlo + (long)g * HD + 4 * d4) = lq;
    }
}

// ---------------- launch ------------------------------------------------------
extern "C" void kernel_launch(void* const* d_in, const int* in_sizes, int n_in,
                              void* d_out, int out_size)
{
    const int*   ent_tok  = (const int*)  d_in[0];
    const int*   ent_len  = (const int*)  d_in[1];
    const int*   at_tok   = (const int*)  d_in[3];
    const int*   at_len   = (const int*)  d_in[4];
    const unsigned char* at_mask = (const unsigned char*)d_in[5];
    const float* emb      = (const float*)d_in[6];
    const float* Wih_ent  = (const float*)d_in[7];
    const float* Whh_ent  = (const float*)d_in[8];
    const float* bih_ent  = (const float*)d_in[9];
    const float* bhh_ent  = (const float*)d_in[10];
    const float* Wih_attr = (const float*)d_in[11];
    const float* Whh_attr = (const float*)d_in[12];
    const float* bih_attr = (const float*)d_in[13];
    const float* bhh_attr = (const float*)d_in[14];
    const float* Wfc      = (const float*)d_in[15];
    const float* bfc      = (const float*)d_in[16];
    const float* Wg       = (const float*)d_in[17];
    const float* a_src    = (const float*)d_in[18];
    const float* a_dst    = (const float*)d_in[19];
    float* out = (float*)d_out;

    float *xp_ent, *xp_attr, *gh, *h_ent, *h_attr, *nodes, *va, *vb;
    int *cntE, *offE, *permE, *mcntE, *cntA, *offA, *permA, *mcntA;
    int *pcE, *gtokE, *orowE, *pcA, *gtokA, *orowA;
    __nv_bfloat16 *embH, *embL, *wiheH, *wiheL, *whheH, *whheL;
    __nv_bfloat16 *wihaH, *wihaL, *whhaH, *whhaL, *wfcH, *wfcL, *wgH, *wgL;
    __nv_bfloat16 *heH, *heL, *haH, *haL, *mixH, *mixL;

    cudaGetSymbolAddress((void**)&xp_ent,  g_xp_ent);
    cudaGetSymbolAddress((void**)&xp_attr, g_xp_attr);
    cudaGetSymbolAddress((void**)&gh,      g_gh);
    cudaGetSymbolAddress((void**)&h_ent,   g_h_ent);
    cudaGetSymbolAddress((void**)&h_attr,  g_h_attr);
    cudaGetSymbolAddress((void**)&nodes,   g_nodes);
    cudaGetSymbolAddress((void**)&va,      g_va);
    cudaGetSymbolAddress((void**)&vb,      g_vb);
    cudaGetSymbolAddress((void**)&cntE,  g_cnt_ent);
    cudaGetSymbolAddress((void**)&offE,  g_off_ent);
    cudaGetSymbolAddress((void**)&permE, g_perm_ent);
    cudaGetSymbolAddress((void**)&mcntE, g_mcnt_ent);
    cudaGetSymbolAddress((void**)&cntA,  g_cnt_attr);
    cudaGetSymbolAddress((void**)&offA,  g_off_attr);
    cudaGetSymbolAddress((void**)&permA, g_perm_attr);
    cudaGetSymbolAddress((void**)&mcntA, g_mcnt_attr);
    cudaGetSymbolAddress((void**)&pcE,   g_paircnt_ent);
    cudaGetSymbolAddress((void**)&gtokE, g_gtok_ent);
    cudaGetSymbolAddress((void**)&orowE, g_orow_ent);
    cudaGetSymbolAddress((void**)&pcA,   g_paircnt_attr);
    cudaGetSymbolAddress((void**)&gtokA, g_gtok_attr);
    cudaGetSymbolAddress((void**)&orowA, g_orow_attr);
    cudaGetSymbolAddress((void**)&embH,  g_emb_hi);
    cudaGetSymbolAddress((void**)&embL,  g_emb_lo);
    cudaGetSymbolAddress((void**)&wiheH, g_wihe_hi);
    cudaGetSymbolAddress((void**)&wiheL, g_wihe_lo);
    cudaGetSymbolAddress((void**)&whheH, g_whhe_hi);
    cudaGetSymbolAddress((void**)&whheL, g_whhe_lo);
    cudaGetSymbolAddress((void**)&wihaH, g_wiha_hi);
    cudaGetSymbolAddress((void**)&wihaL, g_wiha_lo);
    cudaGetSymbolAddress((void**)&whhaH, g_whha_hi);
    cudaGetSymbolAddress((void**)&whhaL, g_whha_lo);
    cudaGetSymbolAddress((void**)&wfcH,  g_wfc_hi);
    cudaGetSymbolAddress((void**)&wfcL,  g_wfc_lo);
    cudaGetSymbolAddress((void**)&wgH,   g_wg_hi);
    cudaGetSymbolAddress((void**)&wgL,   g_wg_lo);
    cudaGetSymbolAddress((void**)&heH,   g_he_hi);
    cudaGetSymbolAddress((void**)&heL,   g_he_lo);
    cudaGetSymbolAddress((void**)&haH,   g_ha_hi);
    cudaGetSymbolAddress((void**)&haL,   g_ha_lo);
    cudaGetSymbolAddress((void**)&mixH,  g_mix_hi);
    cudaGetSymbolAddress((void**)&mixL,  g_mix_lo);

    cudaFuncSetAttribute(tgemm, cudaFuncAttributeMaxDynamicSharedMemorySize, TG_SMEM);

    cudaMemsetAsync(h_ent,  0, (size_t)NG   * WD * sizeof(float));
    cudaMemsetAsync(h_attr, 0, (size_t)NATT * WD * sizeof(float));
    cudaMemsetAsync(heH, 0, (size_t)NG * KP3 * 2);
    cudaMemsetAsync(heL, 0, (size_t)NG * KP3 * 2);
    cudaMemsetAsync(haH, 0, (size_t)NATT * KP3 * 2);
    cudaMemsetAsync(haL, 0, (size_t)NATT * KP3 * 2);
    cudaMemsetAsync(cntE, 0, (TE + 1) * sizeof(int));
    cudaMemsetAsync(cntA, 0, (TA + 1) * sizeof(int));
    cudaMemsetAsync(pcE, 0, sizeof(int));
    cudaMemsetAsync(pcA, 0, sizeof(int));

    // operand splits (once per launch; padded K stride)
    const int q3 = KP3 / 4;
    split_rows<<<(V * q3 + 255) / 256, 256>>>(emb, embH, embL, V, WD, KP3);
    split_rows<<<(G3 * q3 + 255) / 256, 256>>>(Wih_ent, wiheH, wiheL, G3, WD, KP3);
    split_rows<<<(G3 * q3 + 255) / 256, 256>>>(Whh_ent, whheH, whheL, G3, WD, KP3);
    split_rows<<<(G3 * q3 + 255) / 256, 256>>>(Wih_attr, wihaH, wihaL, G3, WD, KP3);
    split_rows<<<(G3 * q3 + 255) / 256, 256>>>(Whh_attr, whhaH, whhaL, G3, WD, KP3);
    split_rows<<<(HD * q3 + 255) / 256, 256>>>(Wfc, wfcH, wfcL, HD, WD, KP3);
    split_rows<<<(HD * (HD / 4) + 255) / 256, 256>>>(Wg, wgH, wgL, HD, HD, HD);

    hist_kernel<<<(NG + 255) / 256, 256>>>(ent_len, NG, TE, cntE);
    offsets_kernel<<<1, 32>>>(cntE, offE, mcntE, TE);
    scatter_kernel<<<(NG + 255) / 256, 256>>>(ent_len, NG, TE, offE, permE);
    hist_kernel<<<(NATT + 255) / 256, 256>>>(at_len, NATT, TA, cntA);
    offsets_kernel<<<1, 32>>>(cntA, offA, mcntA, TA);
    scatter_kernel<<<(NATT + 255) / 256, 256>>>(at_len, NATT, TA, offA, permA);
    build_pairs<<<(NG * TE + 255) / 256, 256>>>(ent_tok, ent_len, NG, TE, pcE, gtokE, orowE);
    build_pairs<<<(NATT * TA + 255) / 256, 256>>>(at_tok, at_len, NATT, TA, pcA, gtokA, orowA);

    const int nt900  = (G3 + TN - 1) / TN;   // 8
    const int nt1024 = HD / TN;              // 8

    // xp = emb[tok] @ Wih^T + bih — valid (row,t) pairs only
    tgemm<<<dim3(NG * TE / TM, nt900), 256, TG_SMEM>>>(
        embH, embL, gtokE, wiheH, wiheL, bih_ent, xp_ent,
        NG * TE, G3, WD, KP3, 0, 0, pcE, orowE);
    tgemm<<<dim3(NATT * TA / TM, nt900), 256, TG_SMEM>>>(
        embH, embL, gtokA, wihaH, wihaL, bih_attr, xp_attr,
        NATT * TA, G3, WD, KP3, 0, 0, pcA, orowA);

    wgt_vec_kernel<<<(HD + 255) / 256, 256>>>(Wg, a_src, a_dst, va, vb);

    // entity GRU
    for (int t = 0; t < TE; ++t) {
        tgemm<<<dim3(NG / TM, nt900), 256, TG_SMEM>>>(
            heH, heL, permE, whheH, whheL, bhh_ent, gh,
            NG, G3, WD, KP3, 0, 0, mcntE + t, nullptr);
        gru_gate4<<<(NG * 75 + 255) / 256, 256>>>(
            xp_ent, gh, h_ent, heH, heL, permE, mcntE + t, t, TE);
    }

    // attribute GRU
    for (int t = 0; t < TA; ++t) {
        tgemm<<<dim3(NATT / TM, nt900), 256, TG_SMEM>>>(
            haH, haL, permA, whhaH, whhaL, bhh_attr, gh,
            NATT, G3, WD, KP3, 0, 0, mcntA + t, nullptr);
        gru_gate4<<<(NATT * 75 + 255) / 256, 256>>>(
            xp_attr, gh, h_attr, haH, haL, permA, mcntA + t, t, TA);
    }

    // FC + ReLU -> node layout [G, 9, HD]
    tgemm<<<dim3(NG / TM,   nt1024), 256, TG_SMEM>>>(
        heH, heL, nullptr, wfcH, wfcL, bfc, nodes,
        NG, HD, WD, KP3, 1, 1, nullptr, nullptr);
    tgemm<<<dim3(NATT / TM, nt1024), 256, TG_SMEM>>>(
        haH, haL, nullptr, wfcH, wfcL, bfc, nodes,
        NATT, HD, WD, KP3, 1, 2, nullptr, nullptr);

    // GAT: dots + alpha + mix (bf16 hi/lo out)
    gat_mix_kernel<<<NG, 320>>>(nodes, va, vb, at_mask, mixH, mixL);

    // out = elu(mix @ Wg^T)
    tgemm<<<dim3(NG / TM, nt1024), 256, TG_SMEM>>>(
        mixH, mixL, nullptr, wgH, wgL, nullptr, out,
        NG, HD, HD, HD, 2, 0, nullptr, nullptr);
}

// round 9
// speedup vs baseline: 3.7094x; 1.2391x over previous
#include <cuda_runtime.h>
#include <cuda_bf16.h>
#include <math.h>

// Problem constants
#define BS   128
#define NE   32
#define NA   8
#define TE   8
#define TA   4
#define WD   300
#define HD   1024
#define G3   900          // 3*WD
#define NG   (BS*NE)      // 4096
#define NATT (NG*NA)      // 32768
#define NNODE 9
#define V    30522
#define KP3  304          // WD padded to multiple of 8

typedef unsigned long long u64;
typedef unsigned int u32;

// ---------------- scratch ----------------------------------------------------
__device__ float g_xp_ent [NG   * TE * G3];
__device__ float g_xp_attr[NATT * TA * G3];
__device__ float g_gh_ent [NG   * G3];
__device__ float g_gh_attr[NATT * G3];
__device__ float g_h_ent  [NG   * WD];
__device__ float g_h_attr [NATT * WD];
__device__ float g_nodes  [NG * NNODE * HD];
__device__ float g_va     [HD];
__device__ float g_vb     [HD];
// bf16 hi/lo operand buffers (K-padded strides; zero-init covers pads)
__device__ __nv_bfloat16 g_emb_hi[V * KP3];
__device__ __nv_bfloat16 g_emb_lo[V * KP3];
__device__ __nv_bfloat16 g_wihe_hi[G3 * KP3];
__device__ __nv_bfloat16 g_wihe_lo[G3 * KP3];
__device__ __nv_bfloat16 g_whhe_hi[G3 * KP3];
__device__ __nv_bfloat16 g_whhe_lo[G3 * KP3];
__device__ __nv_bfloat16 g_wiha_hi[G3 * KP3];
__device__ __nv_bfloat16 g_wiha_lo[G3 * KP3];
__device__ __nv_bfloat16 g_whha_hi[G3 * KP3];
__device__ __nv_bfloat16 g_whha_lo[G3 * KP3];
__device__ __nv_bfloat16 g_wfc_hi[HD * KP3];
__device__ __nv_bfloat16 g_wfc_lo[HD * KP3];
__device__ __nv_bfloat16 g_wg_hi[HD * HD];
__device__ __nv_bfloat16 g_wg_lo[HD * HD];
__device__ __nv_bfloat16 g_he_hi[NG * KP3];
__device__ __nv_bfloat16 g_he_lo[NG * KP3];
__device__ __nv_bfloat16 g_ha_hi[NATT * KP3];
__device__ __nv_bfloat16 g_ha_lo[NATT * KP3];
__device__ __nv_bfloat16 g_mix_hi[NG * HD];
__device__ __nv_bfloat16 g_mix_lo[NG * HD];
// counters: [0..TE] cntE, [10..10+TA] cntA, [20] pcE, [21] pcA
__device__ int g_ctr[32];
__device__ int g_off_ent [TE + 1];
__device__ int g_perm_ent[NG];
__device__ int g_mcnt_ent[TE];
__device__ int g_off_attr [TA + 1];
__device__ int g_perm_attr[NATT];
__device__ int g_mcnt_attr[TA];
__device__ int g_gtok_ent[NG * TE];
__device__ int g_orow_ent[NG * TE];
__device__ int g_gtok_attr[NATT * TA];
__device__ int g_orow_attr[NATT * TA];

// ---------------- helpers ------------------------------------------------------
__device__ __forceinline__ u32 smem_u32(const void* p) {
    u32 a;
    asm("{ .reg .u64 t; cvta.to.shared.u64 t, %1; cvt.u32.u64 %0, t; }"
        : "=r"(a) : "l"(p));
    return a;
}

#define LDSM_X4(r, addr) \
    asm volatile("ldmatrix.sync.aligned.m8n8.x4.shared.b16 {%0,%1,%2,%3}, [%4];" \
        : "=r"((r)[0]), "=r"((r)[1]), "=r"((r)[2]), "=r"((r)[3]) : "r"(addr))

#define LDSM_X2(r0, r1, addr) \
    asm volatile("ldmatrix.sync.aligned.m8n8.x2.shared.b16 {%0,%1}, [%2];" \
        : "=r"(r0), "=r"(r1) : "r"(addr))

#define MMA16816(c, a, b0, b1) \
    asm volatile("mma.sync.aligned.m16n8k16.row.col.f32.bf16.bf16.f32 " \
        "{%0,%1,%2,%3}, {%4,%5,%6,%7}, {%8,%9}, {%0,%1,%2,%3};" \
        : "+f"((c)[0]), "+f"((c)[1]), "+f"((c)[2]), "+f"((c)[3]) \
        : "r"((a)[0]), "r"((a)[1]), "r"((a)[2]), "r"((a)[3]), "r"(b0), "r"(b1))

#define CP16(dst, src, sz) \
    asm volatile("cp.async.cg.shared.global [%0], [%1], 16, %2;" \
        :: "r"(dst), "l"(src), "r"(sz) : "memory")
#define CPCOMMIT() asm volatile("cp.async.commit_group;" ::: "memory")
#define CPWAIT1()  asm volatile("cp.async.wait_group 1;"  ::: "memory")
#define CPWAIT0()  asm volatile("cp.async.wait_group 0;"  ::: "memory")

#define SWZ(o) ((o) ^ (((o) >> 3) & 0x70u))

__device__ __forceinline__ void split4(float4 v, u64& hq, u64& lq) {
    unsigned short h[4], l[4];
    const float* pv = &v.x;
#pragma unroll
    for (int i = 0; i < 4; ++i) {
        __nv_bfloat16 hb = __float2bfloat16(pv[i]);
        __nv_bfloat16 lb = __float2bfloat16(pv[i] - __bfloat162float(hb));
        h[i] = __bfloat16_as_ushort(hb);
        l[i] = __bfloat16_as_ushort(lb);
    }
    hq = (u64)h[0] | ((u64)h[1] << 16) | ((u64)h[2] << 32) | ((u64)h[3] << 48);
    lq = (u64)l[0] | ((u64)l[1] << 16) | ((u64)l[2] << 32) | ((u64)l[3] << 48);
}

// ---------------- fp32 -> bf16 hi/lo splits -----------------------------------
__global__ void split_rows(const float* __restrict__ x,
                           __nv_bfloat16* __restrict__ hi,
                           __nv_bfloat16* __restrict__ lo,
                           int rows, int K, int KP)
{
    int q = KP / 4;
    int idx = blockIdx.x * blockDim.x + threadIdx.x;
    int r = idx / q;
    if (r >= rows) return;
    int i4 = (idx - r * q) * 4;
    float4 v = make_float4(0.f, 0.f, 0.f, 0.f);
    if (i4 + 4 <= K) v = *(const float4*)(x + (long)r * K + i4);
    u64 hq, lq;
    split4(v, hq, lq);
    *(u64*)(hi + (long)r * KP + i4) = hq;
    *(u64*)(lo + (long)r * KP + i4) = lq;
}

// fused split of the 4 GRU weight matrices (blockIdx.y selects)
__global__ void split_w4(const float* s0, const float* s1, const float* s2, const float* s3,
                         __nv_bfloat16* h0, __nv_bfloat16* l0,
                         __nv_bfloat16* h1, __nv_bfloat16* l1,
                         __nv_bfloat16* h2, __nv_bfloat16* l2,
                         __nv_bfloat16* h3, __nv_bfloat16* l3)
{
    const float* src; __nv_bfloat16* hi; __nv_bfloat16* lo;
    switch (blockIdx.y) {
        case 0: src = s0; hi = h0; lo = l0; break;
        case 1: src = s1; hi = h1; lo = l1; break;
        case 2: src = s2; hi = h2; lo = l2; break;
        default: src = s3; hi = h3; lo = l3; break;
    }
    int q = KP3 / 4;
    int idx = blockIdx.x * blockDim.x + threadIdx.x;
    int r = idx / q;
    if (r >= G3) return;
    int i4 = (idx - r * q) * 4;
    float4 v = make_float4(0.f, 0.f, 0.f, 0.f);
    if (i4 + 4 <= WD) v = *(const float4*)(src + (long)r * WD + i4);
    u64 hq, lq;
    split4(v, hq, lq);
    *(u64*)(hi + (long)r * KP3 + i4) = hq;
    *(u64*)(lo + (long)r * KP3 + i4) = lq;
}

// ---------------- tensor GEMM (bf16 hi/lo operands, cp.async pipeline) -------
#define TM 128
#define TN 128
#define CK 64
#define OFF_AHI 0u
#define OFF_ALO 16384u
#define OFF_BHI 32768u
#define OFF_BLO 49152u
#define STAGE   65536u
#define TG_SMEM 131072u

__global__ void __launch_bounds__(256)
tgemm(const __nv_bfloat16* __restrict__ Ahi, const __nv_bfloat16* __restrict__ Alo,
      const int* __restrict__ gather,
      const __nv_bfloat16* __restrict__ Bhi, const __nv_bfloat16* __restrict__ Blo,
      const float* __restrict__ bias,
      float* __restrict__ C, int M, int N, int K, int KP, int act, int outMap,
      const int* __restrict__ mlimit, const int* __restrict__ orow)
{
    extern __shared__ char smem[];
    int Mdyn = M;
    if (mlimit) { Mdyn = *mlimit; if (Mdyn > M) Mdyn = M; }
    const int m0 = blockIdx.x * TM;
    const int n0 = blockIdx.y * TN;
    if (m0 >= Mdyn) return;

    const u32 sbase = smem_u32(smem);
    const int tid  = threadIdx.x;
    const int wid  = tid >> 5;
    const int lane = tid & 31;
    const int wm   = wid >> 1;
    const int wn   = wid & 1;

    const int k8   = (tid & 7) * 8;
    const int rloc = tid >> 3;
    long roA[4], roB[4];
    bool vA[4], vB[4];
    u32  swR[4];
#pragma unroll
    for (int it = 0; it < 4; ++it) {
        int r = rloc + 32 * it;
        int m = m0 + r;
        vA[it] = (m < Mdyn);
        int src = vA[it] ? (gather ? gather[m] : m) : 0;
        roA[it] = (long)src * KP;
        int n = n0 + r;
        vB[it] = (n < N);
        roB[it] = (long)(vB[it] ? n : 0) * KP;
        swR[it] = SWZ((u32)(r * 128 + k8 * 2));
    }

#define FILL_CHUNK(cc, st) do { \
    int gk_ = (cc) * CK + k8; \
    u32 sb_ = sbase + (u32)(st) * STAGE; \
    bool kok_ = (gk_ < KP); \
    _Pragma("unroll") \
    for (int it = 0; it < 4; ++it) { \
        bool aok = vA[it] && kok_; u32 asz = aok ? 16u : 0u; \
        const __nv_bfloat16* pa1 = aok ? (Ahi + roA[it] + gk_) : Ahi; \
        const __nv_bfloat16* pa2 = aok ? (Alo + roA[it] + gk_) : Alo; \
        CP16(sb_ + OFF_AHI + swR[it], pa1, asz); \
        CP16(sb_ + OFF_ALO + swR[it], pa2, asz); \
        bool bok = vB[it] && kok_; u32 bsz = bok ? 16u : 0u; \
        const __nv_bfloat16* pb1 = bok ? (Bhi + roB[it] + gk_) : Bhi; \
        const __nv_bfloat16* pb2 = bok ? (Blo + roB[it] + gk_) : Blo; \
        CP16(sb_ + OFF_BHI + swR[it], pb1, bsz); \
        CP16(sb_ + OFF_BLO + swR[it], pb2, bsz); \
    } \
    CPCOMMIT(); \
} while (0)

    const u32 rbA0 = (u32)((wm * 32 + (lane & 15)) * 128);
    const u32 rbA1 = rbA0 + 16u * 128u;
    const u32 rbB  = (u32)((wn * 64 + (lane & 7)) * 128);
    const u32 xorq = (u32)(lane & 7);
    const u32 qAh  = (u32)(lane >> 4);
    const u32 qBh  = (u32)((lane >> 3) & 1);

    float acc[2][8][4];
#pragma unroll
    for (int i = 0; i < 2; ++i)
#pragma unroll
        for (int j = 0; j < 8; ++j)
#pragma unroll
            for (int q = 0; q < 4; ++q) acc[i][j][q] = 0.f;

    const int nc = (K + CK - 1) / CK;

    FILL_CHUNK(0, 0);
    for (int c = 0; c < nc; ++c) {
        if (c + 1 < nc) { FILL_CHUNK(c + 1, (c + 1) & 1); CPWAIT1(); }
        else            { CPWAIT0(); }
        __syncthreads();

        const u32 stb = sbase + (u32)(c & 1) * STAGE;
        const u32 aoffs[3] = { OFF_AHI, OFF_ALO, OFF_AHI };
        const u32 boffs[3] = { OFF_BHI, OFF_BHI, OFF_BLO };
#pragma unroll
        for (int ps = 0; ps < 3; ++ps) {
            const u32 ab = stb + aoffs[ps];
            const u32 bb = stb + boffs[ps];
#pragma unroll
            for (int ks = 0; ks < 4; ++ks) {
                u32 qa = (((u32)(2 * ks) + qAh) ^ xorq) * 16u;
                u32 a0[4], a1[4];
                LDSM_X4(a0, ab + rbA0 + qa);
                LDSM_X4(a1, ab + rbA1 + qa);
                u32 qb = (((u32)(2 * ks) + qBh) ^ xorq) * 16u;
#pragma unroll
                for (int nb = 0; nb < 8; ++nb) {
                    u32 b0, b1;
                    LDSM_X2(b0, b1, bb + rbB + (u32)nb * 1024u + qb);
                    MMA16816(acc[0][nb], a0, b0, b1);
                    MMA16816(acc[1][nb], a1, b0, b1);
                }
            }
        }
        __syncthreads();
    }
#undef FILL_CHUNK

#pragma unroll
    for (int mi = 0; mi < 2; ++mi) {
#pragma unroll
        for (int half = 0; half < 2; ++half) {
            int m = m0 + wm * 32 + mi * 16 + (lane >> 2) + half * 8;
            if (m >= Mdyn) continue;
            long base;
            if (orow)             base = (long)orow[m] * N;
            else if (outMap == 0) base = (long)m * N;
            else if (outMap == 1) base = (long)m * NNODE * HD;
            else                  base = ((long)(m >> 3) * NNODE + 1 + (m & 7)) * (long)HD;
#pragma unroll
            for (int nb = 0; nb < 8; ++nb) {
                int n = n0 + wn * 64 + nb * 8 + (lane & 3) * 2;
                if (n >= N) continue;
                float x0 = acc[mi][nb][half * 2 + 0];
                float x1 = acc[mi][nb][half * 2 + 1];
                if (bias) { x0 += bias[n]; x1 += bias[n + 1]; }
                if (act == 1)      { x0 = fmaxf(x0, 0.f); x1 = fmaxf(x1, 0.f); }
                else if (act == 2) { x0 = x0 > 0.f ? x0 : expm1f(x0);
                                     x1 = x1 > 0.f ? x1 : expm1f(x1); }
                *(float2*)(C + base + n) = make_float2(x0, x1);
            }
        }
    }
}

// ---------------- fused preprocessing (ent + attr) ---------------------------
__device__ __forceinline__ int clampL(int L, int T) {
    return L < 1 ? 1 : (L > T ? T : L);
}
__global__ void hist2(const int* __restrict__ lenE, const int* __restrict__ lenA,
                      int* __restrict__ cntE, int* __restrict__ cntA)
{
    int i = blockIdx.x * blockDim.x + threadIdx.x;
    if (i < NG)   atomicAdd(&cntE[clampL(lenE[i], TE)], 1);
    if (i < NATT) atomicAdd(&cntA[clampL(lenA[i], TA)], 1);
}
__global__ void offsets2(const int* __restrict__ cntE, int* __restrict__ offE,
                         int* __restrict__ mcntE,
                         const int* __restrict__ cntA, int* __restrict__ offA,
                         int* __restrict__ mcntA)
{
    if (threadIdx.x == 0) {
        int run = 0;
        for (int L = TE; L >= 1; --L) { offE[L] = run; run += cntE[L]; }
        for (int t = 0; t < TE; ++t) {
            int s = 0;
            for (int L = t + 1; L <= TE; ++L) s += cntE[L];
            mcntE[t] = s;
        }
    } else if (threadIdx.x == 1) {
        int run = 0;
        for (int L = TA; L >= 1; --L) { offA[L] = run; run += cntA[L]; }
        for (int t = 0; t < TA; ++t) {
            int s = 0;
            for (int L = t + 1; L <= TA; ++L) s += cntA[L];
            mcntA[t] = s;
        }
    }
}
__global__ void scatter2(const int* __restrict__ lenE, const int* __restrict__ lenA,
                         int* __restrict__ offE, int* __restrict__ permE,
                         int* __restrict__ offA, int* __restrict__ permA)
{
    int i = blockIdx.x * blockDim.x + threadIdx.x;
    if (i < NG) {
        int pos = atomicAdd(&offE[clampL(lenE[i], TE)], 1);
        permE[pos] = i;
    }
    if (i < NATT) {
        int pos = atomicAdd(&offA[clampL(lenA[i], TA)], 1);
        permA[pos] = i;
    }
}
__global__ void pairs2(const int* __restrict__ tokE, const int* __restrict__ lenE,
                       int* __restrict__ pcE, int* __restrict__ gtokE, int* __restrict__ orowE,
                       const int* __restrict__ tokA, const int* __restrict__ lenA,
                       int* __restrict__ pcA, int* __restrict__ gtokA, int* __restrict__ orowA)
{
    int p = blockIdx.x * blockDim.x + threadIdx.x;
    if (p < NG * TE) {
        int i = p / TE, t = p - i * TE;
        if (t < clampL(lenE[i], TE)) {
            int pos = atomicAdd(pcE, 1);
            gtokE[pos] = tokE[p];
            orowE[pos] = p;
        }
    }
    if (p < NATT * TA) {
        int i = p / TA, t = p - i * TA;
        if (t < clampL(lenA[i], TA)) {
            int pos = atomicAdd(pcA, 1);
            gtokA[pos] = tokA[p];
            orowA[pos] = p;
        }
    }
}

// ---------------- GRU gate update (t0 path uses gh = bhh, h = 0) -------------
__global__ void gru_gate4(const float* __restrict__ xp,
                          const float* __restrict__ gh,
                          const float* __restrict__ bhh_t0,   // non-null => t==0
                          float* __restrict__ h,
                          __nv_bfloat16* __restrict__ hhi,
                          __nv_bfloat16* __restrict__ hlo,
                          const int* __restrict__ perm,
                          const int* __restrict__ mcnt,
                          int t, int T)
{
    const int Q = WD / 4;   // 75
    int idx = blockIdx.x * blockDim.x + threadIdx.x;
    int i = idx / Q;
    if (i >= *mcnt) return;
    int d = idx - i * Q;
    int orig = perm[i];
    const float4* x = (const float4*)(xp + ((long)orig * T + t) * G3);
    float4* hp = (float4*)(h + (long)orig * WD);

    float4 xr = x[d], xz = x[Q + d], xn = x[2 * Q + d];
    float4 gr, gz, gn, hv;
    if (bhh_t0) {
        const float4* b = (const float4*)bhh_t0;
        gr = b[d]; gz = b[Q + d]; gn = b[2 * Q + d];
        hv = make_float4(0.f, 0.f, 0.f, 0.f);
    } else {
        const float4* g = (const float4*)(gh + (long)i * G3);
        gr = g[d]; gz = g[Q + d]; gn = g[2 * Q + d];
        hv = hp[d];
    }

    float4 res;
    const float* pxr = &xr.x; const float* pxz = &xz.x; const float* pxn = &xn.x;
    const float* pgr = &gr.x; const float* pgz = &gz.x; const float* pgn = &gn.x;
    const float* phv = &hv.x; float* pres = &res.x;
#pragma unroll
    for (int c = 0; c < 4; ++c) {
        float r = 1.f / (1.f + expf(-(pxr[c] + pgr[c])));
        float z = 1.f / (1.f + expf(-(pxz[c] + pgz[c])));
        float n = tanhf(pxn[c] + r * pgn[c]);
        pres[c] = (1.f - z) * n + z * phv[c];
    }
    hp[d] = res;
    u64 hq, lq;
    split4(res, hq, lq);
    *(u64*)(hhi + (long)orig * KP3 + 4 * d) = hq;
    *(u64*)(hlo + (long)orig * KP3 + 4 * d) = lq;
}

// ---------------- va/vb = Wg^T a_src / Wg^T a_dst ----------------------------
__global__ void wgt_vec_kernel(const float* __restrict__ Wg,
                               const float* __restrict__ a_src,
                               const float* __restrict__ a_dst,
                               float* __restrict__ va, float* __restrict__ vb)
{
    int k = blockIdx.x * blockDim.x + threadIdx.x;
    if (k >= HD) return;
    float sa = 0.f, sb = 0.f;
    for (int d = 0; d < HD; ++d) {
        float w = Wg[(long)d * HD + k];
        sa += w * a_src[d];
        sb += w * a_dst[d];
    }
    va[k] = sa;
    vb[k] = sb;
}

// ---------------- GAT dots + softmax + node mix (writes bf16 hi/lo) ----------
__global__ void gat_mix_kernel(const float* __restrict__ nodes,
                               const float* __restrict__ va,
                               const float* __restrict__ vb,
                               const unsigned char* __restrict__ amask,
                               __nv_bfloat16* __restrict__ mhi,
                               __nv_bfloat16* __restrict__ mlo)
{
    int g = blockIdx.x;
    const float* base = nodes + (long)g * NNODE * HD;
    __shared__ float sdots[10];
    __shared__ float salpha[NNODE];

    int tid  = threadIdx.x;
    int warp = tid >> 5, lane = tid & 31;

    float partial = 0.f;
    if (warp < 9) {
        const float* row = base + warp * HD;
        for (int d = lane; d < HD; d += 32) partial += row[d] * vb[d];
    } else {
        for (int d = lane; d < HD; d += 32) partial += base[d] * va[d];
    }
#pragma unroll
    for (int off = 16; off; off >>= 1)
        partial += __shfl_down_sync(0xffffffffu, partial, off);
    if (lane == 0) sdots[warp] = partial;
    __syncthreads();

    if (tid == 0) {
        float es0 = sdots[9];
        float e[NNODE];
#pragma unroll
        for (int j = 0; j < NNODE; ++j) {
            bool valid;
            if (j == 0) valid = true;
            else {
                const unsigned char* mk = amask + ((long)g * NA + (j - 1)) * TA;
                valid = !(mk[0] && mk[1] && mk[2] && mk[3]);
            }
            if (valid) {
                float v = es0 + sdots[j];
                e[j] = v > 0.f ? v : 0.2f * v;
            } else e[j] = -1e9f;
        }
        float mx = e[0];
#pragma unroll
        for (int j = 1; j < NNODE; ++j) mx = fmaxf(mx, e[j]);
        float s = 0.f, ex[NNODE];
#pragma unroll
        for (int j = 0; j < NNODE; ++j) { ex[j] = expf(e[j] - mx); s += ex[j]; }
        float inv = 1.f / s;
#pragma unroll
        for (int j = 0; j < NNODE; ++j) salpha[j] = ex[j] * inv;
    }
    __syncthreads();

    for (int d4 = tid; d4 < HD / 4; d4 += blockDim.x) {
        float4 s4;
        float* ps = &s4.x;
#pragma unroll
        for (int q = 0; q < 4; ++q) {
            int d = d4 * 4 + q;
            float s = 0.f;
#pragma unroll
            for (int j = 0; j < NNODE; ++j) s += salpha[j] * base[j * HD + d];
            ps[q] = s;
        }
        u64 hq, lq;
        split4(s4, hq, lq);
        *(u64*)(mhi + (long)g * HD + 4 * d4) = hq;
        *(u64*)(mlo + (long)g * HD + 4 * d4) = lq;
    }
}

// ---------------- launch ------------------------------------------------------
extern "C" void kernel_launch(void* const* d_in, const int* in_sizes, int n_in,
                              void* d_out, int out_size)
{
    const int*   ent_tok  = (const int*)  d_in[0];
    const int*   ent_len  = (const int*)  d_in[1];
    const int*   at_tok   = (const int*)  d_in[3];
    const int*   at_len   = (const int*)  d_in[4];
    const unsigned char* at_mask = (const unsigned char*)d_in[5];
    const float* emb      = (const float*)d_in[6];
    const float* Wih_ent  = (const float*)d_in[7];
    const float* Whh_ent  = (const float*)d_in[8];
    const float* bih_ent  = (const float*)d_in[9];
    const float* bhh_ent  = (const float*)d_in[10];
    const float* Wih_attr = (const float*)d_in[11];
    const float* Whh_attr = (const float*)d_in[12];
    const float* bih_attr = (const float*)d_in[13];
    const float* bhh_attr = (const float*)d_in[14];
    const float* Wfc      = (const float*)d_in[15];
    const float* bfc      = (const float*)d_in[16];
    const float* Wg       = (const float*)d_in[17];
    const float* a_src    = (const float*)d_in[18];
    const float* a_dst    = (const float*)d_in[19];
    float* out = (float*)d_out;

    // second stream + fork/join events (host objects; created once)
    static cudaStream_t s2 = nullptr;
    static cudaEvent_t evF = nullptr, evJ = nullptr;
    if (!s2) {
        cudaStreamCreateWithFlags(&s2, cudaStreamNonBlocking);
        cudaEventCreateWithFlags(&evF, cudaEventDisableTiming);
        cudaEventCreateWithFlags(&evJ, cudaEventDisableTiming);
    }

    float *xp_ent, *xp_attr, *ghE, *ghA, *h_ent, *h_attr, *nodes, *va, *vb;
    int *ctr, *offE, *permE, *mcntE, *offA, *permA, *mcntA;
    int *gtokE, *orowE, *gtokA, *orowA;
    __nv_bfloat16 *embH, *embL, *wiheH, *wiheL, *whheH, *whheL;
    __nv_bfloat16 *wihaH, *wihaL, *whhaH, *whhaL, *wfcH, *wfcL, *wgH, *wgL;
    __nv_bfloat16 *heH, *heL, *haH, *haL, *mixH, *mixL;

    cudaGetSymbolAddress((void**)&xp_ent,  g_xp_ent);
    cudaGetSymbolAddress((void**)&xp_attr, g_xp_attr);
    cudaGetSymbolAddress((void**)&ghE,     g_gh_ent);
    cudaGetSymbolAddress((void**)&ghA,     g_gh_attr);
    cudaGetSymbolAddress((void**)&h_ent,   g_h_ent);
    cudaGetSymbolAddress((void**)&h_attr,  g_h_attr);
    cudaGetSymbolAddress((void**)&nodes,   g_nodes);
    cudaGetSymbolAddress((void**)&va,      g_va);
    cudaGetSymbolAddress((void**)&vb,      g_vb);
    cudaGetSymbolAddress((void**)&ctr,   g_ctr);
    cudaGetSymbolAddress((void**)&offE,  g_off_ent);
    cudaGetSymbolAddress((void**)&permE, g_perm_ent);
    cudaGetSymbolAddress((void**)&mcntE, g_mcnt_ent);
    cudaGetSymbolAddress((void**)&offA,  g_off_attr);
    cudaGetSymbolAddress((void**)&permA, g_perm_attr);
    cudaGetSymbolAddress((void**)&mcntA, g_mcnt_attr);
    cudaGetSymbolAddress((void**)&gtokE, g_gtok_ent);
    cudaGetSymbolAddress((void**)&orowE, g_orow_ent);
    cudaGetSymbolAddress((void**)&gtokA, g_gtok_attr);
    cudaGetSymbolAddress((void**)&orowA, g_orow_attr);
    cudaGetSymbolAddress((void**)&embH,  g_emb_hi);
    cudaGetSymbolAddress((void**)&embL,  g_emb_lo);
    cudaGetSymbolAddress((void**)&wiheH, g_wihe_hi);
    cudaGetSymbolAddress((void**)&wiheL, g_wihe_lo);
    cudaGetSymbolAddress((void**)&whheH, g_whhe_hi);
    cudaGetSymbolAddress((void**)&whheL, g_whhe_lo);
    cudaGetSymbolAddress((void**)&wihaH, g_wiha_hi);
    cudaGetSymbolAddress((void**)&wihaL, g_wiha_lo);
    cudaGetSymbolAddress((void**)&whhaH, g_whha_hi);
    cudaGetSymbolAddress((void**)&whhaL, g_whha_lo);
    cudaGetSymbolAddress((void**)&wfcH,  g_wfc_hi);
    cudaGetSymbolAddress((void**)&wfcL,  g_wfc_lo);
    cudaGetSymbolAddress((void**)&wgH,   g_wg_hi);
    cudaGetSymbolAddress((void**)&wgL,   g_wg_lo);
    cudaGetSymbolAddress((void**)&heH,   g_he_hi);
    cudaGetSymbolAddress((void**)&heL,   g_he_lo);
    cudaGetSymbolAddress((void**)&haH,   g_ha_hi);
    cudaGetSymbolAddress((void**)&haL,   g_ha_lo);
    cudaGetSymbolAddress((void**)&mixH,  g_mix_hi);
    cudaGetSymbolAddress((void**)&mixL,  g_mix_lo);

    int* cntE = ctr + 0;
    int* cntA = ctr + 10;
    int* pcE  = ctr + 20;
    int* pcA  = ctr + 21;

    cudaFuncSetAttribute(tgemm, cudaFuncAttributeMaxDynamicSharedMemorySize, TG_SMEM);

    // one small memset for all counters
    cudaMemsetAsync(ctr, 0, 32 * sizeof(int));

    // operand splits
    const int q3 = KP3 / 4;
    split_rows<<<(V * q3 + 255) / 256, 256>>>(emb, embH, embL, V, WD, KP3);
    split_w4<<<dim3((G3 * q3 + 255) / 256, 4), 256>>>(
        Wih_ent, Whh_ent, Wih_attr, Whh_attr,
        wiheH, wiheL, whheH, whheL, wihaH, wihaL, whhaH, whhaL);
    split_rows<<<(HD * q3 + 255) / 256, 256>>>(Wfc, wfcH, wfcL, HD, WD, KP3);
    split_rows<<<(HD * (HD / 4) + 255) / 256, 256>>>(Wg, wgH, wgL, HD, HD, HD);

    // fused preprocessing
    hist2<<<(NATT + 255) / 256, 256>>>(ent_len, at_len, cntE, cntA);
    offsets2<<<1, 32>>>(cntE, offE, mcntE, cntA, offA, mcntA);
    scatter2<<<(NATT + 255) / 256, 256>>>(ent_len, at_len, offE, permE, offA, permA);
    pairs2<<<(NATT * TA + 255) / 256, 256>>>(ent_tok, ent_len, pcE, gtokE, orowE,
                                             at_tok, at_len, pcA, gtokA, orowA);

    wgt_vec_kernel<<<(HD + 255) / 256, 256>>>(Wg, a_src, a_dst, va, vb);

    const int nt900  = (G3 + TN - 1) / TN;   // 8
    const int nt1024 = HD / TN;              // 8

    // xp_ent on main, then fork entity chain onto s2
    tgemm<<<dim3(NG * TE / TM, nt900), 256, TG_SMEM>>>(
        embH, embL, gtokE, wiheH, wiheL, bih_ent, xp_ent,
        NG * TE, G3, WD, KP3, 0, 0, pcE, orowE);

    cudaEventRecord(evF, 0);
    cudaStreamWaitEvent(s2, evF, 0);

    // ---- entity chain (stream s2) ----
    gru_gate4<<<(NG * 75 + 255) / 256, 256, 0, s2>>>(
        xp_ent, nullptr, bhh_ent, h_ent, heH, heL, permE, mcntE + 0, 0, TE);
    for (int t = 1; t < TE; ++t) {
        tgemm<<<dim3(NG / TM, nt900), 256, TG_SMEM, s2>>>(
            heH, heL, permE, whheH, whheL, bhh_ent, ghE,
            NG, G3, WD, KP3, 0, 0, mcntE + t, nullptr);
        gru_gate4<<<(NG * 75 + 255) / 256, 256, 0, s2>>>(
            xp_ent, ghE, nullptr, h_ent, heH, heL, permE, mcntE + t, t, TE);
    }
    tgemm<<<dim3(NG / TM, nt1024), 256, TG_SMEM, s2>>>(
        heH, heL, nullptr, wfcH, wfcL, bfc, nodes,
        NG, HD, WD, KP3, 1, 1, nullptr, nullptr);
    cudaEventRecord(evJ, s2);

    // ---- attribute chain (main stream, concurrent with s2) ----
    tgemm<<<dim3(NATT * TA / TM, nt900), 256, TG_SMEM>>>(
        embH, embL, gtokA, wihaH, wihaL, bih_attr, xp_attr,
        NATT * TA, G3, WD, KP3, 0, 0, pcA, orowA);
    gru_gate4<<<(NATT * 75 + 255) / 256, 256>>>(
        xp_attr, nullptr, bhh_attr, h_attr, haH, haL, permA, mcntA + 0, 0, TA);
    for (int t = 1; t < TA; ++t) {
        tgemm<<<dim3(NATT / TM, nt900), 256, TG_SMEM>>>(
            haH, haL, permA, whhaH, whhaL, bhh_attr, ghA,
            NATT, G3, WD, KP3, 0, 0, mcntA + t, nullptr);
        gru_gate4<<<(NATT * 75 + 255) / 256, 256>>>(
            xp_attr, ghA, nullptr, h_attr, haH, haL, permA, mcntA + t, t, TA);
    }
    tgemm<<<dim3(NATT / TM, nt1024), 256, TG_SMEM>>>(
        haH, haL, nullptr, wfcH, wfcL, bfc, nodes,
        NATT, HD, WD, KP3, 1, 2, nullptr, nullptr);

    // join entity chain
    cudaStreamWaitEvent(0, evJ, 0);

    // GAT: dots + alpha + mix (bf16 hi/lo out)
    gat_mix_kernel<<<NG, 320>>>(nodes, va, vb, at_mask, mixH, mixL);

    // out = elu(mix @ Wg^T)
    tgemm<<<dim3(NG / TM, nt1024), 256, TG_SMEM>>>(
        mixH, mixL, nullptr, wgH, wgL, nullptr, out,
        NG, HD, HD, HD, 2, 0, nullptr, nullptr);
}

// round 10
// speedup vs baseline: 4.9291x; 1.3288x over previous
#include <cuda_runtime.h>
#include <cuda_fp16.h>
#include <math.h>

// Problem constants
#define BS   128
#define NE   32
#define NA   8
#define TE   8
#define TA   4
#define WD   300
#define HD   1024
#define G3   900          // 3*WD
#define NG   (BS*NE)      // 4096
#define NATT (NG*NA)      // 32768
#define NNODE 9
#define V    30522
#define KP3  304          // WD padded to multiple of 8

typedef unsigned long long u64;
typedef unsigned int u32;

// ---------------- scratch ----------------------------------------------------
__device__ float g_xp_ent [NG   * TE * G3];
__device__ float g_xp_attr[NATT * TA * G3];
__device__ float g_gh_ent [NG   * G3];
__device__ float g_gh_attr[NATT * G3];
__device__ float g_h_ent  [NG   * WD];
__device__ float g_h_attr [NATT * WD];
__device__ float g_nodes  [NG * NNODE * HD];
__device__ float g_va     [HD];
__device__ float g_vb     [HD];
// fp16 operand buffers (A-side needs hi+lo; B-side/weights hi only)
__device__ __half g_emb_hi[V * KP3];
__device__ __half g_emb_lo[V * KP3];
__device__ __half g_wihe_hi[G3 * KP3];
__device__ __half g_whhe_hi[G3 * KP3];
__device__ __half g_wiha_hi[G3 * KP3];
__device__ __half g_whha_hi[G3 * KP3];
__device__ __half g_wfc_hi[HD * KP3];
__device__ __half g_wg_hi[HD * HD];
__device__ __half g_he_hi[NG * KP3];
__device__ __half g_he_lo[NG * KP3];
__device__ __half g_ha_hi[NATT * KP3];
__device__ __half g_ha_lo[NATT * KP3];
__device__ __half g_mix_hi[NG * HD];
__device__ __half g_mix_lo[NG * HD];
// counters: [0..TE] cntE, [10..10+TA] cntA, [20] pcE, [21] pcA
__device__ int g_ctr[32];
__device__ int g_off_ent [TE + 1];
__device__ int g_perm_ent[NG];
__device__ int g_mcnt_ent[TE];
__device__ int g_off_attr [TA + 1];
__device__ int g_perm_attr[NATT];
__device__ int g_mcnt_attr[TA];
__device__ int g_gtok_ent[NG * TE];
__device__ int g_orow_ent[NG * TE];
__device__ int g_gtok_attr[NATT * TA];
__device__ int g_orow_attr[NATT * TA];

// ---------------- helpers ------------------------------------------------------
__device__ __forceinline__ u32 smem_u32(const void* p) {
    u32 a;
    asm("{ .reg .u64 t; cvta.to.shared.u64 t, %1; cvt.u32.u64 %0, t; }"
        : "=r"(a) : "l"(p));
    return a;
}

#define LDSM_X4(r, addr) \
    asm volatile("ldmatrix.sync.aligned.m8n8.x4.shared.b16 {%0,%1,%2,%3}, [%4];" \
        : "=r"((r)[0]), "=r"((r)[1]), "=r"((r)[2]), "=r"((r)[3]) : "r"(addr))

#define LDSM_X2(r0, r1, addr) \
    asm volatile("ldmatrix.sync.aligned.m8n8.x2.shared.b16 {%0,%1}, [%2];" \
        : "=r"(r0), "=r"(r1) : "r"(addr))

#define MMA16816(c, a, b0, b1) \
    asm volatile("mma.sync.aligned.m16n8k16.row.col.f32.f16.f16.f32 " \
        "{%0,%1,%2,%3}, {%4,%5,%6,%7}, {%8,%9}, {%0,%1,%2,%3};" \
        : "+f"((c)[0]), "+f"((c)[1]), "+f"((c)[2]), "+f"((c)[3]) \
        : "r"((a)[0]), "r"((a)[1]), "r"((a)[2]), "r"((a)[3]), "r"(b0), "r"(b1))

#define CP16(dst, src, sz) \
    asm volatile("cp.async.cg.shared.global [%0], [%1], 16, %2;" \
        :: "r"(dst), "l"(src), "r"(sz) : "memory")
#define CPCOMMIT() asm volatile("cp.async.commit_group;" ::: "memory")
#define CPWAIT1()  asm volatile("cp.async.wait_group 1;"  ::: "memory")
#define CPWAIT0()  asm volatile("cp.async.wait_group 0;"  ::: "memory")

#define SWZ(o) ((o) ^ (((o) >> 3) & 0x70u))

__device__ __forceinline__ void split4h(float4 v, u64& hq, u64& lq) {
    unsigned short h[4], l[4];
    const float* pv = &v.x;
#pragma unroll
    for (int i = 0; i < 4; ++i) {
        __half hb = __float2half(pv[i]);
        __half lb = __float2half(pv[i] - __half2float(hb));
        h[i] = __half_as_ushort(hb);
        l[i] = __half_as_ushort(lb);
    }
    hq = (u64)h[0] | ((u64)h[1] << 16) | ((u64)h[2] << 32) | ((u64)h[3] << 48);
    lq = (u64)l[0] | ((u64)l[1] << 16) | ((u64)l[2] << 32) | ((u64)l[3] << 48);
}
__device__ __forceinline__ u64 cvt4h(float4 v) {
    unsigned short h[4];
    const float* pv = &v.x;
#pragma unroll
    for (int i = 0; i < 4; ++i) h[i] = __half_as_ushort(__float2half(pv[i]));
    return (u64)h[0] | ((u64)h[1] << 16) | ((u64)h[2] << 32) | ((u64)h[3] << 48);
}

// ---------------- fp32 -> fp16 splits -----------------------------------------
__global__ void split_rows(const float* __restrict__ x,
                           __half* __restrict__ hi, __half* __restrict__ lo,
                           int rows, int K, int KP)
{
    int q = KP / 4;
    int idx = blockIdx.x * blockDim.x + threadIdx.x;
    int r = idx / q;
    if (r >= rows) return;
    int i4 = (idx - r * q) * 4;
    float4 v = make_float4(0.f, 0.f, 0.f, 0.f);
    if (i4 + 4 <= K) v = *(const float4*)(x + (long)r * K + i4);
    u64 hq, lq;
    split4h(v, hq, lq);
    *(u64*)(hi + (long)r * KP + i4) = hq;
    *(u64*)(lo + (long)r * KP + i4) = lq;
}

// hi-only conversion for weight matrices (B operands)
__global__ void cvt_rows_hi(const float* __restrict__ x,
                            __half* __restrict__ hi,
                            int rows, int K, int KP)
{
    int q = KP / 4;
    int idx = blockIdx.x * blockDim.x + threadIdx.x;
    int r = idx / q;
    if (r >= rows) return;
    int i4 = (idx - r * q) * 4;
    float4 v = make_float4(0.f, 0.f, 0.f, 0.f);
    if (i4 + 4 <= K) v = *(const float4*)(x + (long)r * K + i4);
    *(u64*)(hi + (long)r * KP + i4) = cvt4h(v);
}

// fused hi-only conversion of the 4 GRU weight matrices
__global__ void cvt_w4(const float* s0, const float* s1, const float* s2, const float* s3,
                       __half* h0, __half* h1, __half* h2, __half* h3)
{
    const float* src; __half* hi;
    switch (blockIdx.y) {
        case 0: src = s0; hi = h0; break;
        case 1: src = s1; hi = h1; break;
        case 2: src = s2; hi = h2; break;
        default: src = s3; hi = h3; break;
    }
    int q = KP3 / 4;
    int idx = blockIdx.x * blockDim.x + threadIdx.x;
    int r = idx / q;
    if (r >= G3) return;
    int i4 = (idx - r * q) * 4;
    float4 v = make_float4(0.f, 0.f, 0.f, 0.f);
    if (i4 + 4 <= WD) v = *(const float4*)(src + (long)r * WD + i4);
    *(u64*)(hi + (long)r * KP3 + i4) = cvt4h(v);
}

// ---------------- tensor GEMM (fp16 2-pass, cp.async pipeline) ----------------
#define TM 128
#define TN 128
#define CK 64
#define OFF_AHI 0u
#define OFF_ALO 16384u
#define OFF_BHI 32768u
#define STAGE   49152u
#define TG_SMEM 98304u

__global__ void __launch_bounds__(256, 2)
tgemm(const __half* __restrict__ Ahi, const __half* __restrict__ Alo,
      const int* __restrict__ gather,
      const __half* __restrict__ Bhi,
      const float* __restrict__ bias,
      float* __restrict__ C, int M, int N, int K, int KP, int act, int outMap,
      const int* __restrict__ mlimit, const int* __restrict__ orow)
{
    extern __shared__ char smem[];
    int Mdyn = M;
    if (mlimit) { Mdyn = *mlimit; if (Mdyn > M) Mdyn = M; }
    const int m0 = blockIdx.x * TM;
    const int n0 = blockIdx.y * TN;
    if (m0 >= Mdyn) return;

    const u32 sbase = smem_u32(smem);
    const int tid  = threadIdx.x;
    const int wid  = tid >> 5;
    const int lane = tid & 31;
    const int wm   = wid >> 1;
    const int wn   = wid & 1;

    const int k8   = (tid & 7) * 8;
    const int rloc = tid >> 3;
    long roA[4], roB[4];
    bool vA[4], vB[4];
    u32  swR[4];
#pragma unroll
    for (int it = 0; it < 4; ++it) {
        int r = rloc + 32 * it;
        int m = m0 + r;
        vA[it] = (m < Mdyn);
        int src = vA[it] ? (gather ? gather[m] : m) : 0;
        roA[it] = (long)src * KP;
        int n = n0 + r;
        vB[it] = (n < N);
        roB[it] = (long)(vB[it] ? n : 0) * KP;
        swR[it] = SWZ((u32)(r * 128 + k8 * 2));
    }

#define FILL_CHUNK(cc, st) do { \
    int gk_ = (cc) * CK + k8; \
    u32 sb_ = sbase + (u32)(st) * STAGE; \
    bool kok_ = (gk_ < KP); \
    _Pragma("unroll") \
    for (int it = 0; it < 4; ++it) { \
        bool aok = vA[it] && kok_; u32 asz = aok ? 16u : 0u; \
        const __half* pa1 = aok ? (Ahi + roA[it] + gk_) : Ahi; \
        const __half* pa2 = aok ? (Alo + roA[it] + gk_) : Alo; \
        CP16(sb_ + OFF_AHI + swR[it], pa1, asz); \
        CP16(sb_ + OFF_ALO + swR[it], pa2, asz); \
        bool bok = vB[it] && kok_; u32 bsz = bok ? 16u : 0u; \
        const __half* pb1 = bok ? (Bhi + roB[it] + gk_) : Bhi; \
        CP16(sb_ + OFF_BHI + swR[it], pb1, bsz); \
    } \
    CPCOMMIT(); \
} while (0)

    const u32 rbA0 = (u32)((wm * 32 + (lane & 15)) * 128);
    const u32 rbA1 = rbA0 + 16u * 128u;
    const u32 rbB  = (u32)((wn * 64 + (lane & 7)) * 128);
    const u32 xorq = (u32)(lane & 7);
    const u32 qAh  = (u32)(lane >> 4);
    const u32 qBh  = (u32)((lane >> 3) & 1);

    float acc[2][8][4];
#pragma unroll
    for (int i = 0; i < 2; ++i)
#pragma unroll
        for (int j = 0; j < 8; ++j)
#pragma unroll
            for (int q = 0; q < 4; ++q) acc[i][j][q] = 0.f;

    const int nc = (K + CK - 1) / CK;

    FILL_CHUNK(0, 0);
    for (int c = 0; c < nc; ++c) {
        if (c + 1 < nc) { FILL_CHUNK(c + 1, (c + 1) & 1); CPWAIT1(); }
        else            { CPWAIT0(); }
        __syncthreads();

        const u32 stb = sbase + (u32)(c & 1) * STAGE;
        const u32 aoffs[2] = { OFF_AHI, OFF_ALO };
#pragma unroll
        for (int ps = 0; ps < 2; ++ps) {
            const u32 ab = stb + aoffs[ps];
            const u32 bb = stb + OFF_BHI;
#pragma unroll
            for (int ks = 0; ks < 4; ++ks) {
                u32 qa = (((u32)(2 * ks) + qAh) ^ xorq) * 16u;
                u32 a0[4], a1[4];
                LDSM_X4(a0, ab + rbA0 + qa);
                LDSM_X4(a1, ab + rbA1 + qa);
                u32 qb = (((u32)(2 * ks) + qBh) ^ xorq) * 16u;
#pragma unroll
                for (int nb = 0; nb < 8; ++nb) {
                    u32 b0, b1;
                    LDSM_X2(b0, b1, bb + rbB + (u32)nb * 1024u + qb);
                    MMA16816(acc[0][nb], a0, b0, b1);
                    MMA16816(acc[1][nb], a1, b0, b1);
                }
            }
        }
        __syncthreads();
    }
#undef FILL_CHUNK

#pragma unroll
    for (int mi = 0; mi < 2; ++mi) {
#pragma unroll
        for (int half = 0; half < 2; ++half) {
            int m = m0 + wm * 32 + mi * 16 + (lane >> 2) + half * 8;
            if (m >= Mdyn) continue;
            long base;
            if (orow)             base = (long)orow[m] * N;
            else if (outMap == 0) base = (long)m * N;
            else if (outMap == 1) base = (long)m * NNODE * HD;
            else                  base = ((long)(m >> 3) * NNODE + 1 + (m & 7)) * (long)HD;
#pragma unroll
            for (int nb = 0; nb < 8; ++nb) {
                int n = n0 + wn * 64 + nb * 8 + (lane & 3) * 2;
                if (n >= N) continue;
                float x0 = acc[mi][nb][half * 2 + 0];
                float x1 = acc[mi][nb][half * 2 + 1];
                if (bias) { x0 += bias[n]; x1 += bias[n + 1]; }
                if (act == 1)      { x0 = fmaxf(x0, 0.f); x1 = fmaxf(x1, 0.f); }
                else if (act == 2) { x0 = x0 > 0.f ? x0 : expm1f(x0);
                                     x1 = x1 > 0.f ? x1 : expm1f(x1); }
                *(float2*)(C + base + n) = make_float2(x0, x1);
            }
        }
    }
}

// ---------------- fused preprocessing (ent + attr) ---------------------------
__device__ __forceinline__ int clampL(int L, int T) {
    return L < 1 ? 1 : (L > T ? T : L);
}
__global__ void hist2(const int* __restrict__ lenE, const int* __restrict__ lenA,
                      int* __restrict__ cntE, int* __restrict__ cntA)
{
    int i = blockIdx.x * blockDim.x + threadIdx.x;
    if (i < NG)   atomicAdd(&cntE[clampL(lenE[i], TE)], 1);
    if (i < NATT) atomicAdd(&cntA[clampL(lenA[i], TA)], 1);
}
__global__ void offsets2(const int* __restrict__ cntE, int* __restrict__ offE,
                         int* __restrict__ mcntE,
                         const int* __restrict__ cntA, int* __restrict__ offA,
                         int* __restrict__ mcntA)
{
    if (threadIdx.x == 0) {
        int run = 0;
        for (int L = TE; L >= 1; --L) { offE[L] = run; run += cntE[L]; }
        for (int t = 0; t < TE; ++t) {
            int s = 0;
            for (int L = t + 1; L <= TE; ++L) s += cntE[L];
            mcntE[t] = s;
        }
    } else if (threadIdx.x == 1) {
        int run = 0;
        for (int L = TA; L >= 1; --L) { offA[L] = run; run += cntA[L]; }
        for (int t = 0; t < TA; ++t) {
            int s = 0;
            for (int L = t + 1; L <= TA; ++L) s += cntA[L];
            mcntA[t] = s;
        }
    }
}
__global__ void scatter2(const int* __restrict__ lenE, const int* __restrict__ lenA,
                         int* __restrict__ offE, int* __restrict__ permE,
                         int* __restrict__ offA, int* __restrict__ permA)
{
    int i = blockIdx.x * blockDim.x + threadIdx.x;
    if (i < NG) {
        int pos = atomicAdd(&offE[clampL(lenE[i], TE)], 1);
        permE[pos] = i;
    }
    if (i < NATT) {
        int pos = atomicAdd(&offA[clampL(lenA[i], TA)], 1);
        permA[pos] = i;
    }
}
__global__ void pairs2(const int* __restrict__ tokE, const int* __restrict__ lenE,
                       int* __restrict__ pcE, int* __restrict__ gtokE, int* __restrict__ orowE,
                       const int* __restrict__ tokA, const int* __restrict__ lenA,
                       int* __restrict__ pcA, int* __restrict__ gtokA, int* __restrict__ orowA)
{
    int p = blockIdx.x * blockDim.x + threadIdx.x;
    if (p < NG * TE) {
        int i = p / TE, t = p - i * TE;
        if (t < clampL(lenE[i], TE)) {
            int pos = atomicAdd(pcE, 1);
            gtokE[pos] = tokE[p];
            orowE[pos] = p;
        }
    }
    if (p < NATT * TA) {
        int i = p / TA, t = p - i * TA;
        if (t < clampL(lenA[i], TA)) {
            int pos = atomicAdd(pcA, 1);
            gtokA[pos] = tokA[p];
            orowA[pos] = p;
        }
    }
}

// ---------------- GRU gate update (t0 path uses gh = bhh, h = 0) -------------
__global__ void gru_gate4(const float* __restrict__ xp,
                          const float* __restrict__ gh,
                          const float* __restrict__ bhh_t0,   // non-null => t==0
                          float* __restrict__ h,
                          __half* __restrict__ hhi,
                          __half* __restrict__ hlo,
                          const int* __restrict__ perm,
                          const int* __restrict__ mcnt,
                          int t, int T)
{
    const int Q = WD / 4;   // 75
    int idx = blockIdx.x * blockDim.x + threadIdx.x;
    int i = idx / Q;
    if (i >= *mcnt) return;
    int d = idx - i * Q;
    int orig = perm[i];
    const float4* x = (const float4*)(xp + ((long)orig * T + t) * G3);
    float4* hp = (float4*)(h + (long)orig * WD);

    float4 xr = x[d], xz = x[Q + d], xn = x[2 * Q + d];
    float4 gr, gz, gn, hv;
    if (bhh_t0) {
        const float4* b = (const float4*)bhh_t0;
        gr = b[d]; gz = b[Q + d]; gn = b[2 * Q + d];
        hv = make_float4(0.f, 0.f, 0.f, 0.f);
    } else {
        const float4* g = (const float4*)(gh + (long)i * G3);
        gr = g[d]; gz = g[Q + d]; gn = g[2 * Q + d];
        hv = hp[d];
    }

    float4 res;
    const float* pxr = &xr.x; const float* pxz = &xz.x; const float* pxn = &xn.x;
    const float* pgr = &gr.x; const float* pgz = &gz.x; const float* pgn = &gn.x;
    const float* phv = &hv.x; float* pres = &res.x;
#pragma unroll
    for (int c = 0; c < 4; ++c) {
        float r = 1.f / (1.f + expf(-(pxr[c] + pgr[c])));
        float z = 1.f / (1.f + expf(-(pxz[c] + pgz[c])));
        float n = tanhf(pxn[c] + r * pgn[c]);
        pres[c] = (1.f - z) * n + z * phv[c];
    }
    hp[d] = res;
    u64 hq, lq;
    split4h(res, hq, lq);
    *(u64*)(hhi + (long)orig * KP3 + 4 * d) = hq;
    *(u64*)(hlo + (long)orig * KP3 + 4 * d) = lq;
}

// ---------------- va/vb = Wg^T a_src / Wg^T a_dst ----------------------------
__global__ void wgt_vec_kernel(const float* __restrict__ Wg,
                               const float* __restrict__ a_src,
                               const float* __restrict__ a_dst,
                               float* __restrict__ va, float* __restrict__ vb)
{
    int k = blockIdx.x * blockDim.x + threadIdx.x;
    if (k >= HD) return;
    float sa = 0.f, sb = 0.f;
    for (int d = 0; d < HD; ++d) {
        float w = Wg[(long)d * HD + k];
        sa += w * a_src[d];
        sb += w * a_dst[d];
    }
    va[k] = sa;
    vb[k] = sb;
}

// ---------------- GAT dots + softmax + node mix (writes fp16 hi/lo) ----------
__global__ void gat_mix_kernel(const float* __restrict__ nodes,
                               const float* __restrict__ va,
                               const float* __restrict__ vb,
                               const unsigned char* __restrict__ amask,
                               __half* __restrict__ mhi,
                               __half* __restrict__ mlo)
{
    int g = blockIdx.x;
    const float* base = nodes + (long)g * NNODE * HD;
    __shared__ float sdots[10];
    __shared__ float salpha[NNODE];

    int tid  = threadIdx.x;
    int warp = tid >> 5, lane = tid & 31;

    float partial = 0.f;
    if (warp < 9) {
        const float* row = base + warp * HD;
        for (int d = lane; d < HD; d += 32) partial += row[d] * vb[d];
    } else {
        for (int d = lane; d < HD; d += 32) partial += base[d] * va[d];
    }
#pragma unroll
    for (int off = 16; off; off >>= 1)
        partial += __shfl_down_sync(0xffffffffu, partial, off);
    if (lane == 0) sdots[warp] = partial;
    __syncthreads();

    if (tid == 0) {
        float es0 = sdots[9];
        float e[NNODE];
#pragma unroll
        for (int j = 0; j < NNODE; ++j) {
            bool valid;
            if (j == 0) valid = true;
            else {
                const unsigned char* mk = amask + ((long)g * NA + (j - 1)) * TA;
                valid = !(mk[0] && mk[1] && mk[2] && mk[3]);
            }
            if (valid) {
                float v = es0 + sdots[j];
                e[j] = v > 0.f ? v : 0.2f * v;
            } else e[j] = -1e9f;
        }
        float mx = e[0];
#pragma unroll
        for (int j = 1; j < NNODE; ++j) mx = fmaxf(mx, e[j]);
        float s = 0.f, ex[NNODE];
#pragma unroll
        for (int j = 0; j < NNODE; ++j) { ex[j] = expf(e[j] - mx); s += ex[j]; }
        float inv = 1.f / s;
#pragma unroll
        for (int j = 0; j < NNODE; ++j) salpha[j] = ex[j] * inv;
    }
    __syncthreads();

    for (int d4 = tid; d4 < HD / 4; d4 += blockDim.x) {
        float4 s4;
        float* ps = &s4.x;
#pragma unroll
        for (int q = 0; q < 4; ++q) {
            int d = d4 * 4 + q;
            float s = 0.f;
#pragma unroll
            for (int j = 0; j < NNODE; ++j) s += salpha[j] * base[j * HD + d];
            ps[q] = s;
        }
        u64 hq, lq;
        split4h(s4, hq, lq);
        *(u64*)(mhi + (long)g * HD + 4 * d4) = hq;
        *(u64*)(mlo + (long)g * HD + 4 * d4) = lq;
    }
}

// ---------------- launch ------------------------------------------------------
extern "C" void kernel_launch(void* const* d_in, const int* in_sizes, int n_in,
                              void* d_out, int out_size)
{
    const int*   ent_tok  = (const int*)  d_in[0];
    const int*   ent_len  = (const int*)  d_in[1];
    const int*   at_tok   = (const int*)  d_in[3];
    const int*   at_len   = (const int*)  d_in[4];
    const unsigned char* at_mask = (const unsigned char*)d_in[5];
    const float* emb      = (const float*)d_in[6];
    const float* Wih_ent  = (const float*)d_in[7];
    const float* Whh_ent  = (const float*)d_in[8];
    const float* bih_ent  = (const float*)d_in[9];
    const float* bhh_ent  = (const float*)d_in[10];
    const float* Wih_attr = (const float*)d_in[11];
    const float* Whh_attr = (const float*)d_in[12];
    const float* bih_attr = (const float*)d_in[13];
    const float* bhh_attr = (const float*)d_in[14];
    const float* Wfc      = (const float*)d_in[15];
    const float* bfc      = (const float*)d_in[16];
    const float* Wg       = (const float*)d_in[17];
    const float* a_src    = (const float*)d_in[18];
    const float* a_dst    = (const float*)d_in[19];
    float* out = (float*)d_out;

    static cudaStream_t s2 = nullptr;
    static cudaEvent_t evF = nullptr, evJ = nullptr;
    if (!s2) {
        cudaStreamCreateWithFlags(&s2, cudaStreamNonBlocking);
        cudaEventCreateWithFlags(&evF, cudaEventDisableTiming);
        cudaEventCreateWithFlags(&evJ, cudaEventDisableTiming);
    }

    float *xp_ent, *xp_attr, *ghE, *ghA, *h_ent, *h_attr, *nodes, *va, *vb;
    int *ctr, *offE, *permE, *mcntE, *offA, *permA, *mcntA;
    int *gtokE, *orowE, *gtokA, *orowA;
    __half *embH, *embL, *wiheH, *whheH, *wihaH, *whhaH, *wfcH, *wgH;
    __half *heH, *heL, *haH, *haL, *mixH, *mixL;

    cudaGetSymbolAddress((void**)&xp_ent,  g_xp_ent);
    cudaGetSymbolAddress((void**)&xp_attr, g_xp_attr);
    cudaGetSymbolAddress((void**)&ghE,     g_gh_ent);
    cudaGetSymbolAddress((void**)&ghA,     g_gh_attr);
    cudaGetSymbolAddress((void**)&h_ent,   g_h_ent);
    cudaGetSymbolAddress((void**)&h_attr,  g_h_attr);
    cudaGetSymbolAddress((void**)&nodes,   g_nodes);
    cudaGetSymbolAddress((void**)&va,      g_va);
    cudaGetSymbolAddress((void**)&vb,      g_vb);
    cudaGetSymbolAddress((void**)&ctr,   g_ctr);
    cudaGetSymbolAddress((void**)&offE,  g_off_ent);
    cudaGetSymbolAddress((void**)&permE, g_perm_ent);
    cudaGetSymbolAddress((void**)&mcntE, g_mcnt_ent);
    cudaGetSymbolAddress((void**)&offA,  g_off_attr);
    cudaGetSymbolAddress((void**)&permA, g_perm_attr);
    cudaGetSymbolAddress((void**)&mcntA, g_mcnt_attr);
    cudaGetSymbolAddress((void**)&gtokE, g_gtok_ent);
    cudaGetSymbolAddress((void**)&orowE, g_orow_ent);
    cudaGetSymbolAddress((void**)&gtokA, g_gtok_attr);
    cudaGetSymbolAddress((void**)&orowA, g_orow_attr);
    cudaGetSymbolAddress((void**)&embH,  g_emb_hi);
    cudaGetSymbolAddress((void**)&embL,  g_emb_lo);
    cudaGetSymbolAddress((void**)&wiheH, g_wihe_hi);
    cudaGetSymbolAddress((void**)&whheH, g_whhe_hi);
    cudaGetSymbolAddress((void**)&wihaH, g_wiha_hi);
    cudaGetSymbolAddress((void**)&whhaH, g_whha_hi);
    cudaGetSymbolAddress((void**)&wfcH,  g_wfc_hi);
    cudaGetSymbolAddress((void**)&wgH,   g_wg_hi);
    cudaGetSymbolAddress((void**)&heH,   g_he_hi);
    cudaGetSymbolAddress((void**)&heL,   g_he_lo);
    cudaGetSymbolAddress((void**)&haH,   g_ha_hi);
    cudaGetSymbolAddress((void**)&haL,   g_ha_lo);
    cudaGetSymbolAddress((void**)&mixH,  g_mix_hi);
    cudaGetSymbolAddress((void**)&mixL,  g_mix_lo);

    int* cntE = ctr + 0;
    int* cntA = ctr + 10;
    int* pcE  = ctr + 20;
    int* pcA  = ctr + 21;

    cudaFuncSetAttribute(tgemm, cudaFuncAttributeMaxDynamicSharedMemorySize, TG_SMEM);

    cudaMemsetAsync(ctr, 0, 32 * sizeof(int));

    // operand conversions
    const int q3 = KP3 / 4;
    split_rows<<<(V * q3 + 255) / 256, 256>>>(emb, embH, embL, V, WD, KP3);
    cvt_w4<<<dim3((G3 * q3 + 255) / 256, 4), 256>>>(
        Wih_ent, Whh_ent, Wih_attr, Whh_attr, wiheH, whheH, wihaH, whhaH);
    cvt_rows_hi<<<(HD * q3 + 255) / 256, 256>>>(Wfc, wfcH, HD, WD, KP3);
    cvt_rows_hi<<<(HD * (HD / 4) + 255) / 256, 256>>>(Wg, wgH, HD, HD, HD);

    // fused preprocessing
    hist2<<<(NATT + 255) / 256, 256>>>(ent_len, at_len, cntE, cntA);
    offsets2<<<1, 32>>>(cntE, offE, mcntE, cntA, offA, mcntA);
    scatter2<<<(NATT + 255) / 256, 256>>>(ent_len, at_len, offE, permE, offA, permA);
    pairs2<<<(NATT * TA + 255) / 256, 256>>>(ent_tok, ent_len, pcE, gtokE, orowE,
                                             at_tok, at_len, pcA, gtokA, orowA);

    wgt_vec_kernel<<<(HD + 255) / 256, 256>>>(Wg, a_src, a_dst, va, vb);

    const int nt900  = (G3 + TN - 1) / TN;   // 8
    const int nt1024 = HD / TN;              // 8

    // xp_ent on main, then fork entity chain onto s2
    tgemm<<<dim3(NG * TE / TM, nt900), 256, TG_SMEM>>>(
        embH, embL, gtokE, wiheH, bih_ent, xp_ent,
        NG * TE, G3, WD, KP3, 0, 0, pcE, orowE);

    cudaEventRecord(evF, 0);
    cudaStreamWaitEvent(s2, evF, 0);

    // ---- entity chain (stream s2) ----
    gru_gate4<<<(NG * 75 + 255) / 256, 256, 0, s2>>>(
        xp_ent, nullptr, bhh_ent, h_ent, heH, heL, permE, mcntE + 0, 0, TE);
    for (int t = 1; t < TE; ++t) {
        tgemm<<<dim3(NG / TM, nt900), 256, TG_SMEM, s2>>>(
            heH, heL, permE, whheH, bhh_ent, ghE,
            NG, G3, WD, KP3, 0, 0, mcntE + t, nullptr);
        gru_gate4<<<(NG * 75 + 255) / 256, 256, 0, s2>>>(
            xp_ent, ghE, nullptr, h_ent, heH, heL, permE, mcntE + t, t, TE);
    }
    tgemm<<<dim3(NG / TM, nt1024), 256, TG_SMEM, s2>>>(
        heH, heL, nullptr, wfcH, bfc, nodes,
        NG, HD, WD, KP3, 1, 1, nullptr, nullptr);
    cudaEventRecord(evJ, s2);

    // ---- attribute chain (main stream, concurrent with s2) ----
    tgemm<<<dim3(NATT * TA / TM, nt900), 256, TG_SMEM>>>(
        embH, embL, gtokA, wihaH, bih_attr, xp_attr,
        NATT * TA, G3, WD, KP3, 0, 0, pcA, orowA);
    gru_gate4<<<(NATT * 75 + 255) / 256, 256>>>(
        xp_attr, nullptr, bhh_attr, h_attr, haH, haL, permA, mcntA + 0, 0, TA);
    for (int t = 1; t < TA; ++t) {
        tgemm<<<dim3(NATT / TM, nt900), 256, TG_SMEM>>>(
            haH, haL, permA, whhaH, bhh_attr, ghA,
            NATT, G3, WD, KP3, 0, 0, mcntA + t, nullptr);
        gru_gate4<<<(NATT * 75 + 255) / 256, 256>>>(
            xp_attr, ghA, nullptr, h_attr, haH, haL, permA, mcntA + t, t, TA);
    }
    tgemm<<<dim3(NATT / TM, nt1024), 256, TG_SMEM>>>(
        haH, haL, nullptr, wfcH, bfc, nodes,
        NATT, HD, WD, KP3, 1, 2, nullptr, nullptr);

    // join entity chain
    cudaStreamWaitEvent(0, evJ, 0);

    // GAT: dots + alpha + mix (fp16 hi/lo out)
    gat_mix_kernel<<<NG, 320>>>(nodes, va, vb, at_mask, mixH, mixL);

    // out = elu(mix @ Wg^T)
    tgemm<<<dim3(NG / TM, nt1024), 256, TG_SMEM>>>(
        mixH, mixL, nullptr, wgH, nullptr, out,
        NG, HD, HD, HD, 2, 0, nullptr, nullptr);
}

// round 11
// speedup vs baseline: 7.9265x; 1.6081x over previous
#include <cuda_runtime.h>
#include <cuda_fp16.h>
#include <math.h>

// Problem constants
#define BS   128
#define NE   32
#define NA   8
#define TE   8
#define TA   4
#define WD   300
#define HD   1024
#define G3   900          // 3*WD
#define NG   (BS*NE)      // 4096
#define NATT (NG*NA)      // 32768
#define NNODE 9
#define V    30522
#define KP3  304          // WD padded to multiple of 8

typedef unsigned long long u64;
typedef unsigned int u32;

// ---------------- scratch ----------------------------------------------------
__device__ float g_xp_ent [NG   * TE * G3];
__device__ float g_xp_attr[NATT * TA * G3];
__device__ float g_gh_ent [NG   * G3];
__device__ float g_gh_attr[NATT * G3];
__device__ float g_h_ent  [NG   * WD];
__device__ float g_h_attr [NATT * WD];
__device__ float g_nodes  [NG * NNODE * HD];
__device__ float g_va     [HD];
__device__ float g_vb     [HD];
// fp16 operand buffers (hi only — single-pass GEMM)
__device__ __half g_emb_hi[V * KP3];
__device__ __half g_wihe_hi[G3 * KP3];
__device__ __half g_whhe_hi[G3 * KP3];
__device__ __half g_wiha_hi[G3 * KP3];
__device__ __half g_whha_hi[G3 * KP3];
__device__ __half g_wfc_hi[HD * KP3];
__device__ __half g_wg_hi[HD * HD];
__device__ __half g_he_hi[NG * KP3];
__device__ __half g_ha_hi[NATT * KP3];
__device__ __half g_mix_hi[NG * HD];
// counters: [0..TE] cntE, [10..10+TA] cntA, [20] pcE, [21] pcA
__device__ int g_ctr[32];
__device__ int g_off_ent [TE + 1];
__device__ int g_perm_ent[NG];
__device__ int g_mcnt_ent[TE];
__device__ int g_off_attr [TA + 1];
__device__ int g_perm_attr[NATT];
__device__ int g_mcnt_attr[TA];
__device__ int g_gtok_ent[NG * TE];
__device__ int g_orow_ent[NG * TE];
__device__ int g_gtok_attr[NATT * TA];
__device__ int g_orow_attr[NATT * TA];

// ---------------- helpers ------------------------------------------------------
__device__ __forceinline__ u32 smem_u32(const void* p) {
    u32 a;
    asm("{ .reg .u64 t; cvta.to.shared.u64 t, %1; cvt.u32.u64 %0, t; }"
        : "=r"(a) : "l"(p));
    return a;
}

#define LDSM_X4(r, addr) \
    asm volatile("ldmatrix.sync.aligned.m8n8.x4.shared.b16 {%0,%1,%2,%3}, [%4];" \
        : "=r"((r)[0]), "=r"((r)[1]), "=r"((r)[2]), "=r"((r)[3]) : "r"(addr))

#define LDSM_X2(r0, r1, addr) \
    asm volatile("ldmatrix.sync.aligned.m8n8.x2.shared.b16 {%0,%1}, [%2];" \
        : "=r"(r0), "=r"(r1) : "r"(addr))

#define MMA16816(c, a, b0, b1) \
    asm volatile("mma.sync.aligned.m16n8k16.row.col.f32.f16.f16.f32 " \
        "{%0,%1,%2,%3}, {%4,%5,%6,%7}, {%8,%9}, {%0,%1,%2,%3};" \
        : "+f"((c)[0]), "+f"((c)[1]), "+f"((c)[2]), "+f"((c)[3]) \
        : "r"((a)[0]), "r"((a)[1]), "r"((a)[2]), "r"((a)[3]), "r"(b0), "r"(b1))

#define CP16(dst, src, sz) \
    asm volatile("cp.async.cg.shared.global [%0], [%1], 16, %2;" \
        :: "r"(dst), "l"(src), "r"(sz) : "memory")
#define CPCOMMIT() asm volatile("cp.async.commit_group;" ::: "memory")
#define CPWAIT1()  asm volatile("cp.async.wait_group 1;"  ::: "memory")
#define CPWAIT0()  asm volatile("cp.async.wait_group 0;"  ::: "memory")

#define SWZ(o) ((o) ^ (((o) >> 3) & 0x70u))

__device__ __forceinline__ u64 cvt4h(float4 v) {
    unsigned short h[4];
    const float* pv = &v.x;
#pragma unroll
    for (int i = 0; i < 4; ++i) h[i] = __half_as_ushort(__float2half(pv[i]));
    return (u64)h[0] | ((u64)h[1] << 16) | ((u64)h[2] << 32) | ((u64)h[3] << 48);
}

// ---------------- fp32 -> fp16 conversion -------------------------------------
__global__ void cvt_rows_hi(const float* __restrict__ x,
                            __half* __restrict__ hi,
                            int rows, int K, int KP)
{
    int q = KP / 4;
    int idx = blockIdx.x * blockDim.x + threadIdx.x;
    int r = idx / q;
    if (r >= rows) return;
    int i4 = (idx - r * q) * 4;
    float4 v = make_float4(0.f, 0.f, 0.f, 0.f);
    if (i4 + 4 <= K) v = *(const float4*)(x + (long)r * K + i4);
    *(u64*)(hi + (long)r * KP + i4) = cvt4h(v);
}

// fused hi-only conversion of the 4 GRU weight matrices
__global__ void cvt_w4(const float* s0, const float* s1, const float* s2, const float* s3,
                       __half* h0, __half* h1, __half* h2, __half* h3)
{
    const float* src; __half* hi;
    switch (blockIdx.y) {
        case 0: src = s0; hi = h0; break;
        case 1: src = s1; hi = h1; break;
        case 2: src = s2; hi = h2; break;
        default: src = s3; hi = h3; break;
    }
    int q = KP3 / 4;
    int idx = blockIdx.x * blockDim.x + threadIdx.x;
    int r = idx / q;
    if (r >= G3) return;
    int i4 = (idx - r * q) * 4;
    float4 v = make_float4(0.f, 0.f, 0.f, 0.f);
    if (i4 + 4 <= WD) v = *(const float4*)(src + (long)r * WD + i4);
    *(u64*)(hi + (long)r * KP3 + i4) = cvt4h(v);
}

// ---------------- tensor GEMM (fp16 single-pass, cp.async pipeline) ----------
#define TM 128
#define TN 128
#define CK 64
#define OFF_AHI 0u
#define OFF_BHI 16384u
#define STAGE   32768u
#define TG_SMEM 65536u

__global__ void __launch_bounds__(256, 2)
tgemm(const __half* __restrict__ Ahi,
      const int* __restrict__ gather,
      const __half* __restrict__ Bhi,
      const float* __restrict__ bias,
      float* __restrict__ C, int M, int N, int K, int KP, int act, int outMap,
      const int* __restrict__ mlimit, const int* __restrict__ orow)
{
    extern __shared__ char smem[];
    int Mdyn = M;
    if (mlimit) { Mdyn = *mlimit; if (Mdyn > M) Mdyn = M; }
    const int m0 = blockIdx.x * TM;
    const int n0 = blockIdx.y * TN;
    if (m0 >= Mdyn) return;

    const u32 sbase = smem_u32(smem);
    const int tid  = threadIdx.x;
    const int wid  = tid >> 5;
    const int lane = tid & 31;
    const int wm   = wid >> 1;
    const int wn   = wid & 1;

    const int k8   = (tid & 7) * 8;
    const int rloc = tid >> 3;
    long roA[4], roB[4];
    bool vA[4], vB[4];
    u32  swR[4];
#pragma unroll
    for (int it = 0; it < 4; ++it) {
        int r = rloc + 32 * it;
        int m = m0 + r;
        vA[it] = (m < Mdyn);
        int src = vA[it] ? (gather ? gather[m] : m) : 0;
        roA[it] = (long)src * KP;
        int n = n0 + r;
        vB[it] = (n < N);
        roB[it] = (long)(vB[it] ? n : 0) * KP;
        swR[it] = SWZ((u32)(r * 128 + k8 * 2));
    }

#define FILL_CHUNK(cc, st) do { \
    int gk_ = (cc) * CK + k8; \
    u32 sb_ = sbase + (u32)(st) * STAGE; \
    bool kok_ = (gk_ < KP); \
    _Pragma("unroll") \
    for (int it = 0; it < 4; ++it) { \
        bool aok = vA[it] && kok_; u32 asz = aok ? 16u : 0u; \
        const __half* pa1 = aok ? (Ahi + roA[it] + gk_) : Ahi; \
        CP16(sb_ + OFF_AHI + swR[it], pa1, asz); \
        bool bok = vB[it] && kok_; u32 bsz = bok ? 16u : 0u; \
        const __half* pb1 = bok ? (Bhi + roB[it] + gk_) : Bhi; \
        CP16(sb_ + OFF_BHI + swR[it], pb1, bsz); \
    } \
    CPCOMMIT(); \
} while (0)

    const u32 rbA0 = (u32)((wm * 32 + (lane & 15)) * 128);
    const u32 rbA1 = rbA0 + 16u * 128u;
    const u32 rbB  = (u32)((wn * 64 + (lane & 7)) * 128);
    const u32 xorq = (u32)(lane & 7);
    const u32 qAh  = (u32)(lane >> 4);
    const u32 qBh  = (u32)((lane >> 3) & 1);

    float acc[2][8][4];
#pragma unroll
    for (int i = 0; i < 2; ++i)
#pragma unroll
        for (int j = 0; j < 8; ++j)
#pragma unroll
            for (int q = 0; q < 4; ++q) acc[i][j][q] = 0.f;

    const int nc = (K + CK - 1) / CK;

    FILL_CHUNK(0, 0);
    for (int c = 0; c < nc; ++c) {
        if (c + 1 < nc) { FILL_CHUNK(c + 1, (c + 1) & 1); CPWAIT1(); }
        else            { CPWAIT0(); }
        __syncthreads();

        const u32 stb = sbase + (u32)(c & 1) * STAGE;
        const u32 ab = stb + OFF_AHI;
        const u32 bb = stb + OFF_BHI;
#pragma unroll
        for (int ks = 0; ks < 4; ++ks) {
            u32 qa = (((u32)(2 * ks) + qAh) ^ xorq) * 16u;
            u32 a0[4], a1[4];
            LDSM_X4(a0, ab + rbA0 + qa);
            LDSM_X4(a1, ab + rbA1 + qa);
            u32 qb = (((u32)(2 * ks) + qBh) ^ xorq) * 16u;
#pragma unroll
            for (int nb = 0; nb < 8; ++nb) {
                u32 b0, b1;
                LDSM_X2(b0, b1, bb + rbB + (u32)nb * 1024u + qb);
                MMA16816(acc[0][nb], a0, b0, b1);
                MMA16816(acc[1][nb], a1, b0, b1);
            }
        }
        __syncthreads();
    }
#undef FILL_CHUNK

#pragma unroll
    for (int mi = 0; mi < 2; ++mi) {
#pragma unroll
        for (int half = 0; half < 2; ++half) {
            int m = m0 + wm * 32 + mi * 16 + (lane >> 2) + half * 8;
            if (m >= Mdyn) continue;
            long base;
            if (orow)             base = (long)orow[m] * N;
            else if (outMap == 0) base = (long)m * N;
            else if (outMap == 1) base = (long)m * NNODE * HD;
            else                  base = ((long)(m >> 3) * NNODE + 1 + (m & 7)) * (long)HD;
#pragma unroll
            for (int nb = 0; nb < 8; ++nb) {
                int n = n0 + wn * 64 + nb * 8 + (lane & 3) * 2;
                if (n >= N) continue;
                float x0 = acc[mi][nb][half * 2 + 0];
                float x1 = acc[mi][nb][half * 2 + 1];
                if (bias) { x0 += bias[n]; x1 += bias[n + 1]; }
                if (act == 1)      { x0 = fmaxf(x0, 0.f); x1 = fmaxf(x1, 0.f); }
                else if (act == 2) { x0 = x0 > 0.f ? x0 : expm1f(x0);
                                     x1 = x1 > 0.f ? x1 : expm1f(x1); }
                *(float2*)(C + base + n) = make_float2(x0, x1);
            }
        }
    }
}

// ---------------- fused preprocessing (ent + attr) ---------------------------
__device__ __forceinline__ int clampL(int L, int T) {
    return L < 1 ? 1 : (L > T ? T : L);
}
__global__ void hist2(const int* __restrict__ lenE, const int* __restrict__ lenA,
                      int* __restrict__ cntE, int* __restrict__ cntA)
{
    int i = blockIdx.x * blockDim.x + threadIdx.x;
    if (i < NG)   atomicAdd(&cntE[clampL(lenE[i], TE)], 1);
    if (i < NATT) atomicAdd(&cntA[clampL(lenA[i], TA)], 1);
}
__global__ void offsets2(const int* __restrict__ cntE, int* __restrict__ offE,
                         int* __restrict__ mcntE,
                         const int* __restrict__ cntA, int* __restrict__ offA,
                         int* __restrict__ mcntA)
{
    if (threadIdx.x == 0) {
        int run = 0;
        for (int L = TE; L >= 1; --L) { offE[L] = run; run += cntE[L]; }
        for (int t = 0; t < TE; ++t) {
            int s = 0;
            for (int L = t + 1; L <= TE; ++L) s += cntE[L];
            mcntE[t] = s;
        }
    } else if (threadIdx.x == 1) {
        int run = 0;
        for (int L = TA; L >= 1; --L) { offA[L] = run; run += cntA[L]; }
        for (int t = 0; t < TA; ++t) {
            int s = 0;
            for (int L = t + 1; L <= TA; ++L) s += cntA[L];
            mcntA[t] = s;
        }
    }
}
__global__ void scatter2(const int* __restrict__ lenE, const int* __restrict__ lenA,
                         int* __restrict__ offE, int* __restrict__ permE,
                         int* __restrict__ offA, int* __restrict__ permA)
{
    int i = blockIdx.x * blockDim.x + threadIdx.x;
    if (i < NG) {
        int pos = atomicAdd(&offE[clampL(lenE[i], TE)], 1);
        permE[pos] = i;
    }
    if (i < NATT) {
        int pos = atomicAdd(&offA[clampL(lenA[i], TA)], 1);
        permA[pos] = i;
    }
}
__global__ void pairs2(const int* __restrict__ tokE, const int* __restrict__ lenE,
                       int* __restrict__ pcE, int* __restrict__ gtokE, int* __restrict__ orowE,
                       const int* __restrict__ tokA, const int* __restrict__ lenA,
                       int* __restrict__ pcA, int* __restrict__ gtokA, int* __restrict__ orowA)
{
    int p = blockIdx.x * blockDim.x + threadIdx.x;
    if (p < NG * TE) {
        int i = p / TE, t = p - i * TE;
        if (t < clampL(lenE[i], TE)) {
            int pos = atomicAdd(pcE, 1);
            gtokE[pos] = tokE[p];
            orowE[pos] = p;
        }
    }
    if (p < NATT * TA) {
        int i = p / TA, t = p - i * TA;
        if (t < clampL(lenA[i], TA)) {
            int pos = atomicAdd(pcA, 1);
            gtokA[pos] = tokA[p];
            orowA[pos] = p;
        }
    }
}

// ---------------- GRU gate update (t0 path uses gh = bhh, h = 0) -------------
__global__ void gru_gate4(const float* __restrict__ xp,
                          const float* __restrict__ gh,
                          const float* __restrict__ bhh_t0,   // non-null => t==0
                          float* __restrict__ h,
                          __half* __restrict__ hhi,
                          const int* __restrict__ perm,
                          const int* __restrict__ mcnt,
                          int t, int T)
{
    const int Q = WD / 4;   // 75
    int idx = blockIdx.x * blockDim.x + threadIdx.x;
    int i = idx / Q;
    if (i >= *mcnt) return;
    int d = idx - i * Q;
    int orig = perm[i];
    const float4* x = (const float4*)(xp + ((long)orig * T + t) * G3);
    float4* hp = (float4*)(h + (long)orig * WD);

    float4 xr = x[d], xz = x[Q + d], xn = x[2 * Q + d];
    float4 gr, gz, gn, hv;
    if (bhh_t0) {
        const float4* b = (const float4*)bhh_t0;
        gr = b[d]; gz = b[Q + d]; gn = b[2 * Q + d];
        hv = make_float4(0.f, 0.f, 0.f, 0.f);
    } else {
        const float4* g = (const float4*)(gh + (long)i * G3);
        gr = g[d]; gz = g[Q + d]; gn = g[2 * Q + d];
        hv = hp[d];
    }

    float4 res;
    const float* pxr = &xr.x; const float* pxz = &xz.x; const float* pxn = &xn.x;
    const float* pgr = &gr.x; const float* pgz = &gz.x; const float* pgn = &gn.x;
    const float* phv = &hv.x; float* pres = &res.x;
#pragma unroll
    for (int c = 0; c < 4; ++c) {
        float r = 1.f / (1.f + expf(-(pxr[c] + pgr[c])));
        float z = 1.f / (1.f + expf(-(pxz[c] + pgz[c])));
        float n = tanhf(pxn[c] + r * pgn[c]);
        pres[c] = (1.f - z) * n + z * phv[c];
    }
    hp[d] = res;
    *(u64*)(hhi + (long)orig * KP3 + 4 * d) = cvt4h(res);
}

// ---------------- va/vb = Wg^T a_src / Wg^T a_dst ----------------------------
__global__ void wgt_vec_kernel(const float* __restrict__ Wg,
                               const float* __restrict__ a_src,
                               const float* __restrict__ a_dst,
                               float* __restrict__ va, float* __restrict__ vb)
{
    int k = blockIdx.x * blockDim.x + threadIdx.x;
    if (k >= HD) return;
    float sa = 0.f, sb = 0.f;
    for (int d = 0; d < HD; ++d) {
        float w = Wg[(long)d * HD + k];
        sa += w * a_src[d];
        sb += w * a_dst[d];
    }
    va[k] = sa;
    vb[k] = sb;
}

// ---------------- GAT dots + softmax + node mix (writes fp16 hi) -------------
__global__ void gat_mix_kernel(const float* __restrict__ nodes,
                               const float* __restrict__ va,
                               const float* __restrict__ vb,
                               const unsigned char* __restrict__ amask,
                               __half* __restrict__ mhi)
{
    int g = blockIdx.x;
    const float* base = nodes + (long)g * NNODE * HD;
    __shared__ float sdots[10];
    __shared__ float salpha[NNODE];

    int tid  = threadIdx.x;
    int warp = tid >> 5, lane = tid & 31;

    float partial = 0.f;
    if (warp < 9) {
        const float* row = base + warp * HD;
        for (int d = lane; d < HD; d += 32) partial += row[d] * vb[d];
    } else {
        for (int d = lane; d < HD; d += 32) partial += base[d] * va[d];
    }
#pragma unroll
    for (int off = 16; off; off >>= 1)
        partial += __shfl_down_sync(0xffffffffu, partial, off);
    if (lane == 0) sdots[warp] = partial;
    __syncthreads();

    if (tid == 0) {
        float es0 = sdots[9];
        float e[NNODE];
#pragma unroll
        for (int j = 0; j < NNODE; ++j) {
            bool valid;
            if (j == 0) valid = true;
            else {
                const unsigned char* mk = amask + ((long)g * NA + (j - 1)) * TA;
                valid = !(mk[0] && mk[1] && mk[2] && mk[3]);
            }
            if (valid) {
                float v = es0 + sdots[j];
                e[j] = v > 0.f ? v : 0.2f * v;
            } else e[j] = -1e9f;
        }
        float mx = e[0];
#pragma unroll
        for (int j = 1; j < NNODE; ++j) mx = fmaxf(mx, e[j]);
        float s = 0.f, ex[NNODE];
#pragma unroll
        for (int j = 0; j < NNODE; ++j) { ex[j] = expf(e[j] - mx); s += ex[j]; }
        float inv = 1.f / s;
#pragma unroll
        for (int j = 0; j < NNODE; ++j) salpha[j] = ex[j] * inv;
    }
    __syncthreads();

    for (int d4 = tid; d4 < HD / 4; d4 += blockDim.x) {
        float4 s4;
        float* ps = &s4.x;
#pragma unroll
        for (int q = 0; q < 4; ++q) {
            int d = d4 * 4 + q;
            float s = 0.f;
#pragma unroll
            for (int j = 0; j < NNODE; ++j) s += salpha[j] * base[j * HD + d];
            ps[q] = s;
        }
        *(u64*)(mhi + (long)g * HD + 4 * d4) = cvt4h(s4);
    }
}

// ---------------- launch ------------------------------------------------------
extern "C" void kernel_launch(void* const* d_in, const int* in_sizes, int n_in,
                              void* d_out, int out_size)
{
    const int*   ent_tok  = (const int*)  d_in[0];
    const int*   ent_len  = (const int*)  d_in[1];
    const int*   at_tok   = (const int*)  d_in[3];
    const int*   at_len   = (const int*)  d_in[4];
    const unsigned char* at_mask = (const unsigned char*)d_in[5];
    const float* emb      = (const float*)d_in[6];
    const float* Wih_ent  = (const float*)d_in[7];
    const float* Whh_ent  = (const float*)d_in[8];
    const float* bih_ent  = (const float*)d_in[9];
    const float* bhh_ent  = (const float*)d_in[10];
    const float* Wih_attr = (const float*)d_in[11];
    const float* Whh_attr = (const float*)d_in[12];
    const float* bih_attr = (const float*)d_in[13];
    const float* bhh_attr = (const float*)d_in[14];
    const float* Wfc      = (const float*)d_in[15];
    const float* bfc      = (const float*)d_in[16];
    const float* Wg       = (const float*)d_in[17];
    const float* a_src    = (const float*)d_in[18];
    const float* a_dst    = (const float*)d_in[19];
    float* out = (float*)d_out;

    static cudaStream_t s2 = nullptr;
    static cudaEvent_t evF = nullptr, evJ = nullptr;
    if (!s2) {
        cudaStreamCreateWithFlags(&s2, cudaStreamNonBlocking);
        cudaEventCreateWithFlags(&evF, cudaEventDisableTiming);
        cudaEventCreateWithFlags(&evJ, cudaEventDisableTiming);
    }

    float *xp_ent, *xp_attr, *ghE, *ghA, *h_ent, *h_attr, *nodes, *va, *vb;
    int *ctr, *offE, *permE, *mcntE, *offA, *permA, *mcntA;
    int *gtokE, *orowE, *gtokA, *orowA;
    __half *embH, *wiheH, *whheH, *wihaH, *whhaH, *wfcH, *wgH;
    __half *heH, *haH, *mixH;

    cudaGetSymbolAddress((void**)&xp_ent,  g_xp_ent);
    cudaGetSymbolAddress((void**)&xp_attr, g_xp_attr);
    cudaGetSymbolAddress((void**)&ghE,     g_gh_ent);
    cudaGetSymbolAddress((void**)&ghA,     g_gh_attr);
    cudaGetSymbolAddress((void**)&h_ent,   g_h_ent);
    cudaGetSymbolAddress((void**)&h_attr,  g_h_attr);
    cudaGetSymbolAddress((void**)&nodes,   g_nodes);
    cudaGetSymbolAddress((void**)&va,      g_va);
    cudaGetSymbolAddress((void**)&vb,      g_vb);
    cudaGetSymbolAddress((void**)&ctr,   g_ctr);
    cudaGetSymbolAddress((void**)&offE,  g_off_ent);
    cudaGetSymbolAddress((void**)&permE, g_perm_ent);
    cudaGetSymbolAddress((void**)&mcntE, g_mcnt_ent);
    cudaGetSymbolAddress((void**)&offA,  g_off_attr);
    cudaGetSymbolAddress((void**)&permA, g_perm_attr);
    cudaGetSymbolAddress((void**)&mcntA, g_mcnt_attr);
    cudaGetSymbolAddress((void**)&gtokE, g_gtok_ent);
    cudaGetSymbolAddress((void**)&orowE, g_orow_ent);
    cudaGetSymbolAddress((void**)&gtokA, g_gtok_attr);
    cudaGetSymbolAddress((void**)&orowA, g_orow_attr);
    cudaGetSymbolAddress((void**)&embH,  g_emb_hi);
    cudaGetSymbolAddress((void**)&wiheH, g_wihe_hi);
    cudaGetSymbolAddress((void**)&whheH, g_whhe_hi);
    cudaGetSymbolAddress((void**)&wihaH, g_wiha_hi);
    cudaGetSymbolAddress((void**)&whhaH, g_whha_hi);
    cudaGetSymbolAddress((void**)&wfcH,  g_wfc_hi);
    cudaGetSymbolAddress((void**)&wgH,   g_wg_hi);
    cudaGetSymbolAddress((void**)&heH,   g_he_hi);
    cudaGetSymbolAddress((void**)&haH,   g_ha_hi);
    cudaGetSymbolAddress((void**)&mixH,  g_mix_hi);

    int* cntE = ctr + 0;
    int* cntA = ctr + 10;
    int* pcE  = ctr + 20;
    int* pcA  = ctr + 21;

    cudaFuncSetAttribute(tgemm, cudaFuncAttributeMaxDynamicSharedMemorySize, TG_SMEM);

    cudaMemsetAsync(ctr, 0, 32 * sizeof(int));

    // operand conversions
    const int q3 = KP3 / 4;
    cvt_rows_hi<<<(V * q3 + 255) / 256, 256>>>(emb, embH, V, WD, KP3);
    cvt_w4<<<dim3((G3 * q3 + 255) / 256, 4), 256>>>(
        Wih_ent, Whh_ent, Wih_attr, Whh_attr, wiheH, whheH, wihaH, whhaH);
    cvt_rows_hi<<<(HD * q3 + 255) / 256, 256>>>(Wfc, wfcH, HD, WD, KP3);
    cvt_rows_hi<<<(HD * (HD / 4) + 255) / 256, 256>>>(Wg, wgH, HD, HD, HD);

    // fused preprocessing
    hist2<<<(NATT + 255) / 256, 256>>>(ent_len, at_len, cntE, cntA);
    offsets2<<<1, 32>>>(cntE, offE, mcntE, cntA, offA, mcntA);
    scatter2<<<(NATT + 255) / 256, 256>>>(ent_len, at_len, offE, permE, offA, permA);
    pairs2<<<(NATT * TA + 255) / 256, 256>>>(ent_tok, ent_len, pcE, gtokE, orowE,
                                             at_tok, at_len, pcA, gtokA, orowA);

    wgt_vec_kernel<<<(HD + 255) / 256, 256>>>(Wg, a_src, a_dst, va, vb);

    const int nt900  = (G3 + TN - 1) / TN;   // 8
    const int nt1024 = HD / TN;              // 8

    // xp_ent on main, then fork entity chain onto s2
    tgemm<<<dim3(NG * TE / TM, nt900), 256, TG_SMEM>>>(
        embH, gtokE, wiheH, bih_ent, xp_ent,
        NG * TE, G3, WD, KP3, 0, 0, pcE, orowE);

    cudaEventRecord(evF, 0);
    cudaStreamWaitEvent(s2, evF, 0);

    // ---- entity chain (stream s2) ----
    gru_gate4<<<(NG * 75 + 255) / 256, 256, 0, s2>>>(
        xp_ent, nullptr, bhh_ent, h_ent, heH, permE, mcntE + 0, 0, TE);
    for (int t = 1; t < TE; ++t) {
        tgemm<<<dim3(NG / TM, nt900), 256, TG_SMEM, s2>>>(
            heH, permE, whheH, bhh_ent, ghE,
            NG, G3, WD, KP3, 0, 0, mcntE + t, nullptr);
        gru_gate4<<<(NG * 75 + 255) / 256, 256, 0, s2>>>(
            xp_ent, ghE, nullptr, h_ent, heH, permE, mcntE + t, t, TE);
    }
    tgemm<<<dim3(NG / TM, nt1024), 256, TG_SMEM, s2>>>(
        heH, nullptr, wfcH, bfc, nodes,
        NG, HD, WD, KP3, 1, 1, nullptr, nullptr);
    cudaEventRecord(evJ, s2);

    // ---- attribute chain (main stream, concurrent with s2) ----
    tgemm<<<dim3(NATT * TA / TM, nt900), 256, TG_SMEM>>>(
        embH, gtokA, wihaH, bih_attr, xp_attr,
        NATT * TA, G3, WD, KP3, 0, 0, pcA, orowA);
    gru_gate4<<<(NATT * 75 + 255) / 256, 256>>>(
        xp_attr, nullptr, bhh_attr, h_attr, haH, permA, mcntA + 0, 0, TA);
    for (int t = 1; t < TA; ++t) {
        tgemm<<<dim3(NATT / TM, nt900), 256, TG_SMEM>>>(
            haH, permA, whhaH, bhh_attr, ghA,
            NATT, G3, WD, KP3, 0, 0, mcntA + t, nullptr);
        gru_gate4<<<(NATT * 75 + 255) / 256, 256>>>(
            xp_attr, ghA, nullptr, h_attr, haH, permA, mcntA + t, t, TA);
    }
    tgemm<<<dim3(NATT / TM, nt1024), 256, TG_SMEM>>>(
        haH, nullptr, wfcH, bfc, nodes,
        NATT, HD, WD, KP3, 1, 2, nullptr, nullptr);

    // join entity chain
    cudaStreamWaitEvent(0, evJ, 0);

    // GAT: dots + alpha + mix (fp16 out)
    gat_mix_kernel<<<NG, 320>>>(nodes, va, vb, at_mask, mixH);

    // out = elu(mix @ Wg^T)
    tgemm<<<dim3(NG / TM, nt1024), 256, TG_SMEM>>>(
        mixH, nullptr, wgH, nullptr, out,
        NG, HD, HD, HD, 2, 0, nullptr, nullptr);
}

// round 12
// speedup vs baseline: 8.7317x; 1.1016x over previous
#include <cuda_runtime.h>
#include <cuda_fp16.h>
#include <math.h>

// Problem constants
#define BS   128
#define NE   32
#define NA   8
#define TE   8
#define TA   4
#define WD   300
#define HD   1024
#define G3   900          // 3*WD
#define NG   (BS*NE)      // 4096
#define NATT (NG*NA)      // 32768
#define NNODE 9
#define V    30522
#define KP3  304          // WD padded to multiple of 8

typedef unsigned long long u64;
typedef unsigned int u32;

// ---------------- scratch ----------------------------------------------------
__device__ __half g_xp_ent [NG   * TE * G3];
__device__ __half g_xp_attr[NATT * TA * G3];
__device__ __half g_gh_ent [NG   * G3];
__device__ __half g_gh_attr[NATT * G3];
__device__ float g_h_ent  [NG   * WD];
__device__ float g_h_attr [NATT * WD];
__device__ float g_nodes  [NG * NNODE * HD];
__device__ float g_va     [HD];
__device__ float g_vb     [HD];
// fp16 operand buffers (hi only — single-pass GEMM)
__device__ __half g_emb_hi[V * KP3];
__device__ __half g_wihe_hi[G3 * KP3];
__device__ __half g_whhe_hi[G3 * KP3];
__device__ __half g_wiha_hi[G3 * KP3];
__device__ __half g_whha_hi[G3 * KP3];
__device__ __half g_wfc_hi[HD * KP3];
__device__ __half g_wg_hi[HD * HD];
__device__ __half g_he_hi[NG * KP3];
__device__ __half g_ha_hi[NATT * KP3];
__device__ __half g_mix_hi[NG * HD];
// counters: [0..TE] cntE, [10..10+TA] cntA, [20] pcE, [21] pcA, [31] zero
__device__ int g_ctr[32];
__device__ int g_off_ent [TE + 1];
__device__ int g_perm_ent[NG];
__device__ int g_mcnt_ent[TE];
__device__ int g_off_attr [TA + 1];
__device__ int g_perm_attr[NATT];
__device__ int g_mcnt_attr[TA];
__device__ int g_gtok_ent[NG * TE];
__device__ int g_orow_ent[NG * TE];
__device__ int g_gtok_attr[NATT * TA];
__device__ int g_orow_attr[NATT * TA];

// ---------------- helpers ------------------------------------------------------
__device__ __forceinline__ u32 smem_u32(const void* p) {
    u32 a;
    asm("{ .reg .u64 t; cvta.to.shared.u64 t, %1; cvt.u32.u64 %0, t; }"
        : "=r"(a) : "l"(p));
    return a;
}

#define LDSM_X4(r, addr) \
    asm volatile("ldmatrix.sync.aligned.m8n8.x4.shared.b16 {%0,%1,%2,%3}, [%4];" \
        : "=r"((r)[0]), "=r"((r)[1]), "=r"((r)[2]), "=r"((r)[3]) : "r"(addr))

#define LDSM_X2(r0, r1, addr) \
    asm volatile("ldmatrix.sync.aligned.m8n8.x2.shared.b16 {%0,%1}, [%2];" \
        : "=r"(r0), "=r"(r1) : "r"(addr))

#define MMA16816(c, a, b0, b1) \
    asm volatile("mma.sync.aligned.m16n8k16.row.col.f32.f16.f16.f32 " \
        "{%0,%1,%2,%3}, {%4,%5,%6,%7}, {%8,%9}, {%0,%1,%2,%3};" \
        : "+f"((c)[0]), "+f"((c)[1]), "+f"((c)[2]), "+f"((c)[3]) \
        : "r"((a)[0]), "r"((a)[1]), "r"((a)[2]), "r"((a)[3]), "r"(b0), "r"(b1))

#define CP16(dst, src, sz) \
    asm volatile("cp.async.cg.shared.global [%0], [%1], 16, %2;" \
        :: "r"(dst), "l"(src), "r"(sz) : "memory")
#define CPCOMMIT() asm volatile("cp.async.commit_group;" ::: "memory")
#define CPWAIT1()  asm volatile("cp.async.wait_group 1;"  ::: "memory")
#define CPWAIT0()  asm volatile("cp.async.wait_group 0;"  ::: "memory")

#define SWZ(o) ((o) ^ (((o) >> 3) & 0x70u))

__device__ __forceinline__ u64 cvt4h(float4 v) {
    unsigned short h[4];
    const float* pv = &v.x;
#pragma unroll
    for (int i = 0; i < 4; ++i) h[i] = __half_as_ushort(__float2half(pv[i]));
    return (u64)h[0] | ((u64)h[1] << 16) | ((u64)h[2] << 32) | ((u64)h[3] << 48);
}
__device__ __forceinline__ float4 ld4h(const __half* p) {
    __half2 a = *(const __half2*)p;
    __half2 b = *(const __half2*)(p + 2);
    float2 fa = __half22float2(a), fb = __half22float2(b);
    return make_float4(fa.x, fa.y, fb.x, fb.y);
}

// ---------------- fp32 -> fp16 conversion -------------------------------------
__global__ void cvt_rows_hi(const float* __restrict__ x,
                            __half* __restrict__ hi,
                            int rows, int K, int KP)
{
    int q = KP / 4;
    int idx = blockIdx.x * blockDim.x + threadIdx.x;
    int r = idx / q;
    if (r >= rows) return;
    int i4 = (idx - r * q) * 4;
    float4 v = make_float4(0.f, 0.f, 0.f, 0.f);
    if (i4 + 4 <= K) v = *(const float4*)(x + (long)r * K + i4);
    *(u64*)(hi + (long)r * KP + i4) = cvt4h(v);
}

__global__ void cvt_w4(const float* s0, const float* s1, const float* s2, const float* s3,
                       __half* h0, __half* h1, __half* h2, __half* h3)
{
    const float* src; __half* hi;
    switch (blockIdx.y) {
        case 0: src = s0; hi = h0; break;
        case 1: src = s1; hi = h1; break;
        case 2: src = s2; hi = h2; break;
        default: src = s3; hi = h3; break;
    }
    int q = KP3 / 4;
    int idx = blockIdx.x * blockDim.x + threadIdx.x;
    int r = idx / q;
    if (r >= G3) return;
    int i4 = (idx - r * q) * 4;
    float4 v = make_float4(0.f, 0.f, 0.f, 0.f);
    if (i4 + 4 <= WD) v = *(const float4*)(src + (long)r * WD + i4);
    *(u64*)(hi + (long)r * KP3 + i4) = cvt4h(v);
}

// ---------------- tensor GEMM (fp16 single-pass, cp.async pipeline) ----------
// Row range [lo,hi) via device pointers; fp32 or fp16 output.
#define TM 128
#define TN 128
#define CK 64
#define OFF_AHI 0u
#define OFF_BHI 16384u
#define STAGE   32768u
#define TG_SMEM 65536u

__global__ void __launch_bounds__(256, 2)
tgemm(const __half* __restrict__ Ahi,
      const int* __restrict__ gather,
      const __half* __restrict__ Bhi,
      const float* __restrict__ bias,
      void* __restrict__ C, int M, int N, int K, int KP, int act, int outMap,
      const int* __restrict__ mlimit, const int* __restrict__ mlo,
      const int* __restrict__ orow, int outHalf)
{
    extern __shared__ char smem[];
    int hiM = M;
    if (mlimit) { int v = *mlimit; if (v < hiM) hiM = v; }
    int loM = mlo ? *mlo : 0;
    const int m0 = blockIdx.x * TM;
    const int n0 = blockIdx.y * TN;
    if (m0 >= hiM || m0 + TM <= loM) return;

    const u32 sbase = smem_u32(smem);
    const int tid  = threadIdx.x;
    const int wid  = tid >> 5;
    const int lane = tid & 31;
    const int wm   = wid >> 1;
    const int wn   = wid & 1;

    const int k8   = (tid & 7) * 8;
    const int rloc = tid >> 3;
    long roA[4], roB[4];
    bool vA[4], vB[4];
    u32  swR[4];
#pragma unroll
    for (int it = 0; it < 4; ++it) {
        int r = rloc + 32 * it;
        int m = m0 + r;
        vA[it] = (m >= loM && m < hiM);
        int src = vA[it] ? (gather ? gather[m] : m) : 0;
        roA[it] = (long)src * KP;
        int n = n0 + r;
        vB[it] = (n < N);
        roB[it] = (long)(vB[it] ? n : 0) * KP;
        swR[it] = SWZ((u32)(r * 128 + k8 * 2));
    }

#define FILL_CHUNK(cc, st) do { \
    int gk_ = (cc) * CK + k8; \
    u32 sb_ = sbase + (u32)(st) * STAGE; \
    bool kok_ = (gk_ < KP); \
    _Pragma("unroll") \
    for (int it = 0; it < 4; ++it) { \
        bool aok = vA[it] && kok_; u32 asz = aok ? 16u : 0u; \
        const __half* pa1 = aok ? (Ahi + roA[it] + gk_) : Ahi; \
        CP16(sb_ + OFF_AHI + swR[it], pa1, asz); \
        bool bok = vB[it] && kok_; u32 bsz = bok ? 16u : 0u; \
        const __half* pb1 = bok ? (Bhi + roB[it] + gk_) : Bhi; \
        CP16(sb_ + OFF_BHI + swR[it], pb1, bsz); \
    } \
    CPCOMMIT(); \
} while (0)

    const u32 rbA0 = (u32)((wm * 32 + (lane & 15)) * 128);
    const u32 rbA1 = rbA0 + 16u * 128u;
    const u32 rbB  = (u32)((wn * 64 + (lane & 7)) * 128);
    const u32 xorq = (u32)(lane & 7);
    const u32 qAh  = (u32)(lane >> 4);
    const u32 qBh  = (u32)((lane >> 3) & 1);

    float acc[2][8][4];
#pragma unroll
    for (int i = 0; i < 2; ++i)
#pragma unroll
        for (int j = 0; j < 8; ++j)
#pragma unroll
            for (int q = 0; q < 4; ++q) acc[i][j][q] = 0.f;

    const int nc = (K + CK - 1) / CK;

    FILL_CHUNK(0, 0);
    for (int c = 0; c < nc; ++c) {
        if (c + 1 < nc) { FILL_CHUNK(c + 1, (c + 1) & 1); CPWAIT1(); }
        else            { CPWAIT0(); }
        __syncthreads();

        const u32 stb = sbase + (u32)(c & 1) * STAGE;
        const u32 ab = stb + OFF_AHI;
        const u32 bb = stb + OFF_BHI;
#pragma unroll
        for (int ks = 0; ks < 4; ++ks) {
            u32 qa = (((u32)(2 * ks) + qAh) ^ xorq) * 16u;
            u32 a0[4], a1[4];
            LDSM_X4(a0, ab + rbA0 + qa);
            LDSM_X4(a1, ab + rbA1 + qa);
            u32 qb = (((u32)(2 * ks) + qBh) ^ xorq) * 16u;
#pragma unroll
            for (int nb = 0; nb < 8; ++nb) {
                u32 b0, b1;
                LDSM_X2(b0, b1, bb + rbB + (u32)nb * 1024u + qb);
                MMA16816(acc[0][nb], a0, b0, b1);
                MMA16816(acc[1][nb], a1, b0, b1);
            }
        }
        __syncthreads();
    }
#undef FILL_CHUNK

#pragma unroll
    for (int mi = 0; mi < 2; ++mi) {
#pragma unroll
        for (int half = 0; half < 2; ++half) {
            int m = m0 + wm * 32 + mi * 16 + (lane >> 2) + half * 8;
            if (m < loM || m >= hiM) continue;
            int mm = orow ? orow[m] : m;
            long base;
            if (outMap == 0)      base = (long)mm * N;
            else if (outMap == 1) base = (long)mm * NNODE * HD;
            else                  base = ((long)(mm >> 3) * NNODE + 1 + (mm & 7)) * (long)HD;
#pragma unroll
            for (int nb = 0; nb < 8; ++nb) {
                int n = n0 + wn * 64 + nb * 8 + (lane & 3) * 2;
                if (n >= N) continue;
                float x0 = acc[mi][nb][half * 2 + 0];
                float x1 = acc[mi][nb][half * 2 + 1];
                if (bias) { x0 += bias[n]; x1 += bias[n + 1]; }
                if (act == 1)      { x0 = fmaxf(x0, 0.f); x1 = fmaxf(x1, 0.f); }
                else if (act == 2) { x0 = x0 > 0.f ? x0 : expm1f(x0);
                                     x1 = x1 > 0.f ? x1 : expm1f(x1); }
                if (outHalf) {
                    *(__half2*)((__half*)C + base + n) = __floats2half2_rn(x0, x1);
                } else {
                    *(float2*)((float*)C + base + n) = make_float2(x0, x1);
                }
            }
        }
    }
}

// ---------------- fused preprocessing (ent + attr) ---------------------------
__device__ __forceinline__ int clampL(int L, int T) {
    return L < 1 ? 1 : (L > T ? T : L);
}
__global__ void hist2(const int* __restrict__ lenE, const int* __restrict__ lenA,
                      int* __restrict__ cntE, int* __restrict__ cntA)
{
    int i = blockIdx.x * blockDim.x + threadIdx.x;
    if (i < NG)   atomicAdd(&cntE[clampL(lenE[i], TE)], 1);
    if (i < NATT) atomicAdd(&cntA[clampL(lenA[i], TA)], 1);
}
__global__ void offsets2(const int* __restrict__ cntE, int* __restrict__ offE,
                         int* __restrict__ mcntE,
                         const int* __restrict__ cntA, int* __restrict__ offA,
                         int* __restrict__ mcntA)
{
    if (threadIdx.x == 0) {
        int run = 0;
        for (int L = TE; L >= 1; --L) { offE[L] = run; run += cntE[L]; }
        for (int t = 0; t < TE; ++t) {
            int s = 0;
            for (int L = t + 1; L <= TE; ++L) s += cntE[L];
            mcntE[t] = s;
        }
    } else if (threadIdx.x == 1) {
        int run = 0;
        for (int L = TA; L >= 1; --L) { offA[L] = run; run += cntA[L]; }
        for (int t = 0; t < TA; ++t) {
            int s = 0;
            for (int L = t + 1; L <= TA; ++L) s += cntA[L];
            mcntA[t] = s;
        }
    }
}
__global__ void scatter2(const int* __restrict__ lenE, const int* __restrict__ lenA,
                         int* __restrict__ offE, int* __restrict__ permE,
                         int* __restrict__ offA, int* __restrict__ permA)
{
    int i = blockIdx.x * blockDim.x + threadIdx.x;
    if (i < NG) {
        int pos = atomicAdd(&offE[clampL(lenE[i], TE)], 1);
        permE[pos] = i;
    }
    if (i < NATT) {
        int pos = atomicAdd(&offA[clampL(lenA[i], TA)], 1);
        permA[pos] = i;
    }
}
__global__ void pairs2(const int* __restrict__ tokE, const int* __restrict__ lenE,
                       int* __restrict__ pcE, int* __restrict__ gtokE, int* __restrict__ orowE,
                       const int* __restrict__ tokA, const int* __restrict__ lenA,
                       int* __restrict__ pcA, int* __restrict__ gtokA, int* __restrict__ orowA)
{
    int p = blockIdx.x * blockDim.x + threadIdx.x;
    if (p < NG * TE) {
        int i = p / TE, t = p - i * TE;
        if (t < clampL(lenE[i], TE)) {
            int pos = atomicAdd(pcE, 1);
            gtokE[pos] = tokE[p];
            orowE[pos] = p;
        }
    }
    if (p < NATT * TA) {
        int i = p / TA, t = p - i * TA;
        if (t < clampL(lenA[i], TA)) {
            int pos = atomicAdd(pcA, 1);
            gtokA[pos] = tokA[p];
            orowA[pos] = p;
        }
    }
}

// ---------------- GRU gate update (fp16 xp/gh; t0 path uses gh = bhh) --------
__global__ void gru_gate4(const __half* __restrict__ xp,
                          const __half* __restrict__ gh,
                          const float* __restrict__ bhh_t0,   // non-null => t==0
                          float* __restrict__ h,
                          __half* __restrict__ hhi,
                          const int* __restrict__ perm,
                          const int* __restrict__ mcnt,
                          int t, int T)
{
    const int Q = WD / 4;   // 75
    int idx = blockIdx.x * blockDim.x + threadIdx.x;
    int i = idx / Q;
    if (i >= *mcnt) return;
    int d = idx - i * Q;
    int orig = perm[i];
    const __half* x = xp + ((long)orig * T + t) * G3;
    float4* hp = (float4*)(h + (long)orig * WD);

    float4 xr = ld4h(x + 4 * d);
    float4 xz = ld4h(x + WD + 4 * d);
    float4 xn = ld4h(x + 2 * WD + 4 * d);
    float4 gr, gz, gn, hv;
    if (bhh_t0) {
        const float4* b = (const float4*)bhh_t0;
        gr = b[d]; gz = b[Q + d]; gn = b[2 * Q + d];
        hv = make_float4(0.f, 0.f, 0.f, 0.f);
    } else {
        const __half* g = gh + (long)i * G3;
        gr = ld4h(g + 4 * d);
        gz = ld4h(g + WD + 4 * d);
        gn = ld4h(g + 2 * WD + 4 * d);
        hv = hp[d];
    }

    float4 res;
    const float* pxr = &xr.x; const float* pxz = &xz.x; const float* pxn = &xn.x;
    const float* pgr = &gr.x; const float* pgz = &gz.x; const float* pgn = &gn.x;
    const float* phv = &hv.x; float* pres = &res.x;
#pragma unroll
    for (int c = 0; c < 4; ++c) {
        float r = 1.f / (1.f + expf(-(pxr[c] + pgr[c])));
        float z = 1.f / (1.f + expf(-(pxz[c] + pgz[c])));
        float n = tanhf(pxn[c] + r * pgn[c]);
        pres[c] = (1.f - z) * n + z * phv[c];
    }
    hp[d] = res;
    *(u64*)(hhi + (long)orig * KP3 + 4 * d) = cvt4h(res);
}

// ---------------- va/vb = Wg^T a_src / Wg^T a_dst ----------------------------
__global__ void wgt_vec_kernel(const float* __restrict__ Wg,
                               const float* __restrict__ a_src,
                               const float* __restrict__ a_dst,
                               float* __restrict__ va, float* __restrict__ vb)
{
    int k = blockIdx.x * blockDim.x + threadIdx.x;
    if (k >= HD) return;
    float sa = 0.f, sb = 0.f;
    for (int d = 0; d < HD; ++d) {
        float w = Wg[(long)d * HD + k];
        sa += w * a_src[d];
        sb += w * a_dst[d];
    }
    va[k] = sa;
    vb[k] = sb;
}

// ---------------- GAT dots + softmax + node mix (writes fp16 hi) -------------
__global__ void gat_mix_kernel(const float* __restrict__ nodes,
                               const float* __restrict__ va,
                               const float* __restrict__ vb,
                               const unsigned char* __restrict__ amask,
                               __half* __restrict__ mhi)
{
    int g = blockIdx.x;
    const float* base = nodes + (long)g * NNODE * HD;
    __shared__ float sdots[10];
    __shared__ float salpha[NNODE];

    int tid  = threadIdx.x;
    int warp = tid >> 5, lane = tid & 31;

    float partial = 0.f;
    if (warp < 9) {
        const float* row = base + warp * HD;
        for (int d = lane; d < HD; d += 32) partial += row[d] * vb[d];
    } else {
        for (int d = lane; d < HD; d += 32) partial += base[d] * va[d];
    }
#pragma unroll
    for (int off = 16; off; off >>= 1)
        partial += __shfl_down_sync(0xffffffffu, partial, off);
    if (lane == 0) sdots[warp] = partial;
    __syncthreads();

    if (tid == 0) {
        float es0 = sdots[9];
        float e[NNODE];
#pragma unroll
        for (int j = 0; j < NNODE; ++j) {
            bool valid;
            if (j == 0) valid = true;
            else {
                const unsigned char* mk = amask + ((long)g * NA + (j - 1)) * TA;
                valid = !(mk[0] && mk[1] && mk[2] && mk[3]);
            }
            if (valid) {
                float v = es0 + sdots[j];
                e[j] = v > 0.f ? v : 0.2f * v;
            } else e[j] = -1e9f;
        }
        float mx = e[0];
#pragma unroll
        for (int j = 1; j < NNODE; ++j) mx = fmaxf(mx, e[j]);
        float s = 0.f, ex[NNODE];
#pragma unroll
        for (int j = 0; j < NNODE; ++j) { ex[j] = expf(e[j] - mx); s += ex[j]; }
        float inv = 1.f / s;
#pragma unroll
        for (int j = 0; j < NNODE; ++j) salpha[j] = ex[j] * inv;
    }
    __syncthreads();

    for (int d4 = tid; d4 < HD / 4; d4 += blockDim.x) {
        float4 s4;
        float* ps = &s4.x;
#pragma unroll
        for (int q = 0; q < 4; ++q) {
            int d = d4 * 4 + q;
            float s = 0.f;
#pragma unroll
            for (int j = 0; j < NNODE; ++j) s += salpha[j] * base[j * HD + d];
            ps[q] = s;
        }
        *(u64*)(mhi + (long)g * HD + 4 * d4) = cvt4h(s4);
    }
}

// ---------------- launch ------------------------------------------------------
extern "C" void kernel_launch(void* const* d_in, const int* in_sizes, int n_in,
                              void* d_out, int out_size)
{
    const int*   ent_tok  = (const int*)  d_in[0];
    const int*   ent_len  = (const int*)  d_in[1];
    const int*   at_tok   = (const int*)  d_in[3];
    const int*   at_len   = (const int*)  d_in[4];
    const unsigned char* at_mask = (const unsigned char*)d_in[5];
    const float* emb      = (const float*)d_in[6];
    const float* Wih_ent  = (const float*)d_in[7];
    const float* Whh_ent  = (const float*)d_in[8];
    const float* bih_ent  = (const float*)d_in[9];
    const float* bhh_ent  = (const float*)d_in[10];
    const float* Wih_attr = (const float*)d_in[11];
    const float* Whh_attr = (const float*)d_in[12];
    const float* bih_attr = (const float*)d_in[13];
    const float* bhh_attr = (const float*)d_in[14];
    const float* Wfc      = (const float*)d_in[15];
    const float* bfc      = (const float*)d_in[16];
    const float* Wg       = (const float*)d_in[17];
    const float* a_src    = (const float*)d_in[18];
    const float* a_dst    = (const float*)d_in[19];
    float* out = (float*)d_out;

    static cudaStream_t s2 = nullptr, s3 = nullptr;
    static cudaEvent_t evF = nullptr, evJ = nullptr, evFC = nullptr;
    static cudaEvent_t evG[TA] = {};
    if (!s2) {
        cudaStreamCreateWithFlags(&s2, cudaStreamNonBlocking);
        cudaStreamCreateWithFlags(&s3, cudaStreamNonBlocking);
        cudaEventCreateWithFlags(&evF, cudaEventDisableTiming);
        cudaEventCreateWithFlags(&evJ, cudaEventDisableTiming);
        cudaEventCreateWithFlags(&evFC, cudaEventDisableTiming);
        for (int t = 0; t < TA; ++t)
            cudaEventCreateWithFlags(&evG[t], cudaEventDisableTiming);
    }

    __half *xp_ent, *xp_attr, *ghE, *ghA;
    float *h_ent, *h_attr, *nodes, *va, *vb;
    int *ctr, *offE, *permE, *mcntE, *offA, *permA, *mcntA;
    int *gtokE, *orowE, *gtokA, *orowA;
    __half *embH, *wiheH, *whheH, *wihaH, *whhaH, *wfcH, *wgH;
    __half *heH, *haH, *mixH;

    cudaGetSymbolAddress((void**)&xp_ent,  g_xp_ent);
    cudaGetSymbolAddress((void**)&xp_attr, g_xp_attr);
    cudaGetSymbolAddress((void**)&ghE,     g_gh_ent);
    cudaGetSymbolAddress((void**)&ghA,     g_gh_attr);
    cudaGetSymbolAddress((void**)&h_ent,   g_h_ent);
    cudaGetSymbolAddress((void**)&h_attr,  g_h_attr);
    cudaGetSymbolAddress((void**)&nodes,   g_nodes);
    cudaGetSymbolAddress((void**)&va,      g_va);
    cudaGetSymbolAddress((void**)&vb,      g_vb);
    cudaGetSymbolAddress((void**)&ctr,   g_ctr);
    cudaGetSymbolAddress((void**)&offE,  g_off_ent);
    cudaGetSymbolAddress((void**)&permE, g_perm_ent);
    cudaGetSymbolAddress((void**)&mcntE, g_mcnt_ent);
    cudaGetSymbolAddress((void**)&offA,  g_off_attr);
    cudaGetSymbolAddress((void**)&permA, g_perm_attr);
    cudaGetSymbolAddress((void**)&mcntA, g_mcnt_attr);
    cudaGetSymbolAddress((void**)&gtokE, g_gtok_ent);
    cudaGetSymbolAddress((void**)&orowE, g_orow_ent);
    cudaGetSymbolAddress((void**)&gtokA, g_gtok_attr);
    cudaGetSymbolAddress((void**)&orowA, g_orow_attr);
    cudaGetSymbolAddress((void**)&embH,  g_emb_hi);
    cudaGetSymbolAddress((void**)&wiheH, g_wihe_hi);
    cudaGetSymbolAddress((void**)&whheH, g_whhe_hi);
    cudaGetSymbolAddress((void**)&wihaH, g_wiha_hi);
    cudaGetSymbolAddress((void**)&whhaH, g_whha_hi);
    cudaGetSymbolAddress((void**)&wfcH,  g_wfc_hi);
    cudaGetSymbolAddress((void**)&wgH,   g_wg_hi);
    cudaGetSymbolAddress((void**)&heH,   g_he_hi);
    cudaGetSymbolAddress((void**)&haH,   g_ha_hi);
    cudaGetSymbolAddress((void**)&mixH,  g_mix_hi);

    int* cntE = ctr + 0;
    int* cntA = ctr + 10;
    int* pcE  = ctr + 20;
    int* pcA  = ctr + 21;

    cudaFuncSetAttribute(tgemm, cudaFuncAttributeMaxDynamicSharedMemorySize, TG_SMEM);

    cudaMemsetAsync(ctr, 0, 32 * sizeof(int));

    // Wg conversion + attention vectors on s2 (independent of main prefix)
    cvt_rows_hi<<<(HD * (HD / 4) + 255) / 256, 256, 0, s2>>>(Wg, wgH, HD, HD, HD);
    wgt_vec_kernel<<<(HD + 255) / 256, 256, 0, s2>>>(Wg, a_src, a_dst, va, vb);

    // main-prefix conversions + preprocessing
    const int q3 = KP3 / 4;
    cvt_rows_hi<<<(V * q3 + 255) / 256, 256>>>(emb, embH, V, WD, KP3);
    cvt_w4<<<dim3((G3 * q3 + 255) / 256, 4), 256>>>(
        Wih_ent, Whh_ent, Wih_attr, Whh_attr, wiheH, whheH, wihaH, whhaH);
    cvt_rows_hi<<<(HD * q3 + 255) / 256, 256>>>(Wfc, wfcH, HD, WD, KP3);

    hist2<<<(NATT + 255) / 256, 256>>>(ent_len, at_len, cntE, cntA);
    offsets2<<<1, 32>>>(cntE, offE, mcntE, cntA, offA, mcntA);
    scatter2<<<(NATT + 255) / 256, 256>>>(ent_len, at_len, offE, permE, offA, permA);
    pairs2<<<(NATT * TA + 255) / 256, 256>>>(ent_tok, ent_len, pcE, gtokE, orowE,
                                             at_tok, at_len, pcA, gtokA, orowA);

    const int nt900  = (G3 + TN - 1) / TN;   // 8
    const int nt1024 = HD / TN;              // 8

    // xp_ent on main, then fork entity chain onto s2
    tgemm<<<dim3(NG * TE / TM, nt900), 256, TG_SMEM>>>(
        embH, gtokE, wiheH, bih_ent, xp_ent,
        NG * TE, G3, WD, KP3, 0, 0, pcE, nullptr, orowE, 1);

    cudaEventRecord(evF, 0);
    cudaStreamWaitEvent(s2, evF, 0);

    // ---- entity chain (stream s2) ----
    gru_gate4<<<(NG * 75 + 255) / 256, 256, 0, s2>>>(
        xp_ent, nullptr, bhh_ent, h_ent, heH, permE, mcntE + 0, 0, TE);
    for (int t = 1; t < TE; ++t) {
        tgemm<<<dim3(NG / TM, nt900), 256, TG_SMEM, s2>>>(
            heH, permE, whheH, bhh_ent, ghE,
            NG, G3, WD, KP3, 0, 0, mcntE + t, nullptr, nullptr, 1);
        gru_gate4<<<(NG * 75 + 255) / 256, 256, 0, s2>>>(
            xp_ent, ghE, nullptr, h_ent, heH, permE, mcntE + t, t, TE);
    }
    tgemm<<<dim3(NG / TM, nt1024), 256, TG_SMEM, s2>>>(
        heH, nullptr, wfcH, bfc, nodes,
        NG, HD, WD, KP3, 1, 1, nullptr, nullptr, nullptr, 0);
    cudaEventRecord(evJ, s2);

    // ---- attribute chain (main stream) with retired-row FC slices on s3 ----
    tgemm<<<dim3(NATT * TA / TM, nt900), 256, TG_SMEM>>>(
        embH, gtokA, wihaH, bih_attr, xp_attr,
        NATT * TA, G3, WD, KP3, 0, 0, pcA, nullptr, orowA, 1);
    gru_gate4<<<(NATT * 75 + 255) / 256, 256>>>(
        xp_attr, nullptr, bhh_attr, h_attr, haH, permA, mcntA + 0, 0, TA);
    cudaEventRecord(evG[0], 0);
    for (int t = 1; t < TA; ++t) {
        tgemm<<<dim3(NATT / TM, nt900), 256, TG_SMEM>>>(
            haH, permA, whhaH, bhh_attr, ghA,
            NATT, G3, WD, KP3, 0, 0, mcntA + t, nullptr, nullptr, 1);
        gru_gate4<<<(NATT * 75 + 255) / 256, 256>>>(
            xp_attr, ghA, nullptr, h_attr, haH, permA, mcntA + t, t, TA);
        cudaEventRecord(evG[t], 0);
    }
    // FC slices: after gate t, rows [mcnt[t+1], mcnt[t]) are final
    for (int t = 0; t < TA; ++t) {
        cudaStreamWaitEvent(s3, evG[t], 0);
        const int* hiP = mcntA + t;
        const int* loP = (t + 1 < TA) ? (mcntA + t + 1) : nullptr;  // lo = 0 at last
        tgemm<<<dim3(NATT / TM, nt1024), 256, TG_SMEM, s3>>>(
            haH, permA, wfcH, bfc, nodes,
            NATT, HD, WD, KP3, 1, 2, hiP, loP, permA, 0);
    }
    cudaEventRecord(evFC, s3);

    // join entity + FC streams
    cudaStreamWaitEvent(0, evJ, 0);
    cudaStreamWaitEvent(0, evFC, 0);

    // GAT: dots + alpha + mix (fp16 out)
    gat_mix_kernel<<<NG, 320>>>(nodes, va, vb, at_mask, mixH);

    // out = elu(mix @ Wg^T)
    tgemm<<<dim3(NG / TM, nt1024), 256, TG_SMEM>>>(
        mixH, nullptr, wgH, nullptr, out,
        NG, HD, HD, HD, 2, 0, nullptr, nullptr, nullptr, 0);
}